// round 1
// baseline (speedup 1.0000x reference)
#include <cuda_runtime.h>
#include <cstdint>

// Problem constants (from reference setup_inputs)
#define DMODEL 1536
#define HEADS  24
#define HDIM   64
#define S_HID  2048
#define S_ENCC 256
#define T_TOT  2304   // S_HID + S_ENCC

// ---------------------------------------------------------------------------
// Scratch (no allocations allowed -> __device__ globals, selected by tag)
// ---------------------------------------------------------------------------
__device__ float g_Q[(size_t)S_HID * DMODEL];   // queries: hidden rows only
__device__ float g_K[(size_t)T_TOT * DMODEL];   // keys: hidden + encoder
__device__ float g_V[(size_t)T_TOT * DMODEL];   // values: hidden + encoder
__device__ float g_O[(size_t)S_HID * DMODEL];   // attention output (pre-proj)

__device__ __forceinline__ float* scratch_ptr(int tag) {
    switch (tag) {
        case 0: return g_Q;
        case 1: return g_K;
        case 2: return g_V;
        default: return g_O;
    }
}

// ---------------------------------------------------------------------------
// GEMM: C[M,N] = A[M,K] @ W[N,K]^T + bias[N]
// BM=BN=128, BK=8, 256 threads, 8x8 microtile.
// A / C may live in scratch (tag >= 0) or come from kernel args (tag < 0).
// All of M,N,K are multiples of the blocking here (2048/256 x 1536 x 1536).
// ---------------------------------------------------------------------------
__global__ __launch_bounds__(256) void gemm_bias(
    const float* __restrict__ Aext, int a_tag,
    const float* __restrict__ W, const float* __restrict__ bias,
    float* __restrict__ Cext, int c_tag, int c_off,
    int M, int N, int K)
{
    __shared__ float As[8][132];
    __shared__ float Bs[8][132];

    const float* A = (a_tag < 0) ? Aext : scratch_ptr(a_tag);
    float* C = (c_tag < 0) ? Cext : (scratch_ptr(c_tag) + (size_t)c_off);

    int tid = threadIdx.x;
    int tx = tid & 15;        // 0..15  -> N direction
    int ty = tid >> 4;        // 0..15  -> M direction
    int mbase = blockIdx.y << 7;
    int nbase = blockIdx.x << 7;

    // cooperative load mapping: 128 rows x 8 k -> thread loads one float4
    int lrow = tid >> 1;            // 0..127
    int lcol = (tid & 1) << 2;      // 0 or 4

    const float* Ap = A + (size_t)(mbase + lrow) * K + lcol;
    const float* Wp = W + (size_t)(nbase + lrow) * K + lcol;

    float acc[8][8];
#pragma unroll
    for (int i = 0; i < 8; i++)
#pragma unroll
        for (int j = 0; j < 8; j++) acc[i][j] = 0.f;

    for (int kb = 0; kb < K; kb += 8) {
        float4 avv = *(const float4*)(Ap + kb);
        float4 wvv = *(const float4*)(Wp + kb);
        __syncthreads();
        As[lcol + 0][lrow] = avv.x;
        As[lcol + 1][lrow] = avv.y;
        As[lcol + 2][lrow] = avv.z;
        As[lcol + 3][lrow] = avv.w;
        Bs[lcol + 0][lrow] = wvv.x;
        Bs[lcol + 1][lrow] = wvv.y;
        Bs[lcol + 2][lrow] = wvv.z;
        Bs[lcol + 3][lrow] = wvv.w;
        __syncthreads();

#pragma unroll
        for (int kk = 0; kk < 8; kk++) {
            float a[8], b[8];
            *(float4*)(a)     = *(const float4*)&As[kk][(ty << 3)];
            *(float4*)(a + 4) = *(const float4*)&As[kk][(ty << 3) + 4];
            *(float4*)(b)     = *(const float4*)&Bs[kk][(tx << 3)];
            *(float4*)(b + 4) = *(const float4*)&Bs[kk][(tx << 3) + 4];
#pragma unroll
            for (int i = 0; i < 8; i++)
#pragma unroll
                for (int j = 0; j < 8; j++)
                    acc[i][j] = fmaf(a[i], b[j], acc[i][j]);
        }
    }

#pragma unroll
    for (int i = 0; i < 8; i++) {
        float* cp = C + (size_t)(mbase + (ty << 3) + i) * N + nbase + (tx << 3);
        const float* bp = bias + nbase + (tx << 3);
#pragma unroll
        for (int j = 0; j < 8; j++) cp[j] = acc[i][j] + bp[j];
    }
}

// ---------------------------------------------------------------------------
// Per-head RMSNorm over HDIM=64 chunks. One warp per (row, head) chunk.
// rows < split use w0 (main norm weight), rows >= split use w1 (added).
// ---------------------------------------------------------------------------
__global__ __launch_bounds__(256) void rmsnorm_kernel(
    int buf_tag, const float* __restrict__ w0, const float* __restrict__ w1,
    int nrows, int split)
{
    float* buf = scratch_ptr(buf_tag);
    int chunk = blockIdx.x * 8 + (threadIdx.x >> 5);
    int lane = threadIdx.x & 31;
    int row = chunk / HEADS;
    if (row >= nrows) return;
    int head = chunk % HEADS;

    float* p = buf + (size_t)row * DMODEL + head * HDIM;
    float x0 = p[lane];
    float x1 = p[lane + 32];
    float ss = x0 * x0 + x1 * x1;
#pragma unroll
    for (int o = 16; o; o >>= 1) ss += __shfl_xor_sync(0xffffffffu, ss, o);
    float r = rsqrtf(ss * (1.0f / 64.0f) + 1e-6f);
    const float* w = (row < split) ? w0 : w1;
    p[lane]      = x0 * r * w[lane];
    p[lane + 32] = x1 * r * w[lane + 32];
}

// ---------------------------------------------------------------------------
// Flash attention, fp32. BLOCK_Q = BLOCK_K = 64, 256 threads (16x16),
// each thread computes a 4x4 microtile of S and of O.
// Q: g_Q (2048 rows only), K/V: g_K/g_V (2304 rows), out: g_O.
// ---------------------------------------------------------------------------
struct AttnSmem {
    float Qs[64][68];   // [d][q], padded for float4-aligned reads
    float Ks[64][68];   // [d][k]
    float Vs[64][64];   // [k][d]
    float Ss[64][65];   // [k][q]  (scores -> probs in place)
    float mrow[64];
    float lrow[64];
    float corr[64];
    float msk[64];
};

__global__ __launch_bounds__(256) void attn_kernel(const float* __restrict__ mask)
{
    extern __shared__ char smem_raw[];
    AttnSmem& sm = *reinterpret_cast<AttnSmem*>(smem_raw);

    int tid = threadIdx.x;
    int tx = tid & 15;   // k / d direction (4 cols each)
    int ty = tid >> 4;   // q direction (4 rows each)
    int head = blockIdx.y;
    int qbase = blockIdx.x << 6;
    int hoff = head * HDIM;

    // load Q tile transposed: Qs[d][q]
    for (int i = tid; i < 64 * 64; i += 256) {
        int q = i >> 6, d = i & 63;
        sm.Qs[d][q] = g_Q[(size_t)(qbase + q) * DMODEL + hoff + d];
    }
    if (tid < 64) { sm.mrow[tid] = -3e38f; sm.lrow[tid] = 0.f; }

    float o[4][4];
#pragma unroll
    for (int i = 0; i < 4; i++)
#pragma unroll
        for (int j = 0; j < 4; j++) o[i][j] = 0.f;

    const float scale = 0.125f;  // 64^-0.5

    for (int kt = 0; kt < T_TOT / 64; kt++) {
        int kbase = kt << 6;
        __syncthreads();
        // load K (transposed) and V (natural) tiles
        for (int i = tid; i < 64 * 64; i += 256) {
            int k = i >> 6, d = i & 63;
            size_t g = (size_t)(kbase + k) * DMODEL + hoff + d;
            sm.Ks[d][k] = g_K[g];
            sm.Vs[k][d] = g_V[g];
        }
        if (tid < 64) sm.msk[tid] = mask[kbase + tid];
        __syncthreads();

        // S = Q @ K^T  (4x4 per thread)
        float s[4][4];
#pragma unroll
        for (int i = 0; i < 4; i++)
#pragma unroll
            for (int j = 0; j < 4; j++) s[i][j] = 0.f;

#pragma unroll 16
        for (int d = 0; d < 64; d++) {
            float qv[4], kv[4];
            *(float4*)qv = *(const float4*)&sm.Qs[d][ty << 2];
            *(float4*)kv = *(const float4*)&sm.Ks[d][tx << 2];
#pragma unroll
            for (int i = 0; i < 4; i++)
#pragma unroll
                for (int j = 0; j < 4; j++)
                    s[i][j] = fmaf(qv[i], kv[j], s[i][j]);
        }

        // scale + mask, stash to Ss[k][q]
#pragma unroll
        for (int j = 0; j < 4; j++) {
            float mj = sm.msk[(tx << 2) + j];
#pragma unroll
            for (int i = 0; i < 4; i++)
                sm.Ss[(tx << 2) + j][(ty << 2) + i] = s[i][j] * scale + mj;
        }
        __syncthreads();

        // online softmax update, one thread per q row
        if (tid < 64) {
            int q = tid;
            float m_old = sm.mrow[q];
            float m = m_old;
#pragma unroll 8
            for (int k = 0; k < 64; k++) m = fmaxf(m, sm.Ss[k][q]);
            float c = __expf(m_old - m);
            float l = sm.lrow[q] * c;
#pragma unroll 8
            for (int k = 0; k < 64; k++) {
                float p = __expf(sm.Ss[k][q] - m);
                sm.Ss[k][q] = p;
                l += p;
            }
            sm.mrow[q] = m;
            sm.lrow[q] = l;
            sm.corr[q] = c;
        }
        __syncthreads();

        // rescale accumulators, then O += P @ V
        float cr[4];
#pragma unroll
        for (int i = 0; i < 4; i++) cr[i] = sm.corr[(ty << 2) + i];
#pragma unroll
        for (int i = 0; i < 4; i++)
#pragma unroll
            for (int j = 0; j < 4; j++) o[i][j] *= cr[i];

#pragma unroll 16
        for (int k = 0; k < 64; k++) {
            float pv[4], vv[4];
#pragma unroll
            for (int i = 0; i < 4; i++) pv[i] = sm.Ss[k][(ty << 2) + i];
            *(float4*)vv = *(const float4*)&sm.Vs[k][tx << 2];
#pragma unroll
            for (int i = 0; i < 4; i++)
#pragma unroll
                for (int j = 0; j < 4; j++)
                    o[i][j] = fmaf(pv[i], vv[j], o[i][j]);
        }
    }

    // finalize: divide by l and store
#pragma unroll
    for (int i = 0; i < 4; i++) {
        float inv = 1.0f / sm.lrow[(ty << 2) + i];
        float* op = g_O + (size_t)(qbase + (ty << 2) + i) * DMODEL + hoff + (tx << 2);
#pragma unroll
        for (int j = 0; j < 4; j++) op[j] = o[i][j] * inv;
    }
}

// ---------------------------------------------------------------------------
// kernel_launch
// ---------------------------------------------------------------------------
extern "C" void kernel_launch(void* const* d_in, const int* in_sizes, int n_in,
                              void* d_out, int out_size)
{
    (void)in_sizes; (void)n_in; (void)out_size;
    const float* hs   = (const float*)d_in[0];
    const float* enc  = (const float*)d_in[1];
    const float* mask = (const float*)d_in[2];
    const float* wq   = (const float*)d_in[3];
    const float* bq   = (const float*)d_in[4];
    const float* wk   = (const float*)d_in[5];
    const float* bk   = (const float*)d_in[6];
    const float* wv   = (const float*)d_in[7];
    const float* bv   = (const float*)d_in[8];
    const float* nqw  = (const float*)d_in[9];
    const float* nkw  = (const float*)d_in[10];
    // d_in[11], d_in[12]: add_q_proj (encoder queries) -- dead code, output discarded
    const float* akw  = (const float*)d_in[13];
    const float* akb  = (const float*)d_in[14];
    const float* avw  = (const float*)d_in[15];
    const float* avb  = (const float*)d_in[16];
    // d_in[17]: norm_added_q -- dead code
    const float* nakw = (const float*)d_in[18];
    const float* wo   = (const float*)d_in[19];
    const float* bo   = (const float*)d_in[20];
    // d_in[21], d_in[22]: to_add_out -- dead code (context output discarded)
    float* out = (float*)d_out;

    cudaFuncSetAttribute(attn_kernel, cudaFuncAttributeMaxDynamicSharedMemorySize,
                         (int)sizeof(AttnSmem));

    dim3 tb(256);
    const int ENC_OFF = S_HID * DMODEL;

    // QKV projections (hidden stream), K/V projections (encoder stream)
    gemm_bias<<<dim3(12, 16), tb>>>(hs, -1, wq, bq, nullptr, 0, 0, S_HID, DMODEL, DMODEL);
    gemm_bias<<<dim3(12, 16), tb>>>(hs, -1, wk, bk, nullptr, 1, 0, S_HID, DMODEL, DMODEL);
    gemm_bias<<<dim3(12, 16), tb>>>(hs, -1, wv, bv, nullptr, 2, 0, S_HID, DMODEL, DMODEL);
    gemm_bias<<<dim3(12, 2),  tb>>>(enc, -1, akw, akb, nullptr, 1, ENC_OFF, S_ENCC, DMODEL, DMODEL);
    gemm_bias<<<dim3(12, 2),  tb>>>(enc, -1, avw, avb, nullptr, 2, ENC_OFF, S_ENCC, DMODEL, DMODEL);

    // per-head RMSNorm on Q (hidden rows) and K (hidden + encoder rows)
    rmsnorm_kernel<<<(S_HID * HEADS) / 8, tb>>>(0, nqw, nqw, S_HID, S_HID);
    rmsnorm_kernel<<<(T_TOT * HEADS) / 8, tb>>>(1, nkw, nakw, T_TOT, S_HID);

    // flash attention: 32 q-tiles x 24 heads
    attn_kernel<<<dim3(S_HID / 64, HEADS), tb, sizeof(AttnSmem)>>>(mask);

    // output projection (hidden-stream rows only)
    gemm_bias<<<dim3(12, 16), tb>>>(nullptr, 3, wo, bo, out, -1, 0, S_HID, DMODEL, DMODEL);
}

// round 3
// speedup vs baseline: 2.2629x; 2.2629x over previous
#include <cuda_runtime.h>
#include <cuda_fp16.h>
#include <cstdint>

// Problem constants
#define DMODEL 1536
#define HEADS  24
#define HDIM   64
#define S_HID  2048
#define S_ENCC 256
#define T_TOT  2304

// ---------------------------------------------------------------------------
// Scratch (__device__ globals; no allocations allowed)
// ---------------------------------------------------------------------------
__device__ __align__(1024) float g_Q[(size_t)S_HID * DMODEL];
__device__ __align__(1024) float g_K[(size_t)T_TOT * DMODEL];
__device__ __align__(1024) float g_V[(size_t)T_TOT * DMODEL];
__device__ __align__(1024) float g_O[(size_t)S_HID * DMODEL];

__device__ __align__(1024) __half g_hs16[(size_t)S_HID * DMODEL];
__device__ __align__(1024) __half g_enc16[(size_t)S_ENCC * DMODEL];
__device__ __align__(1024) __half g_O16[(size_t)S_HID * DMODEL];
__device__ __align__(1024) __half g_w16[6][(size_t)DMODEL * DMODEL];

__device__ __forceinline__ float* scratch_ptr(int tag) {
    switch (tag) {
        case 0: return g_Q;
        case 1: return g_K;
        case 2: return g_V;
        default: return g_O;
    }
}

// ---------------------------------------------------------------------------
// PTX helpers (plain sm_103-safe: no tcgen05 / no 'a'-gated features)
// ---------------------------------------------------------------------------
__device__ __forceinline__ uint32_t smem_u32(const void* p) {
    return (uint32_t)__cvta_generic_to_shared(p);
}

__device__ __forceinline__ void cp_async16(uint32_t saddr, const void* gaddr) {
    asm volatile("cp.async.cg.shared.global [%0], [%1], 16;" :: "r"(saddr), "l"(gaddr) : "memory");
}

#define LDMATRIX_X4(r0, r1, r2, r3, addr) \
    asm volatile("ldmatrix.sync.aligned.m8n8.x4.shared.b16 {%0,%1,%2,%3}, [%4];" \
                 : "=r"(r0), "=r"(r1), "=r"(r2), "=r"(r3) : "r"(addr))

#define MMA16816(d, a, b) \
    asm volatile("mma.sync.aligned.m16n8k16.row.col.f32.f16.f16.f32 " \
                 "{%0,%1,%2,%3}, {%4,%5,%6,%7}, {%8,%9}, {%0,%1,%2,%3};" \
                 : "+f"((d)[0]), "+f"((d)[1]), "+f"((d)[2]), "+f"((d)[3]) \
                 : "r"((a)[0]), "r"((a)[1]), "r"((a)[2]), "r"((a)[3]), \
                   "r"((b)[0]), "r"((b)[1]))

// ---------------------------------------------------------------------------
// fp32 -> fp16 convert (vectorized x4)
// ---------------------------------------------------------------------------
__global__ __launch_bounds__(256) void cvt_kernel(const float* __restrict__ in,
                                                  __half* __restrict__ out, int n) {
    int i = (blockIdx.x * 256 + threadIdx.x) * 4;
    if (i < n) {
        float4 v = *(const float4*)(in + i);
        union { __half2 h[2]; uint2 u; } pk;
        pk.h[0] = __floats2half2_rn(v.x, v.y);
        pk.h[1] = __floats2half2_rn(v.z, v.w);
        *reinterpret_cast<uint2*>(out + i) = pk.u;
    }
}

// ---------------------------------------------------------------------------
// HMMA fp16 GEMM: C[M,N](fp32) = A[M,K](fp16) @ W[N,K](fp16)^T + bias[N]
// BM=BN=128, BK=32, 256 threads (8 warps: 2 m-warps x 4 n-warps, 64x32 each).
// Smem rows padded 32->40 halfs (80B stride: conflict-free ldmatrix).
// Double-buffered cp.async.
// ---------------------------------------------------------------------------
#define PADK 40

__global__ __launch_bounds__(256) void gemm16(
    const __half* __restrict__ A, const __half* __restrict__ W,
    const float* __restrict__ bias, float* __restrict__ C,
    int M, int N, int K)
{
    __shared__ __align__(16) __half sA[2][128 * PADK];
    __shared__ __align__(16) __half sW[2][128 * PADK];

    int tid = threadIdx.x;
    int wid = tid >> 5, lane = tid & 31;
    int wm = wid >> 2;           // 0..1 -> 64 rows each
    int wn = wid & 3;            // 0..3 -> 32 cols each
    int mbase = blockIdx.y << 7;
    int nbase = blockIdx.x << 7;
    const int NK = K >> 5;

    float acc[4][4][4];
#pragma unroll
    for (int mi = 0; mi < 4; mi++)
#pragma unroll
        for (int ni = 0; ni < 4; ni++)
#pragma unroll
            for (int e = 0; e < 4; e++) acc[mi][ni][e] = 0.f;

    // cooperative load: tile = 128 rows x 32 halfs (64B). 512 x 16B chunks,
    // 2 per thread (per matrix).
    auto load_tile = [&](int it) {
        int st = it & 1;
        int kb = it << 5;
#pragma unroll
        for (int i = 0; i < 2; i++) {
            int c = tid + (i << 8);          // 0..511
            int row = c >> 2;
            int col = (c & 3) << 3;          // half offset (0,8,16,24)
            cp_async16(smem_u32(&sA[st][row * PADK + col]),
                       A + (size_t)(mbase + row) * K + kb + col);
            cp_async16(smem_u32(&sW[st][row * PADK + col]),
                       W + (size_t)(nbase + row) * K + kb + col);
        }
        asm volatile("cp.async.commit_group;" ::: "memory");
    };

    load_tile(0);

    for (int it = 0; it < NK; it++) {
        int st = it & 1;
        if (it + 1 < NK) {
            load_tile(it + 1);
            asm volatile("cp.async.wait_group 1;" ::: "memory");
        } else {
            asm volatile("cp.async.wait_group 0;" ::: "memory");
        }
        __syncthreads();

#pragma unroll
        for (int ks = 0; ks < 2; ks++) {
            uint32_t afr[4][4];
#pragma unroll
            for (int mi = 0; mi < 4; mi++) {
                int m = wm * 64 + mi * 16 + (lane & 15);
                int kk = ks * 16 + ((lane >> 4) << 3);
                uint32_t addr = smem_u32(&sA[st][m * PADK + kk]);
                LDMATRIX_X4(afr[mi][0], afr[mi][1], afr[mi][2], afr[mi][3], addr);
            }
            uint32_t bfr[4][2];
#pragma unroll
            for (int nb = 0; nb < 2; nb++) {
                int n = wn * 32 + nb * 16 + (lane & 7) + (((lane >> 4) & 1) << 3);
                int kk = ks * 16 + (((lane >> 3) & 1) << 3);
                uint32_t addr = smem_u32(&sW[st][n * PADK + kk]);
                uint32_t r0, r1, r2, r3;
                LDMATRIX_X4(r0, r1, r2, r3, addr);
                bfr[nb * 2][0] = r0; bfr[nb * 2][1] = r1;
                bfr[nb * 2 + 1][0] = r2; bfr[nb * 2 + 1][1] = r3;
            }
#pragma unroll
            for (int mi = 0; mi < 4; mi++)
#pragma unroll
                for (int ni = 0; ni < 4; ni++)
                    MMA16816(acc[mi][ni], afr[mi], bfr[ni]);
        }
        __syncthreads();
    }

    // epilogue: thread (group g = lane/4, tq = lane%4)
    int g = lane >> 2, tq = lane & 3;
#pragma unroll
    for (int mi = 0; mi < 4; mi++) {
        int row0 = mbase + wm * 64 + mi * 16 + g;
#pragma unroll
        for (int ni = 0; ni < 4; ni++) {
            int col = nbase + wn * 32 + ni * 8 + tq * 2;
            float bx = bias[col], by = bias[col + 1];
            float2 v0 = make_float2(acc[mi][ni][0] + bx, acc[mi][ni][1] + by);
            float2 v1 = make_float2(acc[mi][ni][2] + bx, acc[mi][ni][3] + by);
            *(float2*)(C + (size_t)row0 * N + col) = v0;
            *(float2*)(C + (size_t)(row0 + 8) * N + col) = v1;
        }
    }
}

// ---------------------------------------------------------------------------
// Per-head RMSNorm
// ---------------------------------------------------------------------------
__global__ __launch_bounds__(256) void rmsnorm_kernel(
    int buf_tag, const float* __restrict__ w0, const float* __restrict__ w1,
    int nrows, int split)
{
    float* buf = scratch_ptr(buf_tag);
    int chunk = blockIdx.x * 8 + (threadIdx.x >> 5);
    int lane = threadIdx.x & 31;
    int row = chunk / HEADS;
    if (row >= nrows) return;
    int head = chunk % HEADS;

    float* p = buf + (size_t)row * DMODEL + head * HDIM;
    float x0 = p[lane];
    float x1 = p[lane + 32];
    float ss = x0 * x0 + x1 * x1;
#pragma unroll
    for (int o = 16; o; o >>= 1) ss += __shfl_xor_sync(0xffffffffu, ss, o);
    float r = rsqrtf(ss * (1.0f / 64.0f) + 1e-6f);
    const float* w = (row < split) ? w0 : w1;
    p[lane]      = x0 * r * w[lane];
    p[lane + 32] = x1 * r * w[lane + 32];
}

// ---------------------------------------------------------------------------
// Flash attention fp32, softmax parallelized across all 256 threads.
// ---------------------------------------------------------------------------
struct AttnSmem {
    float Qs[64][68];
    float Ks[64][68];
    float Vs[64][64];
    float Ss[64][65];
    float mrow[64];
    float lrow[64];
    float msk[64];
};

__global__ __launch_bounds__(256) void attn_kernel(const float* __restrict__ mask)
{
    extern __shared__ char smem_raw[];
    AttnSmem& sm = *reinterpret_cast<AttnSmem*>(smem_raw);

    int tid = threadIdx.x;
    int tx = tid & 15;
    int ty = tid >> 4;
    int head = blockIdx.y;
    int qbase = blockIdx.x << 6;
    int hoff = head * HDIM;

    for (int i = tid; i < 64 * 64; i += 256) {
        int q = i >> 6, d = i & 63;
        sm.Qs[d][q] = g_Q[(size_t)(qbase + q) * DMODEL + hoff + d];
    }
    if (tid < 64) { sm.mrow[tid] = -3e38f; sm.lrow[tid] = 0.f; }

    float o[4][4];
#pragma unroll
    for (int i = 0; i < 4; i++)
#pragma unroll
        for (int j = 0; j < 4; j++) o[i][j] = 0.f;

    const float scale = 0.125f;

    for (int kt = 0; kt < T_TOT / 64; kt++) {
        int kbase = kt << 6;
        __syncthreads();
        for (int i = tid; i < 64 * 64; i += 256) {
            int k = i >> 6, d = i & 63;
            size_t g = (size_t)(kbase + k) * DMODEL + hoff + d;
            sm.Ks[d][k] = g_K[g];
            sm.Vs[k][d] = g_V[g];
        }
        if (tid < 64) sm.msk[tid] = mask[kbase + tid];
        __syncthreads();

        float s[4][4];
#pragma unroll
        for (int i = 0; i < 4; i++)
#pragma unroll
            for (int j = 0; j < 4; j++) s[i][j] = 0.f;

#pragma unroll 16
        for (int d = 0; d < 64; d++) {
            float qv[4], kv[4];
            *(float4*)qv = *(const float4*)&sm.Qs[d][ty << 2];
            *(float4*)kv = *(const float4*)&sm.Ks[d][tx << 2];
#pragma unroll
            for (int i = 0; i < 4; i++)
#pragma unroll
                for (int j = 0; j < 4; j++)
                    s[i][j] = fmaf(qv[i], kv[j], s[i][j]);
        }

#pragma unroll
        for (int j = 0; j < 4; j++) {
            float mj = sm.msk[(tx << 2) + j];
#pragma unroll
            for (int i = 0; i < 4; i++) s[i][j] = s[i][j] * scale + mj;
        }

        // online softmax: row reductions across the 16 tx-lanes (same warp)
        float crr[4], mnew[4], rsum[4];
#pragma unroll
        for (int i = 0; i < 4; i++) {
            float m = fmaxf(fmaxf(s[i][0], s[i][1]), fmaxf(s[i][2], s[i][3]));
#pragma unroll
            for (int off = 1; off < 16; off <<= 1)
                m = fmaxf(m, __shfl_xor_sync(0xffffffffu, m, off));
            float mo = sm.mrow[(ty << 2) + i];
            mnew[i] = fmaxf(mo, m);
            crr[i] = __expf(mo - mnew[i]);
            float sum = 0.f;
#pragma unroll
            for (int j = 0; j < 4; j++) {
                s[i][j] = __expf(s[i][j] - mnew[i]);
                sum += s[i][j];
            }
#pragma unroll
            for (int off = 1; off < 16; off <<= 1)
                sum += __shfl_xor_sync(0xffffffffu, sum, off);
            rsum[i] = sum;
        }
        if (tx == 0) {
#pragma unroll
            for (int i = 0; i < 4; i++) {
                int q = (ty << 2) + i;
                sm.mrow[q] = mnew[i];
                sm.lrow[q] = sm.lrow[q] * crr[i] + rsum[i];
            }
        }
#pragma unroll
        for (int j = 0; j < 4; j++)
#pragma unroll
            for (int i = 0; i < 4; i++)
                sm.Ss[(tx << 2) + j][(ty << 2) + i] = s[i][j];
        __syncthreads();

#pragma unroll
        for (int i = 0; i < 4; i++)
#pragma unroll
            for (int j = 0; j < 4; j++) o[i][j] *= crr[i];

#pragma unroll 16
        for (int k = 0; k < 64; k++) {
            float pv[4], vv[4];
#pragma unroll
            for (int i = 0; i < 4; i++) pv[i] = sm.Ss[k][(ty << 2) + i];
            *(float4*)vv = *(const float4*)&sm.Vs[k][tx << 2];
#pragma unroll
            for (int i = 0; i < 4; i++)
#pragma unroll
                for (int j = 0; j < 4; j++)
                    o[i][j] = fmaf(pv[i], vv[j], o[i][j]);
        }
    }

#pragma unroll
    for (int i = 0; i < 4; i++) {
        float inv = 1.0f / sm.lrow[(ty << 2) + i];
        float* op = g_O + (size_t)(qbase + (ty << 2) + i) * DMODEL + hoff + (tx << 2);
#pragma unroll
        for (int j = 0; j < 4; j++) op[j] = o[i][j] * inv;
    }
}

// ---------------------------------------------------------------------------
// kernel_launch
// ---------------------------------------------------------------------------
extern "C" void kernel_launch(void* const* d_in, const int* in_sizes, int n_in,
                              void* d_out, int out_size)
{
    (void)in_sizes; (void)n_in; (void)out_size;
    const float* hs   = (const float*)d_in[0];
    const float* enc  = (const float*)d_in[1];
    const float* mask = (const float*)d_in[2];
    const float* wq   = (const float*)d_in[3];
    const float* bq   = (const float*)d_in[4];
    const float* wk   = (const float*)d_in[5];
    const float* bk   = (const float*)d_in[6];
    const float* wv   = (const float*)d_in[7];
    const float* bv   = (const float*)d_in[8];
    const float* nqw  = (const float*)d_in[9];
    const float* nkw  = (const float*)d_in[10];
    const float* akw  = (const float*)d_in[13];
    const float* akb  = (const float*)d_in[14];
    const float* avw  = (const float*)d_in[15];
    const float* avb  = (const float*)d_in[16];
    const float* nakw = (const float*)d_in[18];
    const float* wo   = (const float*)d_in[19];
    const float* bo   = (const float*)d_in[20];
    float* out = (float*)d_out;

    float *pQ, *pK, *pV, *pO;
    __half *phs16, *penc16, *pO16, *pw16;
    cudaGetSymbolAddress((void**)&pQ, g_Q);
    cudaGetSymbolAddress((void**)&pK, g_K);
    cudaGetSymbolAddress((void**)&pV, g_V);
    cudaGetSymbolAddress((void**)&pO, g_O);
    cudaGetSymbolAddress((void**)&phs16, g_hs16);
    cudaGetSymbolAddress((void**)&penc16, g_enc16);
    cudaGetSymbolAddress((void**)&pO16, g_O16);
    cudaGetSymbolAddress((void**)&pw16, g_w16);
    __half* w16q  = pw16 + 0 * (size_t)DMODEL * DMODEL;
    __half* w16k  = pw16 + 1 * (size_t)DMODEL * DMODEL;
    __half* w16v  = pw16 + 2 * (size_t)DMODEL * DMODEL;
    __half* w16ak = pw16 + 3 * (size_t)DMODEL * DMODEL;
    __half* w16av = pw16 + 4 * (size_t)DMODEL * DMODEL;
    __half* w16o  = pw16 + 5 * (size_t)DMODEL * DMODEL;

    cudaFuncSetAttribute(attn_kernel, cudaFuncAttributeMaxDynamicSharedMemorySize,
                         (int)sizeof(AttnSmem));

    dim3 tb(256);
    const int NHS = S_HID * DMODEL, NENC = S_ENCC * DMODEL, NW = DMODEL * DMODEL;
    const int ENC_OFF = S_HID * DMODEL;

    // fp32 -> fp16 converts (activations + live weights)
    cvt_kernel<<<NHS / 1024, tb>>>(hs, phs16, NHS);
    cvt_kernel<<<NENC / 1024, tb>>>(enc, penc16, NENC);
    cvt_kernel<<<NW / 1024, tb>>>(wq, w16q, NW);
    cvt_kernel<<<NW / 1024, tb>>>(wk, w16k, NW);
    cvt_kernel<<<NW / 1024, tb>>>(wv, w16v, NW);
    cvt_kernel<<<NW / 1024, tb>>>(akw, w16ak, NW);
    cvt_kernel<<<NW / 1024, tb>>>(avw, w16av, NW);
    cvt_kernel<<<NW / 1024, tb>>>(wo, w16o, NW);

    // HMMA QKV projections
    gemm16<<<dim3(12, 16), tb>>>(phs16, w16q, bq, pQ, S_HID, DMODEL, DMODEL);
    gemm16<<<dim3(12, 16), tb>>>(phs16, w16k, bk, pK, S_HID, DMODEL, DMODEL);
    gemm16<<<dim3(12, 16), tb>>>(phs16, w16v, bv, pV, S_HID, DMODEL, DMODEL);
    gemm16<<<dim3(12, 2),  tb>>>(penc16, w16ak, akb, pK + ENC_OFF, S_ENCC, DMODEL, DMODEL);
    gemm16<<<dim3(12, 2),  tb>>>(penc16, w16av, avb, pV + ENC_OFF, S_ENCC, DMODEL, DMODEL);

    // per-head RMSNorm on Q and K
    rmsnorm_kernel<<<(S_HID * HEADS) / 8, tb>>>(0, nqw, nqw, S_HID, S_HID);
    rmsnorm_kernel<<<(T_TOT * HEADS) / 8, tb>>>(1, nkw, nakw, T_TOT, S_HID);

    // flash attention (fp32 SIMT; HMMA port is next round's target)
    attn_kernel<<<dim3(S_HID / 64, HEADS), tb, sizeof(AttnSmem)>>>(mask);

    // output projection
    cvt_kernel<<<NHS / 1024, tb>>>(pO, pO16, NHS);
    gemm16<<<dim3(12, 16), tb>>>(pO16, w16o, bo, out, S_HID, DMODEL, DMODEL);
}

// round 5
// speedup vs baseline: 3.9811x; 1.7592x over previous
#include <cuda_runtime.h>
#include <cuda_fp16.h>
#include <cstdint>

// Problem constants
#define DMODEL 1536
#define HEADS  24
#define HDIM   64
#define S_HID  2048
#define S_ENCC 256
#define T_TOT  2304
#define NKT    (T_TOT / 64)   // 36 key tiles

// ---------------------------------------------------------------------------
// Scratch (__device__ globals; no allocations allowed)
// ---------------------------------------------------------------------------
__device__ __align__(1024) __half g_Q16[(size_t)S_HID * DMODEL];
__device__ __align__(1024) __half g_K16[(size_t)T_TOT * DMODEL];
__device__ __align__(1024) __half g_V16[(size_t)T_TOT * DMODEL];
__device__ __align__(1024) __half g_O16[(size_t)S_HID * DMODEL];
__device__ __align__(1024) __half g_hs16[(size_t)S_HID * DMODEL];
__device__ __align__(1024) __half g_enc16[(size_t)S_ENCC * DMODEL];
__device__ __align__(1024) __half g_w16[6][(size_t)DMODEL * DMODEL];

// ---------------------------------------------------------------------------
// PTX helpers (plain sm_103-safe)
// ---------------------------------------------------------------------------
__device__ __forceinline__ uint32_t smem_u32(const void* p) {
    return (uint32_t)__cvta_generic_to_shared(p);
}
__device__ __forceinline__ void cp_async16(uint32_t saddr, const void* gaddr) {
    asm volatile("cp.async.cg.shared.global [%0], [%1], 16;" :: "r"(saddr), "l"(gaddr) : "memory");
}
__device__ __forceinline__ void cp_async4(uint32_t saddr, const void* gaddr) {
    asm volatile("cp.async.ca.shared.global [%0], [%1], 4;" :: "r"(saddr), "l"(gaddr) : "memory");
}

#define LDMATRIX_X4(r0, r1, r2, r3, addr) \
    asm volatile("ldmatrix.sync.aligned.m8n8.x4.shared.b16 {%0,%1,%2,%3}, [%4];" \
                 : "=r"(r0), "=r"(r1), "=r"(r2), "=r"(r3) : "r"(addr))
#define LDMATRIX_X2T(r0, r1, addr) \
    asm volatile("ldmatrix.sync.aligned.m8n8.x2.trans.shared.b16 {%0,%1}, [%2];" \
                 : "=r"(r0), "=r"(r1) : "r"(addr))

#define MMA16816(d, a, b) \
    asm volatile("mma.sync.aligned.m16n8k16.row.col.f32.f16.f16.f32 " \
                 "{%0,%1,%2,%3}, {%4,%5,%6,%7}, {%8,%9}, {%0,%1,%2,%3};" \
                 : "+f"((d)[0]), "+f"((d)[1]), "+f"((d)[2]), "+f"((d)[3]) \
                 : "r"((a)[0]), "r"((a)[1]), "r"((a)[2]), "r"((a)[3]), \
                   "r"((b)[0]), "r"((b)[1]))

__device__ __forceinline__ uint32_t pack_h2(float x, float y) {
    union { __half2 h; uint32_t u; } p;
    p.h = __floats2half2_rn(x, y);
    return p.u;
}

// ---------------------------------------------------------------------------
// fp32 -> fp16 convert
// ---------------------------------------------------------------------------
__global__ __launch_bounds__(256) void cvt_kernel(const float* __restrict__ in,
                                                  __half* __restrict__ out, int n) {
    int i = (blockIdx.x * 256 + threadIdx.x) * 4;
    if (i < n) {
        float4 v = *(const float4*)(in + i);
        union { __half2 h[2]; uint2 u; } pk;
        pk.h[0] = __floats2half2_rn(v.x, v.y);
        pk.h[1] = __floats2half2_rn(v.z, v.w);
        *reinterpret_cast<uint2*>(out + i) = pk.u;
    }
}

// ---------------------------------------------------------------------------
// HMMA fp16 GEMM: C = A[M,K] @ W[N,K]^T + bias.  fp16 or fp32 output.
// BM=BN=128, BK=32, 256 threads (8 warps: 2m x 4n, 64x32 each).
// ---------------------------------------------------------------------------
#define PADK 40

__global__ __launch_bounds__(256) void gemm16(
    const __half* __restrict__ A, const __half* __restrict__ W,
    const float* __restrict__ bias,
    float* __restrict__ C32, __half* __restrict__ C16,
    int M, int N, int K)
{
    __shared__ __align__(16) __half sA[2][128 * PADK];
    __shared__ __align__(16) __half sW[2][128 * PADK];

    int tid = threadIdx.x;
    int wid = tid >> 5, lane = tid & 31;
    int wm = wid >> 2;
    int wn = wid & 3;
    int mbase = blockIdx.y << 7;
    int nbase = blockIdx.x << 7;
    const int NK = K >> 5;

    float acc[4][4][4];
#pragma unroll
    for (int mi = 0; mi < 4; mi++)
#pragma unroll
        for (int ni = 0; ni < 4; ni++)
#pragma unroll
            for (int e = 0; e < 4; e++) acc[mi][ni][e] = 0.f;

    auto load_tile = [&](int it) {
        int st = it & 1;
        int kb = it << 5;
#pragma unroll
        for (int i = 0; i < 2; i++) {
            int c = tid + (i << 8);
            int row = c >> 2;
            int col = (c & 3) << 3;
            cp_async16(smem_u32(&sA[st][row * PADK + col]),
                       A + (size_t)(mbase + row) * K + kb + col);
            cp_async16(smem_u32(&sW[st][row * PADK + col]),
                       W + (size_t)(nbase + row) * K + kb + col);
        }
        asm volatile("cp.async.commit_group;" ::: "memory");
    };

    load_tile(0);

    for (int it = 0; it < NK; it++) {
        int st = it & 1;
        if (it + 1 < NK) {
            load_tile(it + 1);
            asm volatile("cp.async.wait_group 1;" ::: "memory");
        } else {
            asm volatile("cp.async.wait_group 0;" ::: "memory");
        }
        __syncthreads();

#pragma unroll
        for (int ks = 0; ks < 2; ks++) {
            uint32_t afr[4][4];
#pragma unroll
            for (int mi = 0; mi < 4; mi++) {
                int m = wm * 64 + mi * 16 + (lane & 15);
                int kk = ks * 16 + ((lane >> 4) << 3);
                LDMATRIX_X4(afr[mi][0], afr[mi][1], afr[mi][2], afr[mi][3],
                            smem_u32(&sA[st][m * PADK + kk]));
            }
            uint32_t bfr[4][2];
#pragma unroll
            for (int nb = 0; nb < 2; nb++) {
                int n = wn * 32 + nb * 16 + (lane & 7) + (((lane >> 4) & 1) << 3);
                int kk = ks * 16 + (((lane >> 3) & 1) << 3);
                uint32_t r0, r1, r2, r3;
                LDMATRIX_X4(r0, r1, r2, r3, smem_u32(&sW[st][n * PADK + kk]));
                bfr[nb * 2][0] = r0; bfr[nb * 2][1] = r1;
                bfr[nb * 2 + 1][0] = r2; bfr[nb * 2 + 1][1] = r3;
            }
#pragma unroll
            for (int mi = 0; mi < 4; mi++)
#pragma unroll
                for (int ni = 0; ni < 4; ni++)
                    MMA16816(acc[mi][ni], afr[mi], bfr[ni]);
        }
        __syncthreads();
    }

    int g = lane >> 2, tq = lane & 3;
#pragma unroll
    for (int mi = 0; mi < 4; mi++) {
        int row0 = mbase + wm * 64 + mi * 16 + g;
#pragma unroll
        for (int ni = 0; ni < 4; ni++) {
            int col = nbase + wn * 32 + ni * 8 + tq * 2;
            float bx = bias[col], by = bias[col + 1];
            float v00 = acc[mi][ni][0] + bx, v01 = acc[mi][ni][1] + by;
            float v10 = acc[mi][ni][2] + bx, v11 = acc[mi][ni][3] + by;
            if (C16) {
                *(__half2*)(C16 + (size_t)row0 * N + col) = __floats2half2_rn(v00, v01);
                *(__half2*)(C16 + (size_t)(row0 + 8) * N + col) = __floats2half2_rn(v10, v11);
            } else {
                *(float2*)(C32 + (size_t)row0 * N + col) = make_float2(v00, v01);
                *(float2*)(C32 + (size_t)(row0 + 8) * N + col) = make_float2(v10, v11);
            }
        }
    }
}

// ---------------------------------------------------------------------------
// Per-head RMSNorm on fp16 buffers (in place). One warp per (row, head).
// ---------------------------------------------------------------------------
__global__ __launch_bounds__(256) void rmsnorm16(
    int which, const float* __restrict__ w0, const float* __restrict__ w1,
    int nrows, int split)
{
    __half* buf = which ? g_K16 : g_Q16;
    int chunk = blockIdx.x * 8 + (threadIdx.x >> 5);
    int lane = threadIdx.x & 31;
    int row = chunk / HEADS;
    if (row >= nrows) return;
    int head = chunk % HEADS;

    __half2* p = (__half2*)(buf + (size_t)row * DMODEL + head * HDIM);
    float2 x = __half22float2(p[lane]);
    float ss = x.x * x.x + x.y * x.y;
#pragma unroll
    for (int o = 16; o; o >>= 1) ss += __shfl_xor_sync(0xffffffffu, ss, o);
    float r = rsqrtf(ss * (1.0f / 64.0f) + 1e-6f);
    const float* w = (row < split) ? w0 : w1;
    p[lane] = __floats2half2_rn(x.x * r * w[2 * lane], x.y * r * w[2 * lane + 1]);
}

// ---------------------------------------------------------------------------
// HMMA flash attention (FA2-style). 128 threads (4 warps x m16 rows).
// BQ=64, BK=64, HD=64. K: ldmatrix.x4 (K-major), V: ldmatrix.x2.trans.
// P stays in registers (S accum -> A fragment identity).
// ---------------------------------------------------------------------------
#define PADA 72

__global__ __launch_bounds__(128, 4) void attn_kernel(const float* __restrict__ mask)
{
    __shared__ __align__(16) __half sQ[64 * PADA];
    __shared__ __align__(16) __half sK[2][64 * PADA];
    __shared__ __align__(16) __half sV[2][64 * PADA];
    __shared__ float smsk[2][64];

    int tid = threadIdx.x;
    int wm = tid >> 5, lane = tid & 31;
    int g = lane >> 2, tq = lane & 3;
    int head = blockIdx.y;
    int qbase = blockIdx.x << 6;
    int hoff = head * HDIM;

    auto load_kv = [&](int kt, int st) {
        int kbase = kt << 6;
#pragma unroll
        for (int i = 0; i < 4; i++) {
            int c = tid + (i << 7);          // 0..511
            int row = c >> 3, col = (c & 7) << 3;
            size_t goff = (size_t)(kbase + row) * DMODEL + hoff + col;
            cp_async16(smem_u32(&sK[st][row * PADA + col]), g_K16 + goff);
            cp_async16(smem_u32(&sV[st][row * PADA + col]), g_V16 + goff);
        }
        if (tid < 64) cp_async4(smem_u32(&smsk[st][tid]), mask + kbase + tid);
        asm volatile("cp.async.commit_group;" ::: "memory");
    };

    // Q tile load (one group) + first K/V tile
#pragma unroll
    for (int i = 0; i < 4; i++) {
        int c = tid + (i << 7);
        int row = c >> 3, col = (c & 7) << 3;
        cp_async16(smem_u32(&sQ[row * PADA + col]),
                   g_Q16 + (size_t)(qbase + row) * DMODEL + hoff + col);
    }
    asm volatile("cp.async.commit_group;" ::: "memory");
    load_kv(0, 0);
    asm volatile("cp.async.wait_group 0;" ::: "memory");
    __syncthreads();

    // Q fragments (held for whole kernel)
    uint32_t qfr[4][4];
#pragma unroll
    for (int kc = 0; kc < 4; kc++) {
        int m = wm * 16 + (lane & 15);
        int kk = kc * 16 + ((lane >> 4) << 3);
        LDMATRIX_X4(qfr[kc][0], qfr[kc][1], qfr[kc][2], qfr[kc][3],
                    smem_u32(&sQ[m * PADA + kk]));
    }

    float o[8][4];
#pragma unroll
    for (int nt = 0; nt < 8; nt++)
#pragma unroll
        for (int e = 0; e < 4; e++) o[nt][e] = 0.f;
    float m_lo = -3e38f, m_hi = -3e38f, l_lo = 0.f, l_hi = 0.f;
    const float scale = 0.125f;

    for (int kt = 0; kt < NKT; kt++) {
        int st = kt & 1;
        if (kt + 1 < NKT) {
            load_kv(kt + 1, st ^ 1);
            asm volatile("cp.async.wait_group 1;" ::: "memory");
        } else {
            asm volatile("cp.async.wait_group 0;" ::: "memory");
        }
        __syncthreads();

        // ---- S = Q @ K^T ----
        float sa[8][4];
#pragma unroll
        for (int nt = 0; nt < 8; nt++)
#pragma unroll
            for (int e = 0; e < 4; e++) sa[nt][e] = 0.f;

#pragma unroll
        for (int kc = 0; kc < 4; kc++) {
            uint32_t kf[8][2];
#pragma unroll
            for (int ntp = 0; ntp < 4; ntp++) {
                int n = ntp * 16 + (lane & 7) + (((lane >> 4) & 1) << 3);
                int kk = kc * 16 + (((lane >> 3) & 1) << 3);
                uint32_t r0, r1, r2, r3;
                LDMATRIX_X4(r0, r1, r2, r3, smem_u32(&sK[st][n * PADA + kk]));
                kf[ntp * 2][0] = r0; kf[ntp * 2][1] = r1;
                kf[ntp * 2 + 1][0] = r2; kf[ntp * 2 + 1][1] = r3;
            }
#pragma unroll
            for (int nt = 0; nt < 8; nt++)
                MMA16816(sa[nt], qfr[kc], kf[nt]);
        }

        // ---- scale + mask + online softmax (rows g and g+8) ----
        float mx_lo = -3e38f, mx_hi = -3e38f;
#pragma unroll
        for (int nt = 0; nt < 8; nt++) {
            float mk0 = smsk[st][nt * 8 + 2 * tq];
            float mk1 = smsk[st][nt * 8 + 2 * tq + 1];
            sa[nt][0] = sa[nt][0] * scale + mk0;
            sa[nt][1] = sa[nt][1] * scale + mk1;
            sa[nt][2] = sa[nt][2] * scale + mk0;
            sa[nt][3] = sa[nt][3] * scale + mk1;
            mx_lo = fmaxf(mx_lo, fmaxf(sa[nt][0], sa[nt][1]));
            mx_hi = fmaxf(mx_hi, fmaxf(sa[nt][2], sa[nt][3]));
        }
#pragma unroll
        for (int off = 1; off < 4; off <<= 1) {
            mx_lo = fmaxf(mx_lo, __shfl_xor_sync(0xffffffffu, mx_lo, off));
            mx_hi = fmaxf(mx_hi, __shfl_xor_sync(0xffffffffu, mx_hi, off));
        }
        float mn_lo = fmaxf(m_lo, mx_lo), mn_hi = fmaxf(m_hi, mx_hi);
        float cr_lo = __expf(m_lo - mn_lo), cr_hi = __expf(m_hi - mn_hi);
        m_lo = mn_lo; m_hi = mn_hi;

        float sum_lo = 0.f, sum_hi = 0.f;
#pragma unroll
        for (int nt = 0; nt < 8; nt++) {
            sa[nt][0] = __expf(sa[nt][0] - m_lo);
            sa[nt][1] = __expf(sa[nt][1] - m_lo);
            sa[nt][2] = __expf(sa[nt][2] - m_hi);
            sa[nt][3] = __expf(sa[nt][3] - m_hi);
            sum_lo += sa[nt][0] + sa[nt][1];
            sum_hi += sa[nt][2] + sa[nt][3];
        }
#pragma unroll
        for (int off = 1; off < 4; off <<= 1) {
            sum_lo += __shfl_xor_sync(0xffffffffu, sum_lo, off);
            sum_hi += __shfl_xor_sync(0xffffffffu, sum_hi, off);
        }
        l_lo = l_lo * cr_lo + sum_lo;
        l_hi = l_hi * cr_hi + sum_hi;

#pragma unroll
        for (int nt = 0; nt < 8; nt++) {
            o[nt][0] *= cr_lo; o[nt][1] *= cr_lo;
            o[nt][2] *= cr_hi; o[nt][3] *= cr_hi;
        }

        // ---- O += P @ V  (P from S accum registers) ----
#pragma unroll
        for (int c = 0; c < 4; c++) {
            uint32_t pa[4];
            pa[0] = pack_h2(sa[2 * c][0], sa[2 * c][1]);
            pa[1] = pack_h2(sa[2 * c][2], sa[2 * c][3]);
            pa[2] = pack_h2(sa[2 * c + 1][0], sa[2 * c + 1][1]);
            pa[3] = pack_h2(sa[2 * c + 1][2], sa[2 * c + 1][3]);
#pragma unroll
            for (int ntd = 0; ntd < 8; ntd++) {
                uint32_t vb[2];
                LDMATRIX_X2T(vb[0], vb[1],
                             smem_u32(&sV[st][(c * 16 + (lane & 15)) * PADA + ntd * 8]));
                MMA16816(o[ntd], pa, vb);
            }
        }
        __syncthreads();
    }

    // ---- finalize & store fp16 ----
    float inv_lo = 1.f / l_lo, inv_hi = 1.f / l_hi;
    int row_lo = qbase + wm * 16 + g;
#pragma unroll
    for (int nt = 0; nt < 8; nt++) {
        int col = hoff + nt * 8 + 2 * tq;
        *(__half2*)(g_O16 + (size_t)row_lo * DMODEL + col) =
            __floats2half2_rn(o[nt][0] * inv_lo, o[nt][1] * inv_lo);
        *(__half2*)(g_O16 + (size_t)(row_lo + 8) * DMODEL + col) =
            __floats2half2_rn(o[nt][2] * inv_hi, o[nt][3] * inv_hi);
    }
}

// ---------------------------------------------------------------------------
// kernel_launch
// ---------------------------------------------------------------------------
extern "C" void kernel_launch(void* const* d_in, const int* in_sizes, int n_in,
                              void* d_out, int out_size)
{
    (void)in_sizes; (void)n_in; (void)out_size;
    const float* hs   = (const float*)d_in[0];
    const float* enc  = (const float*)d_in[1];
    const float* mask = (const float*)d_in[2];
    const float* wq   = (const float*)d_in[3];
    const float* bq   = (const float*)d_in[4];
    const float* wk   = (const float*)d_in[5];
    const float* bk   = (const float*)d_in[6];
    const float* wv   = (const float*)d_in[7];
    const float* bv   = (const float*)d_in[8];
    const float* nqw  = (const float*)d_in[9];
    const float* nkw  = (const float*)d_in[10];
    const float* akw  = (const float*)d_in[13];
    const float* akb  = (const float*)d_in[14];
    const float* avw  = (const float*)d_in[15];
    const float* avb  = (const float*)d_in[16];
    const float* nakw = (const float*)d_in[18];
    const float* wo   = (const float*)d_in[19];
    const float* bo   = (const float*)d_in[20];
    float* out = (float*)d_out;

    __half *pQ16, *pK16, *pV16, *pO16, *phs16, *penc16, *pw16;
    cudaGetSymbolAddress((void**)&pQ16, g_Q16);
    cudaGetSymbolAddress((void**)&pK16, g_K16);
    cudaGetSymbolAddress((void**)&pV16, g_V16);
    cudaGetSymbolAddress((void**)&pO16, g_O16);
    cudaGetSymbolAddress((void**)&phs16, g_hs16);
    cudaGetSymbolAddress((void**)&penc16, g_enc16);
    cudaGetSymbolAddress((void**)&pw16, g_w16);
    __half* w16q  = pw16 + 0 * (size_t)DMODEL * DMODEL;
    __half* w16k  = pw16 + 1 * (size_t)DMODEL * DMODEL;
    __half* w16v  = pw16 + 2 * (size_t)DMODEL * DMODEL;
    __half* w16ak = pw16 + 3 * (size_t)DMODEL * DMODEL;
    __half* w16av = pw16 + 4 * (size_t)DMODEL * DMODEL;
    __half* w16o  = pw16 + 5 * (size_t)DMODEL * DMODEL;

    dim3 tb(256);
    const int NHS = S_HID * DMODEL, NENC = S_ENCC * DMODEL, NW = DMODEL * DMODEL;
    const int ENC_OFF = S_HID * DMODEL;

    // fp32 -> fp16 converts
    cvt_kernel<<<NHS / 1024, tb>>>(hs, phs16, NHS);
    cvt_kernel<<<NENC / 1024, tb>>>(enc, penc16, NENC);
    cvt_kernel<<<NW / 1024, tb>>>(wq, w16q, NW);
    cvt_kernel<<<NW / 1024, tb>>>(wk, w16k, NW);
    cvt_kernel<<<NW / 1024, tb>>>(wv, w16v, NW);
    cvt_kernel<<<NW / 1024, tb>>>(akw, w16ak, NW);
    cvt_kernel<<<NW / 1024, tb>>>(avw, w16av, NW);
    cvt_kernel<<<NW / 1024, tb>>>(wo, w16o, NW);

    // HMMA QKV projections -> fp16
    gemm16<<<dim3(12, 16), tb>>>(phs16, w16q, bq, nullptr, pQ16, S_HID, DMODEL, DMODEL);
    gemm16<<<dim3(12, 16), tb>>>(phs16, w16k, bk, nullptr, pK16, S_HID, DMODEL, DMODEL);
    gemm16<<<dim3(12, 16), tb>>>(phs16, w16v, bv, nullptr, pV16, S_HID, DMODEL, DMODEL);
    gemm16<<<dim3(12, 2),  tb>>>(penc16, w16ak, akb, nullptr, pK16 + ENC_OFF, S_ENCC, DMODEL, DMODEL);
    gemm16<<<dim3(12, 2),  tb>>>(penc16, w16av, avb, nullptr, pV16 + ENC_OFF, S_ENCC, DMODEL, DMODEL);

    // per-head RMSNorm (in place, fp16)
    rmsnorm16<<<(S_HID * HEADS) / 8, tb>>>(0, nqw, nqw, S_HID, S_HID);
    rmsnorm16<<<(T_TOT * HEADS) / 8, tb>>>(1, nkw, nakw, T_TOT, S_HID);

    // HMMA flash attention -> fp16
    attn_kernel<<<dim3(S_HID / 64, HEADS), 128>>>(mask);

    // output projection -> fp32
    gemm16<<<dim3(12, 16), tb>>>(pO16, w16o, bo, out, nullptr, S_HID, DMODEL, DMODEL);
}

// round 7
// speedup vs baseline: 8.2594x; 2.0747x over previous
#include <cuda_runtime.h>
#include <cuda_fp16.h>
#include <cstdint>

// Problem constants
#define DMODEL 1536
#define HEADS  24
#define HDIM   64
#define S_HID  2048
#define S_ENCC 256
#define T_TOT  2304
#define NKT    (T_TOT / 64)           // 36 key tiles
#define NW     (DMODEL * DMODEL)      // weight elements

// ---------------------------------------------------------------------------
// Scratch (__device__ globals; no allocations allowed)
// ---------------------------------------------------------------------------
__device__ __align__(1024) __half g_Q16[(size_t)S_HID * DMODEL];
__device__ __align__(1024) __half g_K16[(size_t)T_TOT * DMODEL];
__device__ __align__(1024) __half g_V16[(size_t)T_TOT * DMODEL];
__device__ __align__(1024) __half g_O16[(size_t)S_HID * DMODEL];
__device__ __align__(1024) __half g_hs16[(size_t)S_HID * DMODEL];
__device__ __align__(1024) __half g_enc16[(size_t)S_ENCC * DMODEL];
__device__ __align__(1024) __half g_w16[6][(size_t)NW];

// ---------------------------------------------------------------------------
// PTX helpers (plain sm_103-safe)
// ---------------------------------------------------------------------------
__device__ __forceinline__ uint32_t smem_u32(const void* p) {
    return (uint32_t)__cvta_generic_to_shared(p);
}
__device__ __forceinline__ void cp_async16(uint32_t saddr, const void* gaddr) {
    asm volatile("cp.async.cg.shared.global [%0], [%1], 16;" :: "r"(saddr), "l"(gaddr) : "memory");
}
__device__ __forceinline__ void cp_async4(uint32_t saddr, const void* gaddr) {
    asm volatile("cp.async.ca.shared.global [%0], [%1], 4;" :: "r"(saddr), "l"(gaddr) : "memory");
}

#define CP_COMMIT()  asm volatile("cp.async.commit_group;" ::: "memory")
#define CP_WAIT(n)   asm volatile("cp.async.wait_group %0;" :: "n"(n) : "memory")

#define LDMATRIX_X4(r0, r1, r2, r3, addr) \
    asm volatile("ldmatrix.sync.aligned.m8n8.x4.shared.b16 {%0,%1,%2,%3}, [%4];" \
                 : "=r"(r0), "=r"(r1), "=r"(r2), "=r"(r3) : "r"(addr))
#define LDMATRIX_X2T(r0, r1, addr) \
    asm volatile("ldmatrix.sync.aligned.m8n8.x2.trans.shared.b16 {%0,%1}, [%2];" \
                 : "=r"(r0), "=r"(r1) : "r"(addr))

#define MMA16816(d, a, b) \
    asm volatile("mma.sync.aligned.m16n8k16.row.col.f32.f16.f16.f32 " \
                 "{%0,%1,%2,%3}, {%4,%5,%6,%7}, {%8,%9}, {%0,%1,%2,%3};" \
                 : "+f"((d)[0]), "+f"((d)[1]), "+f"((d)[2]), "+f"((d)[3]) \
                 : "r"((a)[0]), "r"((a)[1]), "r"((a)[2]), "r"((a)[3]), \
                   "r"((b)[0]), "r"((b)[1]))

__device__ __forceinline__ uint32_t pack_h2(float x, float y) {
    union { __half2 h; uint32_t u; } p;
    p.h = __floats2half2_rn(x, y);
    return p.u;
}

// ---------------------------------------------------------------------------
// Fused converts
// ---------------------------------------------------------------------------
__global__ __launch_bounds__(256) void cvt_act(const float* __restrict__ hs,
                                               const float* __restrict__ enc) {
    int i = (blockIdx.x * 256 + threadIdx.x) * 4;
    const int NHS = S_HID * DMODEL;
    const float* src;
    __half* dst;
    if (i < NHS) { src = hs + i; dst = g_hs16 + i; }
    else { src = enc + (i - NHS); dst = g_enc16 + (i - NHS); }
    float4 v = *(const float4*)src;
    union { __half2 h[2]; uint2 u; } pk;
    pk.h[0] = __floats2half2_rn(v.x, v.y);
    pk.h[1] = __floats2half2_rn(v.z, v.w);
    *reinterpret_cast<uint2*>(dst) = pk.u;
}

struct Ptr6 { const float* p[6]; };

__global__ __launch_bounds__(256) void cvt_weights(Ptr6 srcs) {
    int i = (blockIdx.x * 256 + threadIdx.x) * 4;
    int seg = i / NW;
    int off = i - seg * NW;
    float4 v = *(const float4*)(srcs.p[seg] + off);
    union { __half2 h[2]; uint2 u; } pk;
    pk.h[0] = __floats2half2_rn(v.x, v.y);
    pk.h[1] = __floats2half2_rn(v.z, v.w);
    *reinterpret_cast<uint2*>(&g_w16[seg][off]) = pk.u;
}

// ---------------------------------------------------------------------------
// Fused HMMA GEMM: for seg s, C_s = A @ W_s^T + bias_s.
// W_s contiguous slots starting at Wbase. BM=BN=128, BK=32, 256 thr,
// 3-stage cp.async pipeline, ONE barrier per k-iter.
// ---------------------------------------------------------------------------
#define PADK 40
#define G_STAGE_H (2 * 128 * PADK)            // halfs per stage (A then W)
#define GEMM_SMEM (3 * G_STAGE_H * 2)         // bytes

struct GemmArgs {
    const float* bias[3];
    __half* out16[3];
    float* out32;
};

__global__ __launch_bounds__(256, 2) void gemm_fused(
    const __half* __restrict__ A, const __half* __restrict__ Wbase,
    GemmArgs args, int M)
{
    extern __shared__ __half smg[];

    int tid = threadIdx.x;
    int wid = tid >> 5, lane = tid & 31;
    int wm = wid >> 2;
    int wn = wid & 3;
    int seg = blockIdx.x / 12;
    int nbase = (blockIdx.x % 12) << 7;
    int mbase = blockIdx.y << 7;
    const int K = DMODEL, N = DMODEL;
    const int NK = K >> 5;   // 48

    const __half* W = Wbase + (size_t)seg * NW;

    float acc[4][4][4];
#pragma unroll
    for (int mi = 0; mi < 4; mi++)
#pragma unroll
        for (int ni = 0; ni < 4; ni++)
#pragma unroll
            for (int e = 0; e < 4; e++) acc[mi][ni][e] = 0.f;

    auto load_tile = [&](int it) {
        __half* sA = smg + (it % 3) * G_STAGE_H;
        __half* sW = sA + 128 * PADK;
        int kb = it << 5;
#pragma unroll
        for (int i = 0; i < 2; i++) {
            int c = tid + (i << 8);
            int row = c >> 2;
            int col = (c & 3) << 3;
            cp_async16(smem_u32(&sA[row * PADK + col]),
                       A + (size_t)(mbase + row) * K + kb + col);
            cp_async16(smem_u32(&sW[row * PADK + col]),
                       W + (size_t)(nbase + row) * K + kb + col);
        }
        CP_COMMIT();
    };

    load_tile(0);
    load_tile(1);

    for (int it = 0; it < NK; it++) {
        if (it + 1 < NK) CP_WAIT(1); else CP_WAIT(0);
        __syncthreads();
        if (it + 2 < NK) load_tile(it + 2);

        const __half* sA = smg + (it % 3) * G_STAGE_H;
        const __half* sW = sA + 128 * PADK;
#pragma unroll
        for (int ks = 0; ks < 2; ks++) {
            uint32_t afr[4][4];
#pragma unroll
            for (int mi = 0; mi < 4; mi++) {
                int m = wm * 64 + mi * 16 + (lane & 15);
                int kk = ks * 16 + ((lane >> 4) << 3);
                LDMATRIX_X4(afr[mi][0], afr[mi][1], afr[mi][2], afr[mi][3],
                            smem_u32(&sA[m * PADK + kk]));
            }
            uint32_t bfr[4][2];
#pragma unroll
            for (int nb = 0; nb < 2; nb++) {
                int n = wn * 32 + nb * 16 + (lane & 7) + (((lane >> 4) & 1) << 3);
                int kk = ks * 16 + (((lane >> 3) & 1) << 3);
                uint32_t r0, r1, r2, r3;
                LDMATRIX_X4(r0, r1, r2, r3, smem_u32(&sW[n * PADK + kk]));
                bfr[nb * 2][0] = r0; bfr[nb * 2][1] = r1;
                bfr[nb * 2 + 1][0] = r2; bfr[nb * 2 + 1][1] = r3;
            }
#pragma unroll
            for (int mi = 0; mi < 4; mi++)
#pragma unroll
                for (int ni = 0; ni < 4; ni++)
                    MMA16816(acc[mi][ni], afr[mi], bfr[ni]);
        }
    }

    const float* bias = args.bias[seg];
    __half* O16 = args.out16[seg];
    int g = lane >> 2, tq = lane & 3;
#pragma unroll
    for (int mi = 0; mi < 4; mi++) {
        int row0 = mbase + wm * 64 + mi * 16 + g;
#pragma unroll
        for (int ni = 0; ni < 4; ni++) {
            int col = nbase + wn * 32 + ni * 8 + tq * 2;
            float bx = bias[col], by = bias[col + 1];
            float v00 = acc[mi][ni][0] + bx, v01 = acc[mi][ni][1] + by;
            float v10 = acc[mi][ni][2] + bx, v11 = acc[mi][ni][3] + by;
            if (args.out32) {
                *(float2*)(args.out32 + (size_t)row0 * N + col) = make_float2(v00, v01);
                *(float2*)(args.out32 + (size_t)(row0 + 8) * N + col) = make_float2(v10, v11);
            } else {
                *(__half2*)(O16 + (size_t)row0 * N + col) = __floats2half2_rn(v00, v01);
                *(__half2*)(O16 + (size_t)(row0 + 8) * N + col) = __floats2half2_rn(v10, v11);
            }
        }
    }
}

// ---------------------------------------------------------------------------
// Fused per-head RMSNorm on Q16 and K16 (in place). One warp per chunk.
// ---------------------------------------------------------------------------
#define QCHUNKS (S_HID * HEADS)
#define KCHUNKS (T_TOT * HEADS)

__global__ __launch_bounds__(256) void rms_fused(
    const float* __restrict__ wq, const float* __restrict__ wk,
    const float* __restrict__ wak)
{
    int chunk = blockIdx.x * 8 + (threadIdx.x >> 5);
    int lane = threadIdx.x & 31;

    __half* buf;
    const float* w;
    int row, head;
    if (chunk < QCHUNKS) {
        buf = g_Q16; row = chunk / HEADS; head = chunk % HEADS; w = wq;
    } else {
        int c = chunk - QCHUNKS;
        buf = g_K16; row = c / HEADS; head = c % HEADS;
        w = (row < S_HID) ? wk : wak;
    }

    __half2* p = (__half2*)(buf + (size_t)row * DMODEL + head * HDIM);
    float2 x = __half22float2(p[lane]);
    float ss = x.x * x.x + x.y * x.y;
#pragma unroll
    for (int o = 16; o; o >>= 1) ss += __shfl_xor_sync(0xffffffffu, ss, o);
    float r = rsqrtf(ss * (1.0f / 64.0f) + 1e-6f);
    p[lane] = __floats2half2_rn(x.x * r * w[2 * lane], x.y * r * w[2 * lane + 1]);
}

// ---------------------------------------------------------------------------
// HMMA flash attention, 3-stage K/V pipeline, one barrier per tile.
// 128 threads (4 warps x m16 rows), BQ=BK=64.
// ---------------------------------------------------------------------------
#define PADA 72
#define A_TILE_H (64 * PADA)                     // halfs per K or V tile
// smem layout (halfs): Q[0,4608) | K stages 3x4608 | V stages 3x4608 | mask
#define ATTN_MSK_OFF (7 * A_TILE_H * 2)          // byte offset of float msk[3][64]
#define ATTN_SMEM (ATTN_MSK_OFF + 3 * 64 * 4)

__global__ __launch_bounds__(128, 3) void attn_kernel(const float* __restrict__ mask)
{
    extern __shared__ __half sm[];
    __half* sQ = sm;
    float* smsk = (float*)((char*)sm + ATTN_MSK_OFF);

    int tid = threadIdx.x;
    int wm = tid >> 5, lane = tid & 31;
    int g = lane >> 2, tq = lane & 3;
    int head = blockIdx.y;
    int qbase = blockIdx.x << 6;
    int hoff = head * HDIM;

    auto load_kv = [&](int kt) {
        int st = kt % 3;
        __half* sK = sm + (1 + st) * A_TILE_H;
        __half* sV = sm + (4 + st) * A_TILE_H;
        int kbase = kt << 6;
#pragma unroll
        for (int i = 0; i < 4; i++) {
            int c = tid + (i << 7);
            int row = c >> 3, col = (c & 7) << 3;
            size_t goff = (size_t)(kbase + row) * DMODEL + hoff + col;
            cp_async16(smem_u32(&sK[row * PADA + col]), g_K16 + goff);
            cp_async16(smem_u32(&sV[row * PADA + col]), g_V16 + goff);
        }
        if (tid < 64) cp_async4(smem_u32(&smsk[st * 64 + tid]), mask + kbase + tid);
        CP_COMMIT();
    };

    // group 0: Q + KV tile 0; group 1: KV tile 1
#pragma unroll
    for (int i = 0; i < 4; i++) {
        int c = tid + (i << 7);
        int row = c >> 3, col = (c & 7) << 3;
        cp_async16(smem_u32(&sQ[row * PADA + col]),
                   g_Q16 + (size_t)(qbase + row) * DMODEL + hoff + col);
    }
    {
        int st = 0;
        __half* sK = sm + A_TILE_H;
        __half* sV = sm + 4 * A_TILE_H;
#pragma unroll
        for (int i = 0; i < 4; i++) {
            int c = tid + (i << 7);
            int row = c >> 3, col = (c & 7) << 3;
            size_t goff = (size_t)row * DMODEL + hoff + col;
            cp_async16(smem_u32(&sK[row * PADA + col]), g_K16 + goff);
            cp_async16(smem_u32(&sV[row * PADA + col]), g_V16 + goff);
        }
        if (tid < 64) cp_async4(smem_u32(&smsk[st * 64 + tid]), mask + tid);
        CP_COMMIT();
    }
    load_kv(1);

    uint32_t qfr[4][4];
    float o[8][4];
#pragma unroll
    for (int nt = 0; nt < 8; nt++)
#pragma unroll
        for (int e = 0; e < 4; e++) o[nt][e] = 0.f;
    float m_lo = -3e38f, m_hi = -3e38f, l_lo = 0.f, l_hi = 0.f;
    const float scale = 0.125f;

    for (int kt = 0; kt < NKT; kt++) {
        if (kt + 1 < NKT) CP_WAIT(1); else CP_WAIT(0);
        __syncthreads();
        if (kt == 0) {
#pragma unroll
            for (int kc = 0; kc < 4; kc++) {
                int m = wm * 16 + (lane & 15);
                int kk = kc * 16 + ((lane >> 4) << 3);
                LDMATRIX_X4(qfr[kc][0], qfr[kc][1], qfr[kc][2], qfr[kc][3],
                            smem_u32(&sQ[m * PADA + kk]));
            }
        }
        if (kt + 2 < NKT) load_kv(kt + 2);

        int st = kt % 3;
        const __half* sK = sm + (1 + st) * A_TILE_H;
        const __half* sV = sm + (4 + st) * A_TILE_H;
        const float* mk = smsk + st * 64;

        // ---- S = Q @ K^T ----
        float sa[8][4];
#pragma unroll
        for (int nt = 0; nt < 8; nt++)
#pragma unroll
            for (int e = 0; e < 4; e++) sa[nt][e] = 0.f;

#pragma unroll
        for (int kc = 0; kc < 4; kc++) {
            uint32_t kf[8][2];
#pragma unroll
            for (int ntp = 0; ntp < 4; ntp++) {
                int n = ntp * 16 + (lane & 7) + (((lane >> 4) & 1) << 3);
                int kk = kc * 16 + (((lane >> 3) & 1) << 3);
                uint32_t r0, r1, r2, r3;
                LDMATRIX_X4(r0, r1, r2, r3, smem_u32(&sK[n * PADA + kk]));
                kf[ntp * 2][0] = r0; kf[ntp * 2][1] = r1;
                kf[ntp * 2 + 1][0] = r2; kf[ntp * 2 + 1][1] = r3;
            }
#pragma unroll
            for (int nt = 0; nt < 8; nt++)
                MMA16816(sa[nt], qfr[kc], kf[nt]);
        }

        // ---- scale + mask + online softmax ----
        float mx_lo = -3e38f, mx_hi = -3e38f;
#pragma unroll
        for (int nt = 0; nt < 8; nt++) {
            float mk0 = mk[nt * 8 + 2 * tq];
            float mk1 = mk[nt * 8 + 2 * tq + 1];
            sa[nt][0] = sa[nt][0] * scale + mk0;
            sa[nt][1] = sa[nt][1] * scale + mk1;
            sa[nt][2] = sa[nt][2] * scale + mk0;
            sa[nt][3] = sa[nt][3] * scale + mk1;
            mx_lo = fmaxf(mx_lo, fmaxf(sa[nt][0], sa[nt][1]));
            mx_hi = fmaxf(mx_hi, fmaxf(sa[nt][2], sa[nt][3]));
        }
#pragma unroll
        for (int off = 1; off < 4; off <<= 1) {
            mx_lo = fmaxf(mx_lo, __shfl_xor_sync(0xffffffffu, mx_lo, off));
            mx_hi = fmaxf(mx_hi, __shfl_xor_sync(0xffffffffu, mx_hi, off));
        }
        float mn_lo = fmaxf(m_lo, mx_lo), mn_hi = fmaxf(m_hi, mx_hi);
        float cr_lo = __expf(m_lo - mn_lo), cr_hi = __expf(m_hi - mn_hi);
        m_lo = mn_lo; m_hi = mn_hi;

        float sum_lo = 0.f, sum_hi = 0.f;
#pragma unroll
        for (int nt = 0; nt < 8; nt++) {
            sa[nt][0] = __expf(sa[nt][0] - m_lo);
            sa[nt][1] = __expf(sa[nt][1] - m_lo);
            sa[nt][2] = __expf(sa[nt][2] - m_hi);
            sa[nt][3] = __expf(sa[nt][3] - m_hi);
            sum_lo += sa[nt][0] + sa[nt][1];
            sum_hi += sa[nt][2] + sa[nt][3];
        }
#pragma unroll
        for (int off = 1; off < 4; off <<= 1) {
            sum_lo += __shfl_xor_sync(0xffffffffu, sum_lo, off);
            sum_hi += __shfl_xor_sync(0xffffffffu, sum_hi, off);
        }
        l_lo = l_lo * cr_lo + sum_lo;
        l_hi = l_hi * cr_hi + sum_hi;

#pragma unroll
        for (int nt = 0; nt < 8; nt++) {
            o[nt][0] *= cr_lo; o[nt][1] *= cr_lo;
            o[nt][2] *= cr_hi; o[nt][3] *= cr_hi;
        }

        // ---- O += P @ V ----
#pragma unroll
        for (int c = 0; c < 4; c++) {
            uint32_t pa[4];
            pa[0] = pack_h2(sa[2 * c][0], sa[2 * c][1]);
            pa[1] = pack_h2(sa[2 * c][2], sa[2 * c][3]);
            pa[2] = pack_h2(sa[2 * c + 1][0], sa[2 * c + 1][1]);
            pa[3] = pack_h2(sa[2 * c + 1][2], sa[2 * c + 1][3]);
#pragma unroll
            for (int ntd = 0; ntd < 8; ntd++) {
                uint32_t vb[2];
                LDMATRIX_X2T(vb[0], vb[1],
                             smem_u32(&sV[(c * 16 + (lane & 15)) * PADA + ntd * 8]));
                MMA16816(o[ntd], pa, vb);
            }
        }
    }

    // ---- finalize & store fp16 ----
    float inv_lo = 1.f / l_lo, inv_hi = 1.f / l_hi;
    int row_lo = qbase + wm * 16 + g;
#pragma unroll
    for (int nt = 0; nt < 8; nt++) {
        int col = hoff + nt * 8 + 2 * tq;
        *(__half2*)(g_O16 + (size_t)row_lo * DMODEL + col) =
            __floats2half2_rn(o[nt][0] * inv_lo, o[nt][1] * inv_lo);
        *(__half2*)(g_O16 + (size_t)(row_lo + 8) * DMODEL + col) =
            __floats2half2_rn(o[nt][2] * inv_hi, o[nt][3] * inv_hi);
    }
}

// ---------------------------------------------------------------------------
// kernel_launch (7 launches; #6 is attn for ncu -s 5 -c 1)
// ---------------------------------------------------------------------------
extern "C" void kernel_launch(void* const* d_in, const int* in_sizes, int n_in,
                              void* d_out, int out_size)
{
    (void)in_sizes; (void)n_in; (void)out_size;
    const float* hs   = (const float*)d_in[0];
    const float* enc  = (const float*)d_in[1];
    const float* mask = (const float*)d_in[2];
    const float* wq   = (const float*)d_in[3];
    const float* bq   = (const float*)d_in[4];
    const float* wk   = (const float*)d_in[5];
    const float* bk   = (const float*)d_in[6];
    const float* wv   = (const float*)d_in[7];
    const float* bv   = (const float*)d_in[8];
    const float* nqw  = (const float*)d_in[9];
    const float* nkw  = (const float*)d_in[10];
    const float* akw  = (const float*)d_in[13];
    const float* akb  = (const float*)d_in[14];
    const float* avw  = (const float*)d_in[15];
    const float* avb  = (const float*)d_in[16];
    const float* nakw = (const float*)d_in[18];
    const float* wo   = (const float*)d_in[19];
    const float* bo   = (const float*)d_in[20];
    float* out = (float*)d_out;

    __half *pQ16, *pK16, *pV16, *pO16, *phs16, *penc16, *pw16;
    cudaGetSymbolAddress((void**)&pQ16, g_Q16);
    cudaGetSymbolAddress((void**)&pK16, g_K16);
    cudaGetSymbolAddress((void**)&pV16, g_V16);
    cudaGetSymbolAddress((void**)&pO16, g_O16);
    cudaGetSymbolAddress((void**)&phs16, g_hs16);
    cudaGetSymbolAddress((void**)&penc16, g_enc16);
    cudaGetSymbolAddress((void**)&pw16, g_w16);

    cudaFuncSetAttribute(gemm_fused, cudaFuncAttributeMaxDynamicSharedMemorySize, GEMM_SMEM);
    cudaFuncSetAttribute(attn_kernel, cudaFuncAttributeMaxDynamicSharedMemorySize, ATTN_SMEM);

    dim3 tb(256);
    const int ENC_OFF = S_HID * DMODEL;

    // 1: activation converts (hidden + encoder)
    cvt_act<<<(S_HID + S_ENCC) * DMODEL / 1024, tb>>>(hs, enc);

    // 2: all 6 weight converts (order: q,k,v,ak,av,o -> g_w16 slots)
    Ptr6 wsrc; wsrc.p[0] = wq; wsrc.p[1] = wk; wsrc.p[2] = wv;
    wsrc.p[3] = akw; wsrc.p[4] = avw; wsrc.p[5] = wo;
    cvt_weights<<<6 * NW / 1024, tb>>>(wsrc);

    // 3: fused QKV projections (hidden stream)
    GemmArgs aqkv;
    aqkv.bias[0] = bq;  aqkv.bias[1] = bk;  aqkv.bias[2] = bv;
    aqkv.out16[0] = pQ16; aqkv.out16[1] = pK16; aqkv.out16[2] = pV16;
    aqkv.out32 = nullptr;
    gemm_fused<<<dim3(36, 16), tb, GEMM_SMEM>>>(phs16, pw16, aqkv, S_HID);

    // 4: fused encoder K/V projections
    GemmArgs aenc;
    aenc.bias[0] = akb; aenc.bias[1] = avb; aenc.bias[2] = nullptr;
    aenc.out16[0] = pK16 + ENC_OFF; aenc.out16[1] = pV16 + ENC_OFF; aenc.out16[2] = nullptr;
    aenc.out32 = nullptr;
    gemm_fused<<<dim3(24, 2), tb, GEMM_SMEM>>>(penc16, pw16 + 3 * (size_t)NW, aenc, S_ENCC);

    // 5: fused RMSNorm (Q + K)
    rms_fused<<<(QCHUNKS + KCHUNKS) / 8, tb>>>(nqw, nkw, nakw);

    // 6: flash attention  (ncu capture target)
    attn_kernel<<<dim3(S_HID / 64, HEADS), 128, ATTN_SMEM>>>(mask);

    // 7: output projection -> fp32
    GemmArgs aout;
    aout.bias[0] = bo; aout.bias[1] = nullptr; aout.bias[2] = nullptr;
    aout.out16[0] = nullptr; aout.out16[1] = nullptr; aout.out16[2] = nullptr;
    aout.out32 = out;
    gemm_fused<<<dim3(12, 16), tb, GEMM_SMEM>>>(pO16, pw16 + 5 * (size_t)NW, aout, S_HID);
}

// round 8
// speedup vs baseline: 8.3018x; 1.0051x over previous
#include <cuda_runtime.h>
#include <cuda_fp16.h>
#include <cstdint>

// Problem constants
#define DMODEL 1536
#define HEADS  24
#define HDIM   64
#define S_HID  2048
#define S_ENCC 256
#define T_TOT  2304
#define NKT    (T_TOT / 64)           // 36 key tiles
#define NW     (DMODEL * DMODEL)      // weight elements

// ---------------------------------------------------------------------------
// Scratch (__device__ globals; no allocations allowed)
// ---------------------------------------------------------------------------
__device__ __align__(1024) __half g_Q16[(size_t)S_HID * DMODEL];
__device__ __align__(1024) __half g_K16[(size_t)T_TOT * DMODEL];
__device__ __align__(1024) __half g_V16[(size_t)T_TOT * DMODEL];
__device__ __align__(1024) __half g_O16[(size_t)S_HID * DMODEL];
__device__ __align__(1024) __half g_hs16[(size_t)S_HID * DMODEL];
__device__ __align__(1024) __half g_enc16[(size_t)S_ENCC * DMODEL];
__device__ __align__(1024) __half g_w16[6][(size_t)NW];

// ---------------------------------------------------------------------------
// PTX helpers (plain sm_103-safe)
// ---------------------------------------------------------------------------
__device__ __forceinline__ uint32_t smem_u32(const void* p) {
    return (uint32_t)__cvta_generic_to_shared(p);
}
__device__ __forceinline__ void cp_async16(uint32_t saddr, const void* gaddr) {
    asm volatile("cp.async.cg.shared.global [%0], [%1], 16;" :: "r"(saddr), "l"(gaddr) : "memory");
}
__device__ __forceinline__ void cp_async4(uint32_t saddr, const void* gaddr) {
    asm volatile("cp.async.ca.shared.global [%0], [%1], 4;" :: "r"(saddr), "l"(gaddr) : "memory");
}

#define CP_COMMIT()  asm volatile("cp.async.commit_group;" ::: "memory")
#define CP_WAIT(n)   asm volatile("cp.async.wait_group %0;" :: "n"(n) : "memory")

#define LDMATRIX_X4(r0, r1, r2, r3, addr) \
    asm volatile("ldmatrix.sync.aligned.m8n8.x4.shared.b16 {%0,%1,%2,%3}, [%4];" \
                 : "=r"(r0), "=r"(r1), "=r"(r2), "=r"(r3) : "r"(addr))
#define LDMATRIX_X2T(r0, r1, addr) \
    asm volatile("ldmatrix.sync.aligned.m8n8.x2.trans.shared.b16 {%0,%1}, [%2];" \
                 : "=r"(r0), "=r"(r1) : "r"(addr))

#define MMA16816(d, a, b) \
    asm volatile("mma.sync.aligned.m16n8k16.row.col.f32.f16.f16.f32 " \
                 "{%0,%1,%2,%3}, {%4,%5,%6,%7}, {%8,%9}, {%0,%1,%2,%3};" \
                 : "+f"((d)[0]), "+f"((d)[1]), "+f"((d)[2]), "+f"((d)[3]) \
                 : "r"((a)[0]), "r"((a)[1]), "r"((a)[2]), "r"((a)[3]), \
                   "r"((b)[0]), "r"((b)[1]))

__device__ __forceinline__ uint32_t pack_h2(float x, float y) {
    union { __half2 h; uint32_t u; } p;
    p.h = __floats2half2_rn(x, y);
    return p.u;
}

// ---------------------------------------------------------------------------
// Single fused convert: hidden act + encoder act + all 6 weights
// block ranges: [0,3072) hs, [3072,3456) enc, [3456,17280) weights (2304 ea)
// ---------------------------------------------------------------------------
struct Ptr6 { const float* p[6]; };

#define CVT_BLOCKS (3072 + 384 + 6 * 2304)

__global__ __launch_bounds__(256) void cvt_all(const float* __restrict__ hs,
                                               const float* __restrict__ enc,
                                               Ptr6 w) {
    int b = blockIdx.x;
    const float* src; __half* dst; int off;
    if (b < 3072)      { src = hs;  dst = g_hs16;  off = b * 1024; }
    else if (b < 3456) { src = enc; dst = g_enc16; off = (b - 3072) * 1024; }
    else {
        int e = b - 3456;
        int seg = e / 2304;
        src = w.p[seg]; dst = g_w16[seg]; off = (e % 2304) * 1024;
    }
    int i = off + threadIdx.x * 4;
    float4 v = *(const float4*)(src + i);
    union { __half2 h[2]; uint2 u; } pk;
    pk.h[0] = __floats2half2_rn(v.x, v.y);
    pk.h[1] = __floats2half2_rn(v.z, v.w);
    *reinterpret_cast<uint2*>(dst + i) = pk.u;
}

// ---------------------------------------------------------------------------
// Merged HMMA GEMM.
// mode 0: grid 624. CTAs [0,576): QKV (segs 0..2, A=hs, M=2048, 16 m-tiles).
//                   CTAs [576,624): encoder (segs 3..4, A=enc, M=256, 2 m-tiles).
// mode 1: grid 192. out-proj (seg 5, A=O16, fp32 out).
// BM=BN=128, BK=32, 256 thr, 3-stage cp.async, one barrier per k-iter.
// ---------------------------------------------------------------------------
#define PADK 40
#define G_STAGE_H (2 * 128 * PADK)
#define GEMM_SMEM (3 * G_STAGE_H * 2)

struct GemmArgs {
    const float* bias[6];
    __half* out16[6];
    float* out32;
};

__global__ __launch_bounds__(256, 2) void gemm_fused(
    const __half* __restrict__ A0, const __half* __restrict__ A1,
    const __half* __restrict__ Wbase, GemmArgs args, int mode)
{
    extern __shared__ __half smg[];

    int tid = threadIdx.x;
    int wid = tid >> 5, lane = tid & 31;
    int wm = wid >> 2;
    int wn = wid & 3;

    int bid = blockIdx.x;
    const __half* A;
    int seg, mbase, nbase;
    if (mode == 1) {
        seg = 5;
        mbase = (bid / 12) << 7;
        nbase = (bid % 12) << 7;
        A = A0;
    } else if (bid < 576) {
        seg = bid / 192;
        int r = bid % 192;
        mbase = (r / 12) << 7;
        nbase = (r % 12) << 7;
        A = A0;
    } else {
        int e = bid - 576;
        seg = 3 + e / 24;
        int r = e % 24;
        mbase = (r / 12) << 7;
        nbase = (r % 12) << 7;
        A = A1;
    }
    const int K = DMODEL, N = DMODEL;
    const int NK = K >> 5;   // 48
    const __half* W = Wbase + (size_t)seg * NW;

    float acc[4][4][4];
#pragma unroll
    for (int mi = 0; mi < 4; mi++)
#pragma unroll
        for (int ni = 0; ni < 4; ni++)
#pragma unroll
            for (int e = 0; e < 4; e++) acc[mi][ni][e] = 0.f;

    auto load_tile = [&](int it) {
        __half* sA = smg + (it % 3) * G_STAGE_H;
        __half* sW = sA + 128 * PADK;
        int kb = it << 5;
#pragma unroll
        for (int i = 0; i < 2; i++) {
            int c = tid + (i << 8);
            int row = c >> 2;
            int col = (c & 3) << 3;
            cp_async16(smem_u32(&sA[row * PADK + col]),
                       A + (size_t)(mbase + row) * K + kb + col);
            cp_async16(smem_u32(&sW[row * PADK + col]),
                       W + (size_t)(nbase + row) * K + kb + col);
        }
        CP_COMMIT();
    };

    load_tile(0);
    load_tile(1);

    for (int it = 0; it < NK; it++) {
        if (it + 1 < NK) CP_WAIT(1); else CP_WAIT(0);
        __syncthreads();
        if (it + 2 < NK) load_tile(it + 2);

        const __half* sA = smg + (it % 3) * G_STAGE_H;
        const __half* sW = sA + 128 * PADK;
#pragma unroll
        for (int ks = 0; ks < 2; ks++) {
            uint32_t afr[4][4];
#pragma unroll
            for (int mi = 0; mi < 4; mi++) {
                int m = wm * 64 + mi * 16 + (lane & 15);
                int kk = ks * 16 + ((lane >> 4) << 3);
                LDMATRIX_X4(afr[mi][0], afr[mi][1], afr[mi][2], afr[mi][3],
                            smem_u32(&sA[m * PADK + kk]));
            }
            uint32_t bfr[4][2];
#pragma unroll
            for (int nb = 0; nb < 2; nb++) {
                int n = wn * 32 + nb * 16 + (lane & 7) + (((lane >> 4) & 1) << 3);
                int kk = ks * 16 + (((lane >> 3) & 1) << 3);
                uint32_t r0, r1, r2, r3;
                LDMATRIX_X4(r0, r1, r2, r3, smem_u32(&sW[n * PADK + kk]));
                bfr[nb * 2][0] = r0; bfr[nb * 2][1] = r1;
                bfr[nb * 2 + 1][0] = r2; bfr[nb * 2 + 1][1] = r3;
            }
#pragma unroll
            for (int mi = 0; mi < 4; mi++)
#pragma unroll
                for (int ni = 0; ni < 4; ni++)
                    MMA16816(acc[mi][ni], afr[mi], bfr[ni]);
        }
    }

    const float* bias = args.bias[seg];
    __half* O16 = args.out16[seg];
    int g = lane >> 2, tq = lane & 3;
#pragma unroll
    for (int mi = 0; mi < 4; mi++) {
        int row0 = mbase + wm * 64 + mi * 16 + g;
#pragma unroll
        for (int ni = 0; ni < 4; ni++) {
            int col = nbase + wn * 32 + ni * 8 + tq * 2;
            float bx = bias[col], by = bias[col + 1];
            float v00 = acc[mi][ni][0] + bx, v01 = acc[mi][ni][1] + by;
            float v10 = acc[mi][ni][2] + bx, v11 = acc[mi][ni][3] + by;
            if (mode == 1) {
                *(float2*)(args.out32 + (size_t)row0 * N + col) = make_float2(v00, v01);
                *(float2*)(args.out32 + (size_t)(row0 + 8) * N + col) = make_float2(v10, v11);
            } else {
                *(__half2*)(O16 + (size_t)row0 * N + col) = __floats2half2_rn(v00, v01);
                *(__half2*)(O16 + (size_t)(row0 + 8) * N + col) = __floats2half2_rn(v10, v11);
            }
        }
    }
}

// ---------------------------------------------------------------------------
// Fused per-head RMSNorm on Q16 and K16 (in place). One warp per chunk.
// ---------------------------------------------------------------------------
#define QCHUNKS (S_HID * HEADS)
#define KCHUNKS (T_TOT * HEADS)

__global__ __launch_bounds__(256) void rms_fused(
    const float* __restrict__ wq, const float* __restrict__ wk,
    const float* __restrict__ wak)
{
    int chunk = blockIdx.x * 8 + (threadIdx.x >> 5);
    int lane = threadIdx.x & 31;

    __half* buf;
    const float* w;
    int row, head;
    if (chunk < QCHUNKS) {
        buf = g_Q16; row = chunk / HEADS; head = chunk % HEADS; w = wq;
    } else {
        int c = chunk - QCHUNKS;
        buf = g_K16; row = c / HEADS; head = c % HEADS;
        w = (row < S_HID) ? wk : wak;
    }

    __half2* p = (__half2*)(buf + (size_t)row * DMODEL + head * HDIM);
    float2 x = __half22float2(p[lane]);
    float ss = x.x * x.x + x.y * x.y;
#pragma unroll
    for (int o = 16; o; o >>= 1) ss += __shfl_xor_sync(0xffffffffu, ss, o);
    float r = rsqrtf(ss * (1.0f / 64.0f) + 1e-6f);
    p[lane] = __floats2half2_rn(x.x * r * w[2 * lane], x.y * r * w[2 * lane + 1]);
}

// ---------------------------------------------------------------------------
// HMMA flash attention: BQ=128 (256 threads, 8 warps x m16), BK=64.
// 3-stage K/V pipeline, one barrier per tile.
// ---------------------------------------------------------------------------
#define PADA 72
#define Q_TILE_H (128 * PADA)                    // halfs
#define A_TILE_H (64 * PADA)                     // halfs (K or V tile)
#define ATTN_MSK_OFF ((Q_TILE_H + 6 * A_TILE_H) * 2)
#define ATTN_SMEM (ATTN_MSK_OFF + 3 * 64 * 4)

__global__ __launch_bounds__(256, 2) void attn_kernel(const float* __restrict__ mask)
{
    extern __shared__ __half sm[];
    __half* sQ = sm;
    float* smsk = (float*)((char*)sm + ATTN_MSK_OFF);

    int tid = threadIdx.x;
    int wm = tid >> 5, lane = tid & 31;
    int g = lane >> 2, tq = lane & 3;
    int head = blockIdx.y;
    int qbase = blockIdx.x << 7;
    int hoff = head * HDIM;

    auto load_kv = [&](int kt) {
        int st = kt % 3;
        __half* sK = sm + Q_TILE_H + st * A_TILE_H;
        __half* sV = sm + Q_TILE_H + (3 + st) * A_TILE_H;
        int kbase = kt << 6;
#pragma unroll
        for (int i = 0; i < 2; i++) {
            int c = tid + (i << 8);          // 0..511
            int row = c >> 3, col = (c & 7) << 3;
            size_t goff = (size_t)(kbase + row) * DMODEL + hoff + col;
            cp_async16(smem_u32(&sK[row * PADA + col]), g_K16 + goff);
            cp_async16(smem_u32(&sV[row * PADA + col]), g_V16 + goff);
        }
        if (tid < 64) cp_async4(smem_u32(&smsk[st * 64 + tid]), mask + kbase + tid);
        CP_COMMIT();
    };

    // group 1: Q (128x64) + KV tile 0; group 2: KV tile 1
#pragma unroll
    for (int i = 0; i < 4; i++) {
        int c = tid + (i << 8);              // 0..1023
        int row = c >> 3, col = (c & 7) << 3;
        cp_async16(smem_u32(&sQ[row * PADA + col]),
                   g_Q16 + (size_t)(qbase + row) * DMODEL + hoff + col);
    }
    {
        __half* sK = sm + Q_TILE_H;
        __half* sV = sm + Q_TILE_H + 3 * A_TILE_H;
#pragma unroll
        for (int i = 0; i < 2; i++) {
            int c = tid + (i << 8);
            int row = c >> 3, col = (c & 7) << 3;
            size_t goff = (size_t)row * DMODEL + hoff + col;
            cp_async16(smem_u32(&sK[row * PADA + col]), g_K16 + goff);
            cp_async16(smem_u32(&sV[row * PADA + col]), g_V16 + goff);
        }
        if (tid < 64) cp_async4(smem_u32(&smsk[tid]), mask + tid);
        CP_COMMIT();
    }
    load_kv(1);

    uint32_t qfr[4][4];
    float o[8][4];
#pragma unroll
    for (int nt = 0; nt < 8; nt++)
#pragma unroll
        for (int e = 0; e < 4; e++) o[nt][e] = 0.f;
    float m_lo = -3e38f, m_hi = -3e38f, l_lo = 0.f, l_hi = 0.f;
    const float scale = 0.125f;

    for (int kt = 0; kt < NKT; kt++) {
        if (kt + 1 < NKT) CP_WAIT(1); else CP_WAIT(0);
        __syncthreads();
        if (kt == 0) {
#pragma unroll
            for (int kc = 0; kc < 4; kc++) {
                int m = wm * 16 + (lane & 15);
                int kk = kc * 16 + ((lane >> 4) << 3);
                LDMATRIX_X4(qfr[kc][0], qfr[kc][1], qfr[kc][2], qfr[kc][3],
                            smem_u32(&sQ[m * PADA + kk]));
            }
        }
        if (kt + 2 < NKT) load_kv(kt + 2);

        int st = kt % 3;
        const __half* sK = sm + Q_TILE_H + st * A_TILE_H;
        const __half* sV = sm + Q_TILE_H + (3 + st) * A_TILE_H;
        const float* mk = smsk + st * 64;

        // ---- S = Q @ K^T ----
        float sa[8][4];
#pragma unroll
        for (int nt = 0; nt < 8; nt++)
#pragma unroll
            for (int e = 0; e < 4; e++) sa[nt][e] = 0.f;

#pragma unroll
        for (int kc = 0; kc < 4; kc++) {
            uint32_t kf[8][2];
#pragma unroll
            for (int ntp = 0; ntp < 4; ntp++) {
                int n = ntp * 16 + (lane & 7) + (((lane >> 4) & 1) << 3);
                int kk = kc * 16 + (((lane >> 3) & 1) << 3);
                uint32_t r0, r1, r2, r3;
                LDMATRIX_X4(r0, r1, r2, r3, smem_u32(&sK[n * PADA + kk]));
                kf[ntp * 2][0] = r0; kf[ntp * 2][1] = r1;
                kf[ntp * 2 + 1][0] = r2; kf[ntp * 2 + 1][1] = r3;
            }
#pragma unroll
            for (int nt = 0; nt < 8; nt++)
                MMA16816(sa[nt], qfr[kc], kf[nt]);
        }

        // ---- scale + mask + online softmax (rows wm*16+g, +8) ----
        float mx_lo = -3e38f, mx_hi = -3e38f;
#pragma unroll
        for (int nt = 0; nt < 8; nt++) {
            float mk0 = mk[nt * 8 + 2 * tq];
            float mk1 = mk[nt * 8 + 2 * tq + 1];
            sa[nt][0] = sa[nt][0] * scale + mk0;
            sa[nt][1] = sa[nt][1] * scale + mk1;
            sa[nt][2] = sa[nt][2] * scale + mk0;
            sa[nt][3] = sa[nt][3] * scale + mk1;
            mx_lo = fmaxf(mx_lo, fmaxf(sa[nt][0], sa[nt][1]));
            mx_hi = fmaxf(mx_hi, fmaxf(sa[nt][2], sa[nt][3]));
        }
#pragma unroll
        for (int off = 1; off < 4; off <<= 1) {
            mx_lo = fmaxf(mx_lo, __shfl_xor_sync(0xffffffffu, mx_lo, off));
            mx_hi = fmaxf(mx_hi, __shfl_xor_sync(0xffffffffu, mx_hi, off));
        }
        float mn_lo = fmaxf(m_lo, mx_lo), mn_hi = fmaxf(m_hi, mx_hi);
        float cr_lo = __expf(m_lo - mn_lo), cr_hi = __expf(m_hi - mn_hi);
        m_lo = mn_lo; m_hi = mn_hi;

        float sum_lo = 0.f, sum_hi = 0.f;
#pragma unroll
        for (int nt = 0; nt < 8; nt++) {
            sa[nt][0] = __expf(sa[nt][0] - m_lo);
            sa[nt][1] = __expf(sa[nt][1] - m_lo);
            sa[nt][2] = __expf(sa[nt][2] - m_hi);
            sa[nt][3] = __expf(sa[nt][3] - m_hi);
            sum_lo += sa[nt][0] + sa[nt][1];
            sum_hi += sa[nt][2] + sa[nt][3];
        }
#pragma unroll
        for (int off = 1; off < 4; off <<= 1) {
            sum_lo += __shfl_xor_sync(0xffffffffu, sum_lo, off);
            sum_hi += __shfl_xor_sync(0xffffffffu, sum_hi, off);
        }
        l_lo = l_lo * cr_lo + sum_lo;
        l_hi = l_hi * cr_hi + sum_hi;

#pragma unroll
        for (int nt = 0; nt < 8; nt++) {
            o[nt][0] *= cr_lo; o[nt][1] *= cr_lo;
            o[nt][2] *= cr_hi; o[nt][3] *= cr_hi;
        }

        // ---- O += P @ V ----
#pragma unroll
        for (int c = 0; c < 4; c++) {
            uint32_t pa[4];
            pa[0] = pack_h2(sa[2 * c][0], sa[2 * c][1]);
            pa[1] = pack_h2(sa[2 * c][2], sa[2 * c][3]);
            pa[2] = pack_h2(sa[2 * c + 1][0], sa[2 * c + 1][1]);
            pa[3] = pack_h2(sa[2 * c + 1][2], sa[2 * c + 1][3]);
#pragma unroll
            for (int ntd = 0; ntd < 8; ntd++) {
                uint32_t vb[2];
                LDMATRIX_X2T(vb[0], vb[1],
                             smem_u32(&sV[(c * 16 + (lane & 15)) * PADA + ntd * 8]));
                MMA16816(o[ntd], pa, vb);
            }
        }
    }

    // ---- finalize & store fp16 ----
    float inv_lo = 1.f / l_lo, inv_hi = 1.f / l_hi;
    int row_lo = qbase + wm * 16 + g;
#pragma unroll
    for (int nt = 0; nt < 8; nt++) {
        int col = hoff + nt * 8 + 2 * tq;
        *(__half2*)(g_O16 + (size_t)row_lo * DMODEL + col) =
            __floats2half2_rn(o[nt][0] * inv_lo, o[nt][1] * inv_lo);
        *(__half2*)(g_O16 + (size_t)(row_lo + 8) * DMODEL + col) =
            __floats2half2_rn(o[nt][2] * inv_hi, o[nt][3] * inv_hi);
    }
}

// ---------------------------------------------------------------------------
// kernel_launch (5 launches)
// ---------------------------------------------------------------------------
extern "C" void kernel_launch(void* const* d_in, const int* in_sizes, int n_in,
                              void* d_out, int out_size)
{
    (void)in_sizes; (void)n_in; (void)out_size;
    const float* hs   = (const float*)d_in[0];
    const float* enc  = (const float*)d_in[1];
    const float* mask = (const float*)d_in[2];
    const float* wq   = (const float*)d_in[3];
    const float* bq   = (const float*)d_in[4];
    const float* wk   = (const float*)d_in[5];
    const float* bk   = (const float*)d_in[6];
    const float* wv   = (const float*)d_in[7];
    const float* bv   = (const float*)d_in[8];
    const float* nqw  = (const float*)d_in[9];
    const float* nkw  = (const float*)d_in[10];
    const float* akw  = (const float*)d_in[13];
    const float* akb  = (const float*)d_in[14];
    const float* avw  = (const float*)d_in[15];
    const float* avb  = (const float*)d_in[16];
    const float* nakw = (const float*)d_in[18];
    const float* wo   = (const float*)d_in[19];
    const float* bo   = (const float*)d_in[20];
    float* out = (float*)d_out;

    __half *pQ16, *pK16, *pV16, *pO16, *phs16, *penc16, *pw16;
    cudaGetSymbolAddress((void**)&pQ16, g_Q16);
    cudaGetSymbolAddress((void**)&pK16, g_K16);
    cudaGetSymbolAddress((void**)&pV16, g_V16);
    cudaGetSymbolAddress((void**)&pO16, g_O16);
    cudaGetSymbolAddress((void**)&phs16, g_hs16);
    cudaGetSymbolAddress((void**)&penc16, g_enc16);
    cudaGetSymbolAddress((void**)&pw16, g_w16);

    cudaFuncSetAttribute(gemm_fused, cudaFuncAttributeMaxDynamicSharedMemorySize, GEMM_SMEM);
    cudaFuncSetAttribute(attn_kernel, cudaFuncAttributeMaxDynamicSharedMemorySize, ATTN_SMEM);

    dim3 tb(256);
    const int ENC_OFF = S_HID * DMODEL;

    // 1: all converts (weight slot order: q,k,v,ak,av,o)
    Ptr6 wsrc; wsrc.p[0] = wq; wsrc.p[1] = wk; wsrc.p[2] = wv;
    wsrc.p[3] = akw; wsrc.p[4] = avw; wsrc.p[5] = wo;
    cvt_all<<<CVT_BLOCKS, tb>>>(hs, enc, wsrc);

    // 2: merged QKV + encoder projections (624 CTAs)
    GemmArgs ga;
    ga.bias[0] = bq;  ga.bias[1] = bk;  ga.bias[2] = bv;
    ga.bias[3] = akb; ga.bias[4] = avb; ga.bias[5] = bo;
    ga.out16[0] = pQ16; ga.out16[1] = pK16; ga.out16[2] = pV16;
    ga.out16[3] = pK16 + ENC_OFF; ga.out16[4] = pV16 + ENC_OFF; ga.out16[5] = nullptr;
    ga.out32 = out;
    gemm_fused<<<624, tb, GEMM_SMEM>>>(phs16, penc16, pw16, ga, 0);

    // 3: fused RMSNorm (Q + K)
    rms_fused<<<(QCHUNKS + KCHUNKS) / 8, tb>>>(nqw, nkw, nakw);

    // 4: flash attention (BQ=128)
    attn_kernel<<<dim3(S_HID / 128, HEADS), tb, ATTN_SMEM>>>(mask);

    // 5: output projection -> fp32
    gemm_fused<<<192, tb, GEMM_SMEM>>>(pO16, nullptr, pw16, ga, 1);
}

// round 11
// speedup vs baseline: 9.2413x; 1.1132x over previous
#include <cuda_runtime.h>
#include <cuda_fp16.h>
#include <cstdint>

// Problem constants
#define DMODEL 1536
#define HEADS  24
#define HDIM   64
#define S_HID  2048
#define S_ENCC 256
#define T_TOT  2304
#define NKT    (T_TOT / 64)           // 36 key tiles
#define NW     (DMODEL * DMODEL)      // weight elements
#define LOG2E  1.44269504088896f

// ---------------------------------------------------------------------------
// Scratch (__device__ globals; no allocations allowed)
// ---------------------------------------------------------------------------
__device__ __align__(1024) __half g_Q16[(size_t)S_HID * DMODEL];
__device__ __align__(1024) __half g_K16[(size_t)T_TOT * DMODEL];
__device__ __align__(1024) __half g_V16[(size_t)T_TOT * DMODEL];
__device__ __align__(1024) __half g_O16[(size_t)S_HID * DMODEL];
__device__ __align__(1024) __half g_hs16[(size_t)S_HID * DMODEL];
__device__ __align__(1024) __half g_enc16[(size_t)S_ENCC * DMODEL];
__device__ __align__(1024) __half g_w16[6][(size_t)NW];
__device__ __align__(1024) float  g_mask2[T_TOT];   // mask * log2(e)

// ---------------------------------------------------------------------------
// PTX helpers (plain sm_103-safe)
// ---------------------------------------------------------------------------
__device__ __forceinline__ uint32_t smem_u32(const void* p) {
    return (uint32_t)__cvta_generic_to_shared(p);
}
__device__ __forceinline__ void cp_async16(uint32_t saddr, const void* gaddr) {
    asm volatile("cp.async.cg.shared.global [%0], [%1], 16;" :: "r"(saddr), "l"(gaddr) : "memory");
}
__device__ __forceinline__ void cp_async4(uint32_t saddr, const void* gaddr) {
    asm volatile("cp.async.ca.shared.global [%0], [%1], 4;" :: "r"(saddr), "l"(gaddr) : "memory");
}
__device__ __forceinline__ float ex2(float x) {
    float y;
    asm("ex2.approx.f32 %0, %1;" : "=f"(y) : "f"(x));
    return y;
}

#define CP_COMMIT()  asm volatile("cp.async.commit_group;" ::: "memory")
#define CP_WAIT(n)   asm volatile("cp.async.wait_group %0;" :: "n"(n) : "memory")

#define LDMATRIX_X4(r0, r1, r2, r3, addr) \
    asm volatile("ldmatrix.sync.aligned.m8n8.x4.shared.b16 {%0,%1,%2,%3}, [%4];" \
                 : "=r"(r0), "=r"(r1), "=r"(r2), "=r"(r3) : "r"(addr))
#define LDMATRIX_X4T(r0, r1, r2, r3, addr) \
    asm volatile("ldmatrix.sync.aligned.m8n8.x4.trans.shared.b16 {%0,%1,%2,%3}, [%4];" \
                 : "=r"(r0), "=r"(r1), "=r"(r2), "=r"(r3) : "r"(addr))

#define MMA16816(d, a, b) \
    asm volatile("mma.sync.aligned.m16n8k16.row.col.f32.f16.f16.f32 " \
                 "{%0,%1,%2,%3}, {%4,%5,%6,%7}, {%8,%9}, {%0,%1,%2,%3};" \
                 : "+f"((d)[0]), "+f"((d)[1]), "+f"((d)[2]), "+f"((d)[3]) \
                 : "r"((a)[0]), "r"((a)[1]), "r"((a)[2]), "r"((a)[3]), \
                   "r"((b)[0]), "r"((b)[1]))

__device__ __forceinline__ uint32_t pack_h2(float x, float y) {
    union { __half2 h; uint32_t u; } p;
    p.h = __floats2half2_rn(x, y);
    return p.u;
}

// ---------------------------------------------------------------------------
// Fused convert: hs + enc + 6 weights + mask (prescaled by log2e).
// Each block: 4096 floats, 4 independent float4 per thread (MLP=4).
// blocks: [0,768) hs | [768,864) enc | [864,4320) weights | 4320 mask
// ---------------------------------------------------------------------------
struct Ptr6 { const float* p[6]; };
#define CVT_BLOCKS 4321

__global__ __launch_bounds__(256) void cvt_all(const float* __restrict__ hs,
                                               const float* __restrict__ enc,
                                               const float* __restrict__ mask,
                                               Ptr6 w) {
    int b = blockIdx.x;
    int t4 = threadIdx.x * 4;

    if (b == 4320) {
#pragma unroll
        for (int p = 0; p < 3; p++) {
            int i = t4 + p * 1024;
            if (i < T_TOT) {
                float4 v = *(const float4*)(mask + i);
                v.x *= LOG2E; v.y *= LOG2E; v.z *= LOG2E; v.w *= LOG2E;
                *(float4*)(g_mask2 + i) = v;
            }
        }
        return;
    }

    const float* src; __half* dst; int off;
    if (b < 768)      { src = hs;  dst = g_hs16;  off = b * 4096; }
    else if (b < 864) { src = enc; dst = g_enc16; off = (b - 768) * 4096; }
    else {
        int e = b - 864;
        int seg = e / 576;
        src = w.p[seg]; dst = g_w16[seg]; off = (e % 576) * 4096;
    }

    float4 v[4];
#pragma unroll
    for (int p = 0; p < 4; p++)
        v[p] = *(const float4*)(src + off + t4 + p * 1024);
#pragma unroll
    for (int p = 0; p < 4; p++) {
        union { __half2 h[2]; uint2 u; } pk;
        pk.h[0] = __floats2half2_rn(v[p].x, v[p].y);
        pk.h[1] = __floats2half2_rn(v[p].z, v[p].w);
        *reinterpret_cast<uint2*>(dst + off + t4 + p * 1024) = pk.u;
    }
}

// ---------------------------------------------------------------------------
// Merged HMMA GEMM (unchanged from R8).
// mode 0: grid 624 (QKV + encoder).  mode 1: grid 192 (out-proj, fp32).
// ---------------------------------------------------------------------------
#define PADK 40
#define G_STAGE_H (2 * 128 * PADK)
#define GEMM_SMEM (3 * G_STAGE_H * 2)

struct GemmArgs {
    const float* bias[6];
    __half* out16[6];
    float* out32;
};

__global__ __launch_bounds__(256, 2) void gemm_fused(
    const __half* __restrict__ A0, const __half* __restrict__ A1,
    const __half* __restrict__ Wbase, GemmArgs args, int mode)
{
    extern __shared__ __half smg[];

    int tid = threadIdx.x;
    int wid = tid >> 5, lane = tid & 31;
    int wm = wid >> 2;
    int wn = wid & 3;

    int bid = blockIdx.x;
    const __half* A;
    int seg, mbase, nbase;
    if (mode == 1) {
        seg = 5;
        mbase = (bid / 12) << 7;
        nbase = (bid % 12) << 7;
        A = A0;
    } else if (bid < 576) {
        seg = bid / 192;
        int r = bid % 192;
        mbase = (r / 12) << 7;
        nbase = (r % 12) << 7;
        A = A0;
    } else {
        int e = bid - 576;
        seg = 3 + e / 24;
        int r = e % 24;
        mbase = (r / 12) << 7;
        nbase = (r % 12) << 7;
        A = A1;
    }
    const int K = DMODEL, N = DMODEL;
    const int NK = K >> 5;   // 48
    const __half* W = Wbase + (size_t)seg * NW;

    float acc[4][4][4];
#pragma unroll
    for (int mi = 0; mi < 4; mi++)
#pragma unroll
        for (int ni = 0; ni < 4; ni++)
#pragma unroll
            for (int e = 0; e < 4; e++) acc[mi][ni][e] = 0.f;

    auto load_tile = [&](int it) {
        __half* sA = smg + (it % 3) * G_STAGE_H;
        __half* sW = sA + 128 * PADK;
        int kb = it << 5;
#pragma unroll
        for (int i = 0; i < 2; i++) {
            int c = tid + (i << 8);
            int row = c >> 2;
            int col = (c & 3) << 3;
            cp_async16(smem_u32(&sA[row * PADK + col]),
                       A + (size_t)(mbase + row) * K + kb + col);
            cp_async16(smem_u32(&sW[row * PADK + col]),
                       W + (size_t)(nbase + row) * K + kb + col);
        }
        CP_COMMIT();
    };

    load_tile(0);
    load_tile(1);

    for (int it = 0; it < NK; it++) {
        if (it + 1 < NK) CP_WAIT(1); else CP_WAIT(0);
        __syncthreads();
        if (it + 2 < NK) load_tile(it + 2);

        const __half* sA = smg + (it % 3) * G_STAGE_H;
        const __half* sW = sA + 128 * PADK;
#pragma unroll
        for (int ks = 0; ks < 2; ks++) {
            uint32_t afr[4][4];
#pragma unroll
            for (int mi = 0; mi < 4; mi++) {
                int m = wm * 64 + mi * 16 + (lane & 15);
                int kk = ks * 16 + ((lane >> 4) << 3);
                LDMATRIX_X4(afr[mi][0], afr[mi][1], afr[mi][2], afr[mi][3],
                            smem_u32(&sA[m * PADK + kk]));
            }
            uint32_t bfr[4][2];
#pragma unroll
            for (int nb = 0; nb < 2; nb++) {
                int n = wn * 32 + nb * 16 + (lane & 7) + (((lane >> 4) & 1) << 3);
                int kk = ks * 16 + (((lane >> 3) & 1) << 3);
                uint32_t r0, r1, r2, r3;
                LDMATRIX_X4(r0, r1, r2, r3, smem_u32(&sW[n * PADK + kk]));
                bfr[nb * 2][0] = r0; bfr[nb * 2][1] = r1;
                bfr[nb * 2 + 1][0] = r2; bfr[nb * 2 + 1][1] = r3;
            }
#pragma unroll
            for (int mi = 0; mi < 4; mi++)
#pragma unroll
                for (int ni = 0; ni < 4; ni++)
                    MMA16816(acc[mi][ni], afr[mi], bfr[ni]);
        }
    }

    const float* bias = args.bias[seg];
    __half* O16 = args.out16[seg];
    int g = lane >> 2, tq = lane & 3;
#pragma unroll
    for (int mi = 0; mi < 4; mi++) {
        int row0 = mbase + wm * 64 + mi * 16 + g;
#pragma unroll
        for (int ni = 0; ni < 4; ni++) {
            int col = nbase + wn * 32 + ni * 8 + tq * 2;
            float bx = bias[col], by = bias[col + 1];
            float v00 = acc[mi][ni][0] + bx, v01 = acc[mi][ni][1] + by;
            float v10 = acc[mi][ni][2] + bx, v11 = acc[mi][ni][3] + by;
            if (mode == 1) {
                *(float2*)(args.out32 + (size_t)row0 * N + col) = make_float2(v00, v01);
                *(float2*)(args.out32 + (size_t)(row0 + 8) * N + col) = make_float2(v10, v11);
            } else {
                *(__half2*)(O16 + (size_t)row0 * N + col) = __floats2half2_rn(v00, v01);
                *(__half2*)(O16 + (size_t)(row0 + 8) * N + col) = __floats2half2_rn(v10, v11);
            }
        }
    }
}

// ---------------------------------------------------------------------------
// Fused per-head RMSNorm. Q chunks additionally folded with 0.125*log2(e)
// (attention scale + exp2 base conversion).
// ---------------------------------------------------------------------------
#define QCHUNKS (S_HID * HEADS)
#define KCHUNKS (T_TOT * HEADS)
#define QSCALE  (0.125f * LOG2E)

__global__ __launch_bounds__(256) void rms_fused(
    const float* __restrict__ wq, const float* __restrict__ wk,
    const float* __restrict__ wak)
{
    int chunk = blockIdx.x * 8 + (threadIdx.x >> 5);
    int lane = threadIdx.x & 31;

    __half* buf;
    const float* w;
    int row, head;
    float post;
    if (chunk < QCHUNKS) {
        buf = g_Q16; row = chunk / HEADS; head = chunk % HEADS; w = wq;
        post = QSCALE;
    } else {
        int c = chunk - QCHUNKS;
        buf = g_K16; row = c / HEADS; head = c % HEADS;
        w = (row < S_HID) ? wk : wak;
        post = 1.0f;
    }

    __half2* p = (__half2*)(buf + (size_t)row * DMODEL + head * HDIM);
    float2 x = __half22float2(p[lane]);
    float ss = x.x * x.x + x.y * x.y;
#pragma unroll
    for (int o = 16; o; o >>= 1) ss += __shfl_xor_sync(0xffffffffu, ss, o);
    float r = rsqrtf(ss * (1.0f / 64.0f) + 1e-6f) * post;
    p[lane] = __floats2half2_rn(x.x * r * w[2 * lane], x.y * r * w[2 * lane + 1]);
}

// ---------------------------------------------------------------------------
// HMMA flash attention, no-max softmax (scores bounded: RMSNorm'd q,k).
// BQ=128 (256 threads), BK=64, 3-stage K/V pipeline.
// p = exp2(qk*0.125*log2e + mask*log2e); denominator reduced once at end.
// ---------------------------------------------------------------------------
#define PADA 72
#define Q_TILE_H (128 * PADA)
#define A_TILE_H (64 * PADA)
#define ATTN_MSK_OFF ((Q_TILE_H + 6 * A_TILE_H) * 2)
#define ATTN_SMEM (ATTN_MSK_OFF + 3 * 64 * 4)

__global__ __launch_bounds__(256, 2) void attn_kernel()
{
    extern __shared__ __half sm[];
    __half* sQ = sm;
    float* smsk = (float*)((char*)sm + ATTN_MSK_OFF);

    int tid = threadIdx.x;
    int wm = tid >> 5, lane = tid & 31;
    int g = lane >> 2, tq = lane & 3;
    int head = blockIdx.y;
    int qbase = blockIdx.x << 7;
    int hoff = head * HDIM;

    auto load_kv = [&](int kt) {
        int st = kt % 3;
        __half* sK = sm + Q_TILE_H + st * A_TILE_H;
        __half* sV = sm + Q_TILE_H + (3 + st) * A_TILE_H;
        int kbase = kt << 6;
#pragma unroll
        for (int i = 0; i < 2; i++) {
            int c = tid + (i << 8);
            int row = c >> 3, col = (c & 7) << 3;
            size_t goff = (size_t)(kbase + row) * DMODEL + hoff + col;
            cp_async16(smem_u32(&sK[row * PADA + col]), g_K16 + goff);
            cp_async16(smem_u32(&sV[row * PADA + col]), g_V16 + goff);
        }
        if (tid < 64) cp_async4(smem_u32(&smsk[st * 64 + tid]), g_mask2 + kbase + tid);
        CP_COMMIT();
    };

#pragma unroll
    for (int i = 0; i < 4; i++) {
        int c = tid + (i << 8);
        int row = c >> 3, col = (c & 7) << 3;
        cp_async16(smem_u32(&sQ[row * PADA + col]),
                   g_Q16 + (size_t)(qbase + row) * DMODEL + hoff + col);
    }
    {
        __half* sK = sm + Q_TILE_H;
        __half* sV = sm + Q_TILE_H + 3 * A_TILE_H;
#pragma unroll
        for (int i = 0; i < 2; i++) {
            int c = tid + (i << 8);
            int row = c >> 3, col = (c & 7) << 3;
            size_t goff = (size_t)row * DMODEL + hoff + col;
            cp_async16(smem_u32(&sK[row * PADA + col]), g_K16 + goff);
            cp_async16(smem_u32(&sV[row * PADA + col]), g_V16 + goff);
        }
        if (tid < 64) cp_async4(smem_u32(&smsk[tid]), g_mask2 + tid);
        CP_COMMIT();
    }
    load_kv(1);

    uint32_t qfr[4][4];
    float o[8][4];
#pragma unroll
    for (int nt = 0; nt < 8; nt++)
#pragma unroll
        for (int e = 0; e < 4; e++) o[nt][e] = 0.f;
    float l_lo = 0.f, l_hi = 0.f;

    for (int kt = 0; kt < NKT; kt++) {
        if (kt + 1 < NKT) CP_WAIT(1); else CP_WAIT(0);
        __syncthreads();
        if (kt == 0) {
#pragma unroll
            for (int kc = 0; kc < 4; kc++) {
                int m = wm * 16 + (lane & 15);
                int kk = kc * 16 + ((lane >> 4) << 3);
                LDMATRIX_X4(qfr[kc][0], qfr[kc][1], qfr[kc][2], qfr[kc][3],
                            smem_u32(&sQ[m * PADA + kk]));
            }
        }
        if (kt + 2 < NKT) load_kv(kt + 2);

        int st = kt % 3;
        const __half* sK = sm + Q_TILE_H + st * A_TILE_H;
        const __half* sV = sm + Q_TILE_H + (3 + st) * A_TILE_H;
        const float* mk = smsk + st * 64;

        // ---- S = Q @ K^T (prescaled by 0.125*log2e via Q) ----
        float sa[8][4];
#pragma unroll
        for (int nt = 0; nt < 8; nt++)
#pragma unroll
            for (int e = 0; e < 4; e++) sa[nt][e] = 0.f;

#pragma unroll
        for (int kc = 0; kc < 4; kc++) {
            uint32_t kf[8][2];
#pragma unroll
            for (int ntp = 0; ntp < 4; ntp++) {
                int n = ntp * 16 + (lane & 7) + (((lane >> 4) & 1) << 3);
                int kk = kc * 16 + (((lane >> 3) & 1) << 3);
                uint32_t r0, r1, r2, r3;
                LDMATRIX_X4(r0, r1, r2, r3, smem_u32(&sK[n * PADA + kk]));
                kf[ntp * 2][0] = r0; kf[ntp * 2][1] = r1;
                kf[ntp * 2 + 1][0] = r2; kf[ntp * 2 + 1][1] = r3;
            }
#pragma unroll
            for (int nt = 0; nt < 8; nt++)
                MMA16816(sa[nt], qfr[kc], kf[nt]);
        }

        // ---- p = exp2(s + mask'), accumulate denominator per-thread ----
#pragma unroll
        for (int nt = 0; nt < 8; nt++) {
            float mk0 = mk[nt * 8 + 2 * tq];
            float mk1 = mk[nt * 8 + 2 * tq + 1];
            sa[nt][0] = ex2(sa[nt][0] + mk0);
            sa[nt][1] = ex2(sa[nt][1] + mk1);
            sa[nt][2] = ex2(sa[nt][2] + mk0);
            sa[nt][3] = ex2(sa[nt][3] + mk1);
            l_lo += sa[nt][0] + sa[nt][1];
            l_hi += sa[nt][2] + sa[nt][3];
        }

        // ---- O += P @ V (V via x4.trans: 2 n-blocks per LDSM) ----
#pragma unroll
        for (int c = 0; c < 4; c++) {
            uint32_t pa[4];
            pa[0] = pack_h2(sa[2 * c][0], sa[2 * c][1]);
            pa[1] = pack_h2(sa[2 * c][2], sa[2 * c][3]);
            pa[2] = pack_h2(sa[2 * c + 1][0], sa[2 * c + 1][1]);
            pa[3] = pack_h2(sa[2 * c + 1][2], sa[2 * c + 1][3]);
            uint32_t vrow = smem_u32(&sV[(c * 16 + (lane & 15)) * PADA + ((lane >> 4) & 1) * 8]);
#pragma unroll
            for (int ntd = 0; ntd < 8; ntd += 2) {
                uint32_t vb[4];
                LDMATRIX_X4T(vb[0], vb[1], vb[2], vb[3], vrow + ntd * 16);
                MMA16816(o[ntd], pa, vb);
                MMA16816(o[ntd + 1], pa, (vb + 2));
            }
        }
    }

    // ---- single final denominator reduction (across the lane quad) ----
#pragma unroll
    for (int off = 1; off < 4; off <<= 1) {
        l_lo += __shfl_xor_sync(0xffffffffu, l_lo, off);
        l_hi += __shfl_xor_sync(0xffffffffu, l_hi, off);
    }
    float inv_lo = 1.f / l_lo, inv_hi = 1.f / l_hi;
    int row_lo = qbase + wm * 16 + g;
#pragma unroll
    for (int nt = 0; nt < 8; nt++) {
        int col = hoff + nt * 8 + 2 * tq;
        *(__half2*)(g_O16 + (size_t)row_lo * DMODEL + col) =
            __floats2half2_rn(o[nt][0] * inv_lo, o[nt][1] * inv_lo);
        *(__half2*)(g_O16 + (size_t)(row_lo + 8) * DMODEL + col) =
            __floats2half2_rn(o[nt][2] * inv_hi, o[nt][3] * inv_hi);
    }
}

// ---------------------------------------------------------------------------
// kernel_launch (5 launches)
// ---------------------------------------------------------------------------
extern "C" void kernel_launch(void* const* d_in, const int* in_sizes, int n_in,
                              void* d_out, int out_size)
{
    (void)in_sizes; (void)n_in; (void)out_size;
    const float* hs   = (const float*)d_in[0];
    const float* enc  = (const float*)d_in[1];
    const float* mask = (const float*)d_in[2];
    const float* wq   = (const float*)d_in[3];
    const float* bq   = (const float*)d_in[4];
    const float* wk   = (const float*)d_in[5];
    const float* bk   = (const float*)d_in[6];
    const float* wv   = (const float*)d_in[7];
    const float* bv   = (const float*)d_in[8];
    const float* nqw  = (const float*)d_in[9];
    const float* nkw  = (const float*)d_in[10];
    const float* akw  = (const float*)d_in[13];
    const float* akb  = (const float*)d_in[14];
    const float* avw  = (const float*)d_in[15];
    const float* avb  = (const float*)d_in[16];
    const float* nakw = (const float*)d_in[18];
    const float* wo   = (const float*)d_in[19];
    const float* bo   = (const float*)d_in[20];
    float* out = (float*)d_out;

    __half *pQ16, *pK16, *pV16, *pO16, *phs16, *penc16, *pw16;
    cudaGetSymbolAddress((void**)&pQ16, g_Q16);
    cudaGetSymbolAddress((void**)&pK16, g_K16);
    cudaGetSymbolAddress((void**)&pV16, g_V16);
    cudaGetSymbolAddress((void**)&pO16, g_O16);
    cudaGetSymbolAddress((void**)&phs16, g_hs16);
    cudaGetSymbolAddress((void**)&penc16, g_enc16);
    cudaGetSymbolAddress((void**)&pw16, g_w16);

    cudaFuncSetAttribute(gemm_fused, cudaFuncAttributeMaxDynamicSharedMemorySize, GEMM_SMEM);
    cudaFuncSetAttribute(attn_kernel, cudaFuncAttributeMaxDynamicSharedMemorySize, ATTN_SMEM);

    dim3 tb(256);
    const int ENC_OFF = S_HID * DMODEL;

    // 1: all converts (weights: q,k,v,ak,av,o) + mask prescale
    Ptr6 wsrc; wsrc.p[0] = wq; wsrc.p[1] = wk; wsrc.p[2] = wv;
    wsrc.p[3] = akw; wsrc.p[4] = avw; wsrc.p[5] = wo;
    cvt_all<<<CVT_BLOCKS, tb>>>(hs, enc, mask, wsrc);

    // 2: merged QKV + encoder projections (624 CTAs)
    GemmArgs ga;
    ga.bias[0] = bq;  ga.bias[1] = bk;  ga.bias[2] = bv;
    ga.bias[3] = akb; ga.bias[4] = avb; ga.bias[5] = bo;
    ga.out16[0] = pQ16; ga.out16[1] = pK16; ga.out16[2] = pV16;
    ga.out16[3] = pK16 + ENC_OFF; ga.out16[4] = pV16 + ENC_OFF; ga.out16[5] = nullptr;
    ga.out32 = out;
    gemm_fused<<<624, tb, GEMM_SMEM>>>(phs16, penc16, pw16, ga, 0);

    // 3: fused RMSNorm (Q gets 0.125*log2e folded in)
    rms_fused<<<(QCHUNKS + KCHUNKS) / 8, tb>>>(nqw, nkw, nakw);

    // 4: flash attention (BQ=128, no-max softmax)
    attn_kernel<<<dim3(S_HID / 128, HEADS), tb, ATTN_SMEM>>>();

    // 5: output projection -> fp32
    gemm_fused<<<192, tb, GEMM_SMEM>>>(pO16, nullptr, pw16, ga, 1);
}

// round 12
// speedup vs baseline: 9.4374x; 1.0212x over previous
#include <cuda_runtime.h>
#include <cuda_fp16.h>
#include <cstdint>

// Problem constants
#define DMODEL 1536
#define HEADS  24
#define HDIM   64
#define S_HID  2048
#define S_ENCC 256
#define T_TOT  2304
#define NKT    (T_TOT / 64)           // 36 key tiles
#define NW     (DMODEL * DMODEL)      // weight elements
#define LOG2E  1.44269504088896f

// ---------------------------------------------------------------------------
// Scratch (__device__ globals; no allocations allowed)
// ---------------------------------------------------------------------------
__device__ __align__(1024) __half g_Q16[(size_t)S_HID * DMODEL];
__device__ __align__(1024) __half g_K16[(size_t)T_TOT * DMODEL];
__device__ __align__(1024) __half g_V16[(size_t)T_TOT * DMODEL];
__device__ __align__(1024) __half g_O16[(size_t)S_HID * DMODEL];
__device__ __align__(1024) __half g_hs16[(size_t)S_HID * DMODEL];
__device__ __align__(1024) __half g_enc16[(size_t)S_ENCC * DMODEL];
__device__ __align__(1024) __half g_w16[6][(size_t)NW];
__device__ __align__(1024) float  g_mask2[T_TOT];   // mask * log2(e)

// ---------------------------------------------------------------------------
// PTX helpers (plain sm_103-safe)
// ---------------------------------------------------------------------------
__device__ __forceinline__ uint32_t smem_u32(const void* p) {
    return (uint32_t)__cvta_generic_to_shared(p);
}
__device__ __forceinline__ void cp_async16(uint32_t saddr, const void* gaddr) {
    asm volatile("cp.async.cg.shared.global [%0], [%1], 16;" :: "r"(saddr), "l"(gaddr) : "memory");
}
__device__ __forceinline__ void cp_async4(uint32_t saddr, const void* gaddr) {
    asm volatile("cp.async.ca.shared.global [%0], [%1], 4;" :: "r"(saddr), "l"(gaddr) : "memory");
}
__device__ __forceinline__ float ex2(float x) {
    float y;
    asm("ex2.approx.f32 %0, %1;" : "=f"(y) : "f"(x));
    return y;
}

#define CP_COMMIT()  asm volatile("cp.async.commit_group;" ::: "memory")
#define CP_WAIT(n)   asm volatile("cp.async.wait_group %0;" :: "n"(n) : "memory")

#define LDMATRIX_X4(r0, r1, r2, r3, addr) \
    asm volatile("ldmatrix.sync.aligned.m8n8.x4.shared.b16 {%0,%1,%2,%3}, [%4];" \
                 : "=r"(r0), "=r"(r1), "=r"(r2), "=r"(r3) : "r"(addr))
#define LDMATRIX_X4T(r0, r1, r2, r3, addr) \
    asm volatile("ldmatrix.sync.aligned.m8n8.x4.trans.shared.b16 {%0,%1,%2,%3}, [%4];" \
                 : "=r"(r0), "=r"(r1), "=r"(r2), "=r"(r3) : "r"(addr))

#define MMA16816(d, a, b) \
    asm volatile("mma.sync.aligned.m16n8k16.row.col.f32.f16.f16.f32 " \
                 "{%0,%1,%2,%3}, {%4,%5,%6,%7}, {%8,%9}, {%0,%1,%2,%3};" \
                 : "+f"((d)[0]), "+f"((d)[1]), "+f"((d)[2]), "+f"((d)[3]) \
                 : "r"((a)[0]), "r"((a)[1]), "r"((a)[2]), "r"((a)[3]), \
                   "r"((b)[0]), "r"((b)[1]))

__device__ __forceinline__ uint32_t pack_h2(float x, float y) {
    union { __half2 h; uint32_t u; } p;
    p.h = __floats2half2_rn(x, y);
    return p.u;
}

// ---------------------------------------------------------------------------
// Fused convert: hs + enc + 6 weights + mask (prescaled by log2e).
// Each block: 4096 floats, 4 independent float4 per thread (MLP=4).
// blocks: [0,768) hs | [768,864) enc | [864,4320) weights | 4320 mask
// ---------------------------------------------------------------------------
struct Ptr6 { const float* p[6]; };
#define CVT_BLOCKS 4321

__global__ __launch_bounds__(256) void cvt_all(const float* __restrict__ hs,
                                               const float* __restrict__ enc,
                                               const float* __restrict__ mask,
                                               Ptr6 w) {
    int b = blockIdx.x;
    int t4 = threadIdx.x * 4;

    if (b == 4320) {
#pragma unroll
        for (int p = 0; p < 3; p++) {
            int i = t4 + p * 1024;
            if (i < T_TOT) {
                float4 v = *(const float4*)(mask + i);
                v.x *= LOG2E; v.y *= LOG2E; v.z *= LOG2E; v.w *= LOG2E;
                *(float4*)(g_mask2 + i) = v;
            }
        }
        return;
    }

    const float* src; __half* dst; int off;
    if (b < 768)      { src = hs;  dst = g_hs16;  off = b * 4096; }
    else if (b < 864) { src = enc; dst = g_enc16; off = (b - 768) * 4096; }
    else {
        int e = b - 864;
        int seg = e / 576;
        src = w.p[seg]; dst = g_w16[seg]; off = (e % 576) * 4096;
    }

    float4 v[4];
#pragma unroll
    for (int p = 0; p < 4; p++)
        v[p] = *(const float4*)(src + off + t4 + p * 1024);
#pragma unroll
    for (int p = 0; p < 4; p++) {
        union { __half2 h[2]; uint2 u; } pk;
        pk.h[0] = __floats2half2_rn(v[p].x, v[p].y);
        pk.h[1] = __floats2half2_rn(v[p].z, v[p].w);
        *reinterpret_cast<uint2*>(dst + off + t4 + p * 1024) = pk.u;
    }
}

// ---------------------------------------------------------------------------
// Merged HMMA GEMM (unchanged).
// mode 0: grid 624 (QKV + encoder).  mode 1: grid 192 (out-proj, fp32).
// ---------------------------------------------------------------------------
#define PADK 40
#define G_STAGE_H (2 * 128 * PADK)
#define GEMM_SMEM (3 * G_STAGE_H * 2)

struct GemmArgs {
    const float* bias[6];
    __half* out16[6];
    float* out32;
};

__global__ __launch_bounds__(256, 2) void gemm_fused(
    const __half* __restrict__ A0, const __half* __restrict__ A1,
    const __half* __restrict__ Wbase, GemmArgs args, int mode)
{
    extern __shared__ __half smg[];

    int tid = threadIdx.x;
    int wid = tid >> 5, lane = tid & 31;
    int wm = wid >> 2;
    int wn = wid & 3;

    int bid = blockIdx.x;
    const __half* A;
    int seg, mbase, nbase;
    if (mode == 1) {
        seg = 5;
        mbase = (bid / 12) << 7;
        nbase = (bid % 12) << 7;
        A = A0;
    } else if (bid < 576) {
        seg = bid / 192;
        int r = bid % 192;
        mbase = (r / 12) << 7;
        nbase = (r % 12) << 7;
        A = A0;
    } else {
        int e = bid - 576;
        seg = 3 + e / 24;
        int r = e % 24;
        mbase = (r / 12) << 7;
        nbase = (r % 12) << 7;
        A = A1;
    }
    const int K = DMODEL, N = DMODEL;
    const int NK = K >> 5;   // 48
    const __half* W = Wbase + (size_t)seg * NW;

    float acc[4][4][4];
#pragma unroll
    for (int mi = 0; mi < 4; mi++)
#pragma unroll
        for (int ni = 0; ni < 4; ni++)
#pragma unroll
            for (int e = 0; e < 4; e++) acc[mi][ni][e] = 0.f;

    auto load_tile = [&](int it) {
        __half* sA = smg + (it % 3) * G_STAGE_H;
        __half* sW = sA + 128 * PADK;
        int kb = it << 5;
#pragma unroll
        for (int i = 0; i < 2; i++) {
            int c = tid + (i << 8);
            int row = c >> 2;
            int col = (c & 3) << 3;
            cp_async16(smem_u32(&sA[row * PADK + col]),
                       A + (size_t)(mbase + row) * K + kb + col);
            cp_async16(smem_u32(&sW[row * PADK + col]),
                       W + (size_t)(nbase + row) * K + kb + col);
        }
        CP_COMMIT();
    };

    load_tile(0);
    load_tile(1);

    for (int it = 0; it < NK; it++) {
        if (it + 1 < NK) CP_WAIT(1); else CP_WAIT(0);
        __syncthreads();
        if (it + 2 < NK) load_tile(it + 2);

        const __half* sA = smg + (it % 3) * G_STAGE_H;
        const __half* sW = sA + 128 * PADK;
#pragma unroll
        for (int ks = 0; ks < 2; ks++) {
            uint32_t afr[4][4];
#pragma unroll
            for (int mi = 0; mi < 4; mi++) {
                int m = wm * 64 + mi * 16 + (lane & 15);
                int kk = ks * 16 + ((lane >> 4) << 3);
                LDMATRIX_X4(afr[mi][0], afr[mi][1], afr[mi][2], afr[mi][3],
                            smem_u32(&sA[m * PADK + kk]));
            }
            uint32_t bfr[4][2];
#pragma unroll
            for (int nb = 0; nb < 2; nb++) {
                int n = wn * 32 + nb * 16 + (lane & 7) + (((lane >> 4) & 1) << 3);
                int kk = ks * 16 + (((lane >> 3) & 1) << 3);
                uint32_t r0, r1, r2, r3;
                LDMATRIX_X4(r0, r1, r2, r3, smem_u32(&sW[n * PADK + kk]));
                bfr[nb * 2][0] = r0; bfr[nb * 2][1] = r1;
                bfr[nb * 2 + 1][0] = r2; bfr[nb * 2 + 1][1] = r3;
            }
#pragma unroll
            for (int mi = 0; mi < 4; mi++)
#pragma unroll
                for (int ni = 0; ni < 4; ni++)
                    MMA16816(acc[mi][ni], afr[mi], bfr[ni]);
        }
    }

    const float* bias = args.bias[seg];
    __half* O16 = args.out16[seg];
    int g = lane >> 2, tq = lane & 3;
#pragma unroll
    for (int mi = 0; mi < 4; mi++) {
        int row0 = mbase + wm * 64 + mi * 16 + g;
#pragma unroll
        for (int ni = 0; ni < 4; ni++) {
            int col = nbase + wn * 32 + ni * 8 + tq * 2;
            float bx = bias[col], by = bias[col + 1];
            float v00 = acc[mi][ni][0] + bx, v01 = acc[mi][ni][1] + by;
            float v10 = acc[mi][ni][2] + bx, v11 = acc[mi][ni][3] + by;
            if (mode == 1) {
                *(float2*)(args.out32 + (size_t)row0 * N + col) = make_float2(v00, v01);
                *(float2*)(args.out32 + (size_t)(row0 + 8) * N + col) = make_float2(v10, v11);
            } else {
                *(__half2*)(O16 + (size_t)row0 * N + col) = __floats2half2_rn(v00, v01);
                *(__half2*)(O16 + (size_t)(row0 + 8) * N + col) = __floats2half2_rn(v10, v11);
            }
        }
    }
}

// ---------------------------------------------------------------------------
// Fused per-head RMSNorm. Q chunks folded with 0.125*log2(e).
// ---------------------------------------------------------------------------
#define QCHUNKS (S_HID * HEADS)
#define KCHUNKS (T_TOT * HEADS)
#define QSCALE  (0.125f * LOG2E)

__global__ __launch_bounds__(256) void rms_fused(
    const float* __restrict__ wq, const float* __restrict__ wk,
    const float* __restrict__ wak)
{
    int chunk = blockIdx.x * 8 + (threadIdx.x >> 5);
    int lane = threadIdx.x & 31;

    __half* buf;
    const float* w;
    int row, head;
    float post;
    if (chunk < QCHUNKS) {
        buf = g_Q16; row = chunk / HEADS; head = chunk % HEADS; w = wq;
        post = QSCALE;
    } else {
        int c = chunk - QCHUNKS;
        buf = g_K16; row = c / HEADS; head = c % HEADS;
        w = (row < S_HID) ? wk : wak;
        post = 1.0f;
    }

    __half2* p = (__half2*)(buf + (size_t)row * DMODEL + head * HDIM);
    float2 x = __half22float2(p[lane]);
    float ss = x.x * x.x + x.y * x.y;
#pragma unroll
    for (int o = 16; o; o >>= 1) ss += __shfl_xor_sync(0xffffffffu, ss, o);
    float r = rsqrtf(ss * (1.0f / 64.0f) + 1e-6f) * post;
    p[lane] = __floats2half2_rn(x.x * r * w[2 * lane], x.y * r * w[2 * lane + 1]);
}

// ---------------------------------------------------------------------------
// HMMA flash attention, no-max softmax. BQ=128, 128 threads (4 warps x 32
// q-rows = 2 m-tiles/warp). K/V fragments reused across both m-tiles:
// LDSM/MMA ratio halved vs 8-warp version. 3-stage K/V pipeline.
// ---------------------------------------------------------------------------
#define PADA 72
#define Q_TILE_H (128 * PADA)
#define A_TILE_H (64 * PADA)
#define ATTN_MSK_OFF ((Q_TILE_H + 6 * A_TILE_H) * 2)
#define ATTN_SMEM (ATTN_MSK_OFF + 3 * 64 * 4)

__global__ void __launch_bounds__(128, 2) attn_kernel()
{
    extern __shared__ __half sm[];
    __half* sQ = sm;
    float* smsk = (float*)((char*)sm + ATTN_MSK_OFF);

    int tid = threadIdx.x;
    int wm = tid >> 5, lane = tid & 31;
    int g = lane >> 2, tq = lane & 3;
    int head = blockIdx.y;
    int qbase = blockIdx.x << 7;
    int hoff = head * HDIM;

    auto load_kv = [&](int kt) {
        int st = kt % 3;
        __half* sK = sm + Q_TILE_H + st * A_TILE_H;
        __half* sV = sm + Q_TILE_H + (3 + st) * A_TILE_H;
        int kbase = kt << 6;
#pragma unroll
        for (int i = 0; i < 4; i++) {
            int c = tid + (i << 7);          // 0..511
            int row = c >> 3, col = (c & 7) << 3;
            size_t goff = (size_t)(kbase + row) * DMODEL + hoff + col;
            cp_async16(smem_u32(&sK[row * PADA + col]), g_K16 + goff);
            cp_async16(smem_u32(&sV[row * PADA + col]), g_V16 + goff);
        }
        if (tid < 64) cp_async4(smem_u32(&smsk[st * 64 + tid]), g_mask2 + kbase + tid);
        CP_COMMIT();
    };

    // group A: Q (128x64) + KV tile 0; group B: KV tile 1
#pragma unroll
    for (int i = 0; i < 8; i++) {
        int c = tid + (i << 7);              // 0..1023
        int row = c >> 3, col = (c & 7) << 3;
        cp_async16(smem_u32(&sQ[row * PADA + col]),
                   g_Q16 + (size_t)(qbase + row) * DMODEL + hoff + col);
    }
    {
        __half* sK = sm + Q_TILE_H;
        __half* sV = sm + Q_TILE_H + 3 * A_TILE_H;
#pragma unroll
        for (int i = 0; i < 4; i++) {
            int c = tid + (i << 7);
            int row = c >> 3, col = (c & 7) << 3;
            size_t goff = (size_t)row * DMODEL + hoff + col;
            cp_async16(smem_u32(&sK[row * PADA + col]), g_K16 + goff);
            cp_async16(smem_u32(&sV[row * PADA + col]), g_V16 + goff);
        }
        if (tid < 64) cp_async4(smem_u32(&smsk[tid]), g_mask2 + tid);
        CP_COMMIT();
    }
    load_kv(1);

    uint32_t qfr[2][4][4];
    float o[2][8][4];
#pragma unroll
    for (int mi = 0; mi < 2; mi++)
#pragma unroll
        for (int nt = 0; nt < 8; nt++)
#pragma unroll
            for (int e = 0; e < 4; e++) o[mi][nt][e] = 0.f;
    float l_lo[2] = {0.f, 0.f}, l_hi[2] = {0.f, 0.f};

    for (int kt = 0; kt < NKT; kt++) {
        if (kt + 1 < NKT) CP_WAIT(1); else CP_WAIT(0);
        __syncthreads();
        if (kt == 0) {
#pragma unroll
            for (int mi = 0; mi < 2; mi++)
#pragma unroll
                for (int kc = 0; kc < 4; kc++) {
                    int m = wm * 32 + mi * 16 + (lane & 15);
                    int kk = kc * 16 + ((lane >> 4) << 3);
                    LDMATRIX_X4(qfr[mi][kc][0], qfr[mi][kc][1], qfr[mi][kc][2],
                                qfr[mi][kc][3], smem_u32(&sQ[m * PADA + kk]));
                }
        }
        if (kt + 2 < NKT) load_kv(kt + 2);

        int st = kt % 3;
        const __half* sK = sm + Q_TILE_H + st * A_TILE_H;
        const __half* sV = sm + Q_TILE_H + (3 + st) * A_TILE_H;
        const float* mk = smsk + st * 64;

        // ---- S = Q @ K^T, K fragments shared across both m-tiles ----
        float sa[2][8][4];
#pragma unroll
        for (int mi = 0; mi < 2; mi++)
#pragma unroll
            for (int nt = 0; nt < 8; nt++)
#pragma unroll
                for (int e = 0; e < 4; e++) sa[mi][nt][e] = 0.f;

#pragma unroll
        for (int kc = 0; kc < 4; kc++) {
            uint32_t kf[8][2];
#pragma unroll
            for (int ntp = 0; ntp < 4; ntp++) {
                int n = ntp * 16 + (lane & 7) + (((lane >> 4) & 1) << 3);
                int kk = kc * 16 + (((lane >> 3) & 1) << 3);
                uint32_t r0, r1, r2, r3;
                LDMATRIX_X4(r0, r1, r2, r3, smem_u32(&sK[n * PADA + kk]));
                kf[ntp * 2][0] = r0; kf[ntp * 2][1] = r1;
                kf[ntp * 2 + 1][0] = r2; kf[ntp * 2 + 1][1] = r3;
            }
#pragma unroll
            for (int nt = 0; nt < 8; nt++) {
                MMA16816(sa[0][nt], qfr[0][kc], kf[nt]);
                MMA16816(sa[1][nt], qfr[1][kc], kf[nt]);
            }
        }

        // ---- p = exp2(s + mask'), per-thread denominator, pack to half ----
        uint32_t pa[2][4][4];
#pragma unroll
        for (int mi = 0; mi < 2; mi++) {
#pragma unroll
            for (int nt = 0; nt < 8; nt++) {
                float mk0 = mk[nt * 8 + 2 * tq];
                float mk1 = mk[nt * 8 + 2 * tq + 1];
                sa[mi][nt][0] = ex2(sa[mi][nt][0] + mk0);
                sa[mi][nt][1] = ex2(sa[mi][nt][1] + mk1);
                sa[mi][nt][2] = ex2(sa[mi][nt][2] + mk0);
                sa[mi][nt][3] = ex2(sa[mi][nt][3] + mk1);
                l_lo[mi] += sa[mi][nt][0] + sa[mi][nt][1];
                l_hi[mi] += sa[mi][nt][2] + sa[mi][nt][3];
            }
#pragma unroll
            for (int c = 0; c < 4; c++) {
                pa[mi][c][0] = pack_h2(sa[mi][2 * c][0], sa[mi][2 * c][1]);
                pa[mi][c][1] = pack_h2(sa[mi][2 * c][2], sa[mi][2 * c][3]);
                pa[mi][c][2] = pack_h2(sa[mi][2 * c + 1][0], sa[mi][2 * c + 1][1]);
                pa[mi][c][3] = pack_h2(sa[mi][2 * c + 1][2], sa[mi][2 * c + 1][3]);
            }
        }

        // ---- O += P @ V, V fragments shared across both m-tiles ----
#pragma unroll
        for (int c = 0; c < 4; c++) {
            uint32_t vrow = smem_u32(&sV[(c * 16 + (lane & 15)) * PADA + ((lane >> 4) & 1) * 8]);
#pragma unroll
            for (int ntd = 0; ntd < 8; ntd += 2) {
                uint32_t vb[4];
                LDMATRIX_X4T(vb[0], vb[1], vb[2], vb[3], vrow + ntd * 16);
                MMA16816(o[0][ntd], pa[0][c], vb);
                MMA16816(o[0][ntd + 1], pa[0][c], (vb + 2));
                MMA16816(o[1][ntd], pa[1][c], vb);
                MMA16816(o[1][ntd + 1], pa[1][c], (vb + 2));
            }
        }
    }

    // ---- single final denominator reduction + store ----
#pragma unroll
    for (int mi = 0; mi < 2; mi++) {
#pragma unroll
        for (int off = 1; off < 4; off <<= 1) {
            l_lo[mi] += __shfl_xor_sync(0xffffffffu, l_lo[mi], off);
            l_hi[mi] += __shfl_xor_sync(0xffffffffu, l_hi[mi], off);
        }
        float inv_lo = 1.f / l_lo[mi], inv_hi = 1.f / l_hi[mi];
        int row_lo = qbase + wm * 32 + mi * 16 + g;
#pragma unroll
        for (int nt = 0; nt < 8; nt++) {
            int col = hoff + nt * 8 + 2 * tq;
            *(__half2*)(g_O16 + (size_t)row_lo * DMODEL + col) =
                __floats2half2_rn(o[mi][nt][0] * inv_lo, o[mi][nt][1] * inv_lo);
            *(__half2*)(g_O16 + (size_t)(row_lo + 8) * DMODEL + col) =
                __floats2half2_rn(o[mi][nt][2] * inv_hi, o[mi][nt][3] * inv_hi);
        }
    }
}

// ---------------------------------------------------------------------------
// kernel_launch (5 launches)
// ---------------------------------------------------------------------------
extern "C" void kernel_launch(void* const* d_in, const int* in_sizes, int n_in,
                              void* d_out, int out_size)
{
    (void)in_sizes; (void)n_in; (void)out_size;
    const float* hs   = (const float*)d_in[0];
    const float* enc  = (const float*)d_in[1];
    const float* mask = (const float*)d_in[2];
    const float* wq   = (const float*)d_in[3];
    const float* bq   = (const float*)d_in[4];
    const float* wk   = (const float*)d_in[5];
    const float* bk   = (const float*)d_in[6];
    const float* wv   = (const float*)d_in[7];
    const float* bv   = (const float*)d_in[8];
    const float* nqw  = (const float*)d_in[9];
    const float* nkw  = (const float*)d_in[10];
    const float* akw  = (const float*)d_in[13];
    const float* akb  = (const float*)d_in[14];
    const float* avw  = (const float*)d_in[15];
    const float* avb  = (const float*)d_in[16];
    const float* nakw = (const float*)d_in[18];
    const float* wo   = (const float*)d_in[19];
    const float* bo   = (const float*)d_in[20];
    float* out = (float*)d_out;

    __half *pQ16, *pK16, *pV16, *pO16, *phs16, *penc16, *pw16;
    cudaGetSymbolAddress((void**)&pQ16, g_Q16);
    cudaGetSymbolAddress((void**)&pK16, g_K16);
    cudaGetSymbolAddress((void**)&pV16, g_V16);
    cudaGetSymbolAddress((void**)&pO16, g_O16);
    cudaGetSymbolAddress((void**)&phs16, g_hs16);
    cudaGetSymbolAddress((void**)&penc16, g_enc16);
    cudaGetSymbolAddress((void**)&pw16, g_w16);

    cudaFuncSetAttribute(gemm_fused, cudaFuncAttributeMaxDynamicSharedMemorySize, GEMM_SMEM);
    cudaFuncSetAttribute(attn_kernel, cudaFuncAttributeMaxDynamicSharedMemorySize, ATTN_SMEM);

    dim3 tb(256);
    const int ENC_OFF = S_HID * DMODEL;

    // 1: all converts (weights: q,k,v,ak,av,o) + mask prescale
    Ptr6 wsrc; wsrc.p[0] = wq; wsrc.p[1] = wk; wsrc.p[2] = wv;
    wsrc.p[3] = akw; wsrc.p[4] = avw; wsrc.p[5] = wo;
    cvt_all<<<CVT_BLOCKS, tb>>>(hs, enc, mask, wsrc);

    // 2: merged QKV + encoder projections (624 CTAs)
    GemmArgs ga;
    ga.bias[0] = bq;  ga.bias[1] = bk;  ga.bias[2] = bv;
    ga.bias[3] = akb; ga.bias[4] = avb; ga.bias[5] = bo;
    ga.out16[0] = pQ16; ga.out16[1] = pK16; ga.out16[2] = pV16;
    ga.out16[3] = pK16 + ENC_OFF; ga.out16[4] = pV16 + ENC_OFF; ga.out16[5] = nullptr;
    ga.out32 = out;
    gemm_fused<<<624, tb, GEMM_SMEM>>>(phs16, penc16, pw16, ga, 0);

    // 3: fused RMSNorm (Q gets 0.125*log2e folded in)
    rms_fused<<<(QCHUNKS + KCHUNKS) / 8, tb>>>(nqw, nkw, nakw);

    // 4: flash attention (BQ=128, 4 warps x 32 rows)
    attn_kernel<<<dim3(S_HID / 128, HEADS), 128, ATTN_SMEM>>>();

    // 5: output projection -> fp32
    gemm_fused<<<192, tb, GEMM_SMEM>>>(pO16, nullptr, pw16, ga, 1);
}

// round 13
// speedup vs baseline: 9.6358x; 1.0210x over previous
#include <cuda_runtime.h>
#include <cuda_fp16.h>
#include <cstdint>

// Problem constants
#define DMODEL 1536
#define HEADS  24
#define HDIM   64
#define S_HID  2048
#define S_ENCC 256
#define T_TOT  2304
#define NKT    (T_TOT / 64)           // 36 key tiles
#define NW     (DMODEL * DMODEL)      // weight elements
#define LOG2E  1.44269504088896f

// ---------------------------------------------------------------------------
// Scratch (__device__ globals; no allocations allowed)
// ---------------------------------------------------------------------------
__device__ __align__(1024) __half g_Q16[(size_t)S_HID * DMODEL];
__device__ __align__(1024) __half g_K16[(size_t)T_TOT * DMODEL];
__device__ __align__(1024) __half g_V16[(size_t)T_TOT * DMODEL];
__device__ __align__(1024) __half g_O16[(size_t)S_HID * DMODEL];
__device__ __align__(1024) __half g_hs16[(size_t)S_HID * DMODEL];
__device__ __align__(1024) __half g_enc16[(size_t)S_ENCC * DMODEL];
__device__ __align__(1024) __half g_w16[6][(size_t)NW];
__device__ __align__(1024) __half g_mask2h[T_TOT];  // mask * log2(e), half

// ---------------------------------------------------------------------------
// PTX helpers (plain sm_103-safe)
// ---------------------------------------------------------------------------
__device__ __forceinline__ uint32_t smem_u32(const void* p) {
    return (uint32_t)__cvta_generic_to_shared(p);
}
__device__ __forceinline__ void cp_async16(uint32_t saddr, const void* gaddr) {
    asm volatile("cp.async.cg.shared.global [%0], [%1], 16;" :: "r"(saddr), "l"(gaddr) : "memory");
}
__device__ __forceinline__ void cp_async4(uint32_t saddr, const void* gaddr) {
    asm volatile("cp.async.ca.shared.global [%0], [%1], 4;" :: "r"(saddr), "l"(gaddr) : "memory");
}
__device__ __forceinline__ uint32_t hadd2u(uint32_t a, uint32_t b) {
    uint32_t d;
    asm("add.rn.f16x2 %0, %1, %2;" : "=r"(d) : "r"(a), "r"(b));
    return d;
}
__device__ __forceinline__ uint32_t ex2h2(uint32_t a) {
    uint32_t d;
    asm("ex2.approx.f16x2 %0, %1;" : "=r"(d) : "r"(a));
    return d;
}

#define CP_COMMIT()  asm volatile("cp.async.commit_group;" ::: "memory")
#define CP_WAIT(n)   asm volatile("cp.async.wait_group %0;" :: "n"(n) : "memory")

#define LDMATRIX_X4(r0, r1, r2, r3, addr) \
    asm volatile("ldmatrix.sync.aligned.m8n8.x4.shared.b16 {%0,%1,%2,%3}, [%4];" \
                 : "=r"(r0), "=r"(r1), "=r"(r2), "=r"(r3) : "r"(addr))
#define LDMATRIX_X4T(r0, r1, r2, r3, addr) \
    asm volatile("ldmatrix.sync.aligned.m8n8.x4.trans.shared.b16 {%0,%1,%2,%3}, [%4];" \
                 : "=r"(r0), "=r"(r1), "=r"(r2), "=r"(r3) : "r"(addr))

#define MMA16816(d, a, b) \
    asm volatile("mma.sync.aligned.m16n8k16.row.col.f32.f16.f16.f32 " \
                 "{%0,%1,%2,%3}, {%4,%5,%6,%7}, {%8,%9}, {%0,%1,%2,%3};" \
                 : "+f"((d)[0]), "+f"((d)[1]), "+f"((d)[2]), "+f"((d)[3]) \
                 : "r"((a)[0]), "r"((a)[1]), "r"((a)[2]), "r"((a)[3]), \
                   "r"((b)[0]), "r"((b)[1]))

__device__ __forceinline__ uint32_t pack_h2(float x, float y) {
    union { __half2 h; uint32_t u; } p;
    p.h = __floats2half2_rn(x, y);
    return p.u;
}

// ---------------------------------------------------------------------------
// Fused convert: hs + enc + 6 weights + mask (prescaled by log2e, half).
// blocks: [0,768) hs | [768,864) enc | [864,4320) weights | 4320 mask
// ---------------------------------------------------------------------------
struct Ptr6 { const float* p[6]; };
#define CVT_BLOCKS 4321

__global__ __launch_bounds__(256) void cvt_all(const float* __restrict__ hs,
                                               const float* __restrict__ enc,
                                               const float* __restrict__ mask,
                                               Ptr6 w) {
    int b = blockIdx.x;
    int t4 = threadIdx.x * 4;

    if (b == 4320) {
#pragma unroll
        for (int p = 0; p < 3; p++) {
            int i = t4 + p * 1024;
            if (i < T_TOT) {
                float4 v = *(const float4*)(mask + i);
                union { __half2 h[2]; uint2 u; } pk;
                pk.h[0] = __floats2half2_rn(v.x * LOG2E, v.y * LOG2E);
                pk.h[1] = __floats2half2_rn(v.z * LOG2E, v.w * LOG2E);
                *reinterpret_cast<uint2*>(g_mask2h + i) = pk.u;
            }
        }
        return;
    }

    const float* src; __half* dst; int off;
    if (b < 768)      { src = hs;  dst = g_hs16;  off = b * 4096; }
    else if (b < 864) { src = enc; dst = g_enc16; off = (b - 768) * 4096; }
    else {
        int e = b - 864;
        int seg = e / 576;
        src = w.p[seg]; dst = g_w16[seg]; off = (e % 576) * 4096;
    }

    float4 v[4];
#pragma unroll
    for (int p = 0; p < 4; p++)
        v[p] = *(const float4*)(src + off + t4 + p * 1024);
#pragma unroll
    for (int p = 0; p < 4; p++) {
        union { __half2 h[2]; uint2 u; } pk;
        pk.h[0] = __floats2half2_rn(v[p].x, v[p].y);
        pk.h[1] = __floats2half2_rn(v[p].z, v[p].w);
        *reinterpret_cast<uint2*>(dst + off + t4 + p * 1024) = pk.u;
    }
}

// ---------------------------------------------------------------------------
// Merged HMMA GEMM (unchanged).
// mode 0: grid 624 (QKV + encoder).  mode 1: grid 192 (out-proj, fp32).
// ---------------------------------------------------------------------------
#define PADK 40
#define G_STAGE_H (2 * 128 * PADK)
#define GEMM_SMEM (3 * G_STAGE_H * 2)

struct GemmArgs {
    const float* bias[6];
    __half* out16[6];
    float* out32;
};

__global__ __launch_bounds__(256, 2) void gemm_fused(
    const __half* __restrict__ A0, const __half* __restrict__ A1,
    const __half* __restrict__ Wbase, GemmArgs args, int mode)
{
    extern __shared__ __half smg[];

    int tid = threadIdx.x;
    int wid = tid >> 5, lane = tid & 31;
    int wm = wid >> 2;
    int wn = wid & 3;

    int bid = blockIdx.x;
    const __half* A;
    int seg, mbase, nbase;
    if (mode == 1) {
        seg = 5;
        mbase = (bid / 12) << 7;
        nbase = (bid % 12) << 7;
        A = A0;
    } else if (bid < 576) {
        seg = bid / 192;
        int r = bid % 192;
        mbase = (r / 12) << 7;
        nbase = (r % 12) << 7;
        A = A0;
    } else {
        int e = bid - 576;
        seg = 3 + e / 24;
        int r = e % 24;
        mbase = (r / 12) << 7;
        nbase = (r % 12) << 7;
        A = A1;
    }
    const int K = DMODEL, N = DMODEL;
    const int NK = K >> 5;   // 48
    const __half* W = Wbase + (size_t)seg * NW;

    float acc[4][4][4];
#pragma unroll
    for (int mi = 0; mi < 4; mi++)
#pragma unroll
        for (int ni = 0; ni < 4; ni++)
#pragma unroll
            for (int e = 0; e < 4; e++) acc[mi][ni][e] = 0.f;

    auto load_tile = [&](int it) {
        __half* sA = smg + (it % 3) * G_STAGE_H;
        __half* sW = sA + 128 * PADK;
        int kb = it << 5;
#pragma unroll
        for (int i = 0; i < 2; i++) {
            int c = tid + (i << 8);
            int row = c >> 2;
            int col = (c & 3) << 3;
            cp_async16(smem_u32(&sA[row * PADK + col]),
                       A + (size_t)(mbase + row) * K + kb + col);
            cp_async16(smem_u32(&sW[row * PADK + col]),
                       W + (size_t)(nbase + row) * K + kb + col);
        }
        CP_COMMIT();
    };

    load_tile(0);
    load_tile(1);

    for (int it = 0; it < NK; it++) {
        if (it + 1 < NK) CP_WAIT(1); else CP_WAIT(0);
        __syncthreads();
        if (it + 2 < NK) load_tile(it + 2);

        const __half* sA = smg + (it % 3) * G_STAGE_H;
        const __half* sW = sA + 128 * PADK;
#pragma unroll
        for (int ks = 0; ks < 2; ks++) {
            uint32_t afr[4][4];
#pragma unroll
            for (int mi = 0; mi < 4; mi++) {
                int m = wm * 64 + mi * 16 + (lane & 15);
                int kk = ks * 16 + ((lane >> 4) << 3);
                LDMATRIX_X4(afr[mi][0], afr[mi][1], afr[mi][2], afr[mi][3],
                            smem_u32(&sA[m * PADK + kk]));
            }
            uint32_t bfr[4][2];
#pragma unroll
            for (int nb = 0; nb < 2; nb++) {
                int n = wn * 32 + nb * 16 + (lane & 7) + (((lane >> 4) & 1) << 3);
                int kk = ks * 16 + (((lane >> 3) & 1) << 3);
                uint32_t r0, r1, r2, r3;
                LDMATRIX_X4(r0, r1, r2, r3, smem_u32(&sW[n * PADK + kk]));
                bfr[nb * 2][0] = r0; bfr[nb * 2][1] = r1;
                bfr[nb * 2 + 1][0] = r2; bfr[nb * 2 + 1][1] = r3;
            }
#pragma unroll
            for (int mi = 0; mi < 4; mi++)
#pragma unroll
                for (int ni = 0; ni < 4; ni++)
                    MMA16816(acc[mi][ni], afr[mi], bfr[ni]);
        }
    }

    const float* bias = args.bias[seg];
    __half* O16 = args.out16[seg];
    int g = lane >> 2, tq = lane & 3;
#pragma unroll
    for (int mi = 0; mi < 4; mi++) {
        int row0 = mbase + wm * 64 + mi * 16 + g;
#pragma unroll
        for (int ni = 0; ni < 4; ni++) {
            int col = nbase + wn * 32 + ni * 8 + tq * 2;
            float bx = bias[col], by = bias[col + 1];
            float v00 = acc[mi][ni][0] + bx, v01 = acc[mi][ni][1] + by;
            float v10 = acc[mi][ni][2] + bx, v11 = acc[mi][ni][3] + by;
            if (mode == 1) {
                *(float2*)(args.out32 + (size_t)row0 * N + col) = make_float2(v00, v01);
                *(float2*)(args.out32 + (size_t)(row0 + 8) * N + col) = make_float2(v10, v11);
            } else {
                *(__half2*)(O16 + (size_t)row0 * N + col) = __floats2half2_rn(v00, v01);
                *(__half2*)(O16 + (size_t)(row0 + 8) * N + col) = __floats2half2_rn(v10, v11);
            }
        }
    }
}

// ---------------------------------------------------------------------------
// Fused per-head RMSNorm. Q chunks folded with 0.125*log2(e).
// ---------------------------------------------------------------------------
#define QCHUNKS (S_HID * HEADS)
#define KCHUNKS (T_TOT * HEADS)
#define QSCALE  (0.125f * LOG2E)

__global__ __launch_bounds__(256) void rms_fused(
    const float* __restrict__ wq, const float* __restrict__ wk,
    const float* __restrict__ wak)
{
    int chunk = blockIdx.x * 8 + (threadIdx.x >> 5);
    int lane = threadIdx.x & 31;

    __half* buf;
    const float* w;
    int row, head;
    float post;
    if (chunk < QCHUNKS) {
        buf = g_Q16; row = chunk / HEADS; head = chunk % HEADS; w = wq;
        post = QSCALE;
    } else {
        int c = chunk - QCHUNKS;
        buf = g_K16; row = c / HEADS; head = c % HEADS;
        w = (row < S_HID) ? wk : wak;
        post = 1.0f;
    }

    __half2* p = (__half2*)(buf + (size_t)row * DMODEL + head * HDIM);
    float2 x = __half22float2(p[lane]);
    float ss = x.x * x.x + x.y * x.y;
#pragma unroll
    for (int o = 16; o; o >>= 1) ss += __shfl_xor_sync(0xffffffffu, ss, o);
    float r = rsqrtf(ss * (1.0f / 64.0f) + 1e-6f) * post;
    p[lane] = __floats2half2_rn(x.x * r * w[2 * lane], x.y * r * w[2 * lane + 1]);
}

// ---------------------------------------------------------------------------
// HMMA flash attention, no-max softmax. BQ=128, 128 threads (4 warps x 32
// q-rows). exp via ex2.approx.f16x2 (half MUFU), denominator via ones-MMA
// (no FADDs, no final shuffle). 3-stage K/V pipeline.
// ---------------------------------------------------------------------------
#define PADA 72
#define Q_TILE_H (128 * PADA)
#define A_TILE_H (64 * PADA)
#define ATTN_MSK_OFF ((Q_TILE_H + 6 * A_TILE_H) * 2)   // byte offset, half msk[3][64]
#define ATTN_SMEM (ATTN_MSK_OFF + 3 * 64 * 2)

__global__ void __launch_bounds__(128, 2) attn_kernel()
{
    extern __shared__ __half sm[];
    __half* sQ = sm;
    __half* smskh = (__half*)((char*)sm + ATTN_MSK_OFF);

    int tid = threadIdx.x;
    int wm = tid >> 5, lane = tid & 31;
    int g = lane >> 2, tq = lane & 3;
    int head = blockIdx.y;
    int qbase = blockIdx.x << 7;
    int hoff = head * HDIM;

    auto load_kv = [&](int kt) {
        int st = kt % 3;
        __half* sK = sm + Q_TILE_H + st * A_TILE_H;
        __half* sV = sm + Q_TILE_H + (3 + st) * A_TILE_H;
        int kbase = kt << 6;
#pragma unroll
        for (int i = 0; i < 4; i++) {
            int c = tid + (i << 7);          // 0..511
            int row = c >> 3, col = (c & 7) << 3;
            size_t goff = (size_t)(kbase + row) * DMODEL + hoff + col;
            cp_async16(smem_u32(&sK[row * PADA + col]), g_K16 + goff);
            cp_async16(smem_u32(&sV[row * PADA + col]), g_V16 + goff);
        }
        if (tid < 32) cp_async4(smem_u32(&smskh[st * 64 + tid * 2]),
                                g_mask2h + kbase + tid * 2);
        CP_COMMIT();
    };

    // group A: Q (128x64) + KV tile 0; group B: KV tile 1
#pragma unroll
    for (int i = 0; i < 8; i++) {
        int c = tid + (i << 7);              // 0..1023
        int row = c >> 3, col = (c & 7) << 3;
        cp_async16(smem_u32(&sQ[row * PADA + col]),
                   g_Q16 + (size_t)(qbase + row) * DMODEL + hoff + col);
    }
    {
        __half* sK = sm + Q_TILE_H;
        __half* sV = sm + Q_TILE_H + 3 * A_TILE_H;
#pragma unroll
        for (int i = 0; i < 4; i++) {
            int c = tid + (i << 7);
            int row = c >> 3, col = (c & 7) << 3;
            size_t goff = (size_t)row * DMODEL + hoff + col;
            cp_async16(smem_u32(&sK[row * PADA + col]), g_K16 + goff);
            cp_async16(smem_u32(&sV[row * PADA + col]), g_V16 + goff);
        }
        if (tid < 32) cp_async4(smem_u32(&smskh[tid * 2]), g_mask2h + tid * 2);
        CP_COMMIT();
    }
    load_kv(1);

    const uint32_t ones2[2] = {0x3C003C00u, 0x3C003C00u};   // half2(1,1) x2

    uint32_t qfr[2][4][4];
    float o[2][8][4];
    float lacc[2][4];
#pragma unroll
    for (int mi = 0; mi < 2; mi++) {
#pragma unroll
        for (int nt = 0; nt < 8; nt++)
#pragma unroll
            for (int e = 0; e < 4; e++) o[mi][nt][e] = 0.f;
#pragma unroll
        for (int e = 0; e < 4; e++) lacc[mi][e] = 0.f;
    }

    for (int kt = 0; kt < NKT; kt++) {
        if (kt + 1 < NKT) CP_WAIT(1); else CP_WAIT(0);
        __syncthreads();
        if (kt == 0) {
#pragma unroll
            for (int mi = 0; mi < 2; mi++)
#pragma unroll
                for (int kc = 0; kc < 4; kc++) {
                    int m = wm * 32 + mi * 16 + (lane & 15);
                    int kk = kc * 16 + ((lane >> 4) << 3);
                    LDMATRIX_X4(qfr[mi][kc][0], qfr[mi][kc][1], qfr[mi][kc][2],
                                qfr[mi][kc][3], smem_u32(&sQ[m * PADA + kk]));
                }
        }
        if (kt + 2 < NKT) load_kv(kt + 2);

        int st = kt % 3;
        const __half* sK = sm + Q_TILE_H + st * A_TILE_H;
        const __half* sV = sm + Q_TILE_H + (3 + st) * A_TILE_H;
        const __half* mk = smskh + st * 64;

        // ---- S = Q @ K^T, K fragments shared across both m-tiles ----
        float sa[2][8][4];
#pragma unroll
        for (int mi = 0; mi < 2; mi++)
#pragma unroll
            for (int nt = 0; nt < 8; nt++)
#pragma unroll
                for (int e = 0; e < 4; e++) sa[mi][nt][e] = 0.f;

#pragma unroll
        for (int kc = 0; kc < 4; kc++) {
            uint32_t kf[8][2];
#pragma unroll
            for (int ntp = 0; ntp < 4; ntp++) {
                int n = ntp * 16 + (lane & 7) + (((lane >> 4) & 1) << 3);
                int kk = kc * 16 + (((lane >> 3) & 1) << 3);
                uint32_t r0, r1, r2, r3;
                LDMATRIX_X4(r0, r1, r2, r3, smem_u32(&sK[n * PADA + kk]));
                kf[ntp * 2][0] = r0; kf[ntp * 2][1] = r1;
                kf[ntp * 2 + 1][0] = r2; kf[ntp * 2 + 1][1] = r3;
            }
#pragma unroll
            for (int nt = 0; nt < 8; nt++) {
                MMA16816(sa[0][nt], qfr[0][kc], kf[nt]);
                MMA16816(sa[1][nt], qfr[1][kc], kf[nt]);
            }
        }

        // ---- p = exp2(s + mask') in f16x2; l via ones-MMA ----
        uint32_t pa[2][4][4];
#pragma unroll
        for (int mi = 0; mi < 2; mi++) {
#pragma unroll
            for (int c = 0; c < 4; c++) {
                int nt0 = 2 * c, nt1 = 2 * c + 1;
                uint32_t hm0 = *(const uint32_t*)(mk + nt0 * 8 + 2 * tq);
                uint32_t hm1 = *(const uint32_t*)(mk + nt1 * 8 + 2 * tq);
                pa[mi][c][0] = ex2h2(hadd2u(pack_h2(sa[mi][nt0][0], sa[mi][nt0][1]), hm0));
                pa[mi][c][1] = ex2h2(hadd2u(pack_h2(sa[mi][nt0][2], sa[mi][nt0][3]), hm0));
                pa[mi][c][2] = ex2h2(hadd2u(pack_h2(sa[mi][nt1][0], sa[mi][nt1][1]), hm1));
                pa[mi][c][3] = ex2h2(hadd2u(pack_h2(sa[mi][nt1][2], sa[mi][nt1][3]), hm1));
                MMA16816(lacc[mi], pa[mi][c], ones2);
            }
        }

        // ---- O += P @ V, V fragments shared across both m-tiles ----
#pragma unroll
        for (int c = 0; c < 4; c++) {
            uint32_t vrow = smem_u32(&sV[(c * 16 + (lane & 15)) * PADA + ((lane >> 4) & 1) * 8]);
#pragma unroll
            for (int ntd = 0; ntd < 8; ntd += 2) {
                uint32_t vb[4];
                LDMATRIX_X4T(vb[0], vb[1], vb[2], vb[3], vrow + ntd * 16);
                MMA16816(o[0][ntd], pa[0][c], vb);
                MMA16816(o[0][ntd + 1], pa[0][c], (vb + 2));
                MMA16816(o[1][ntd], pa[1][c], vb);
                MMA16816(o[1][ntd + 1], pa[1][c], (vb + 2));
            }
        }
    }

    // ---- finalize: l is already fully reduced in lacc (replicated in quad) ----
#pragma unroll
    for (int mi = 0; mi < 2; mi++) {
        float inv_lo = 1.f / lacc[mi][0], inv_hi = 1.f / lacc[mi][2];
        int row_lo = qbase + wm * 32 + mi * 16 + g;
#pragma unroll
        for (int nt = 0; nt < 8; nt++) {
            int col = hoff + nt * 8 + 2 * tq;
            *(__half2*)(g_O16 + (size_t)row_lo * DMODEL + col) =
                __floats2half2_rn(o[mi][nt][0] * inv_lo, o[mi][nt][1] * inv_lo);
            *(__half2*)(g_O16 + (size_t)(row_lo + 8) * DMODEL + col) =
                __floats2half2_rn(o[mi][nt][2] * inv_hi, o[mi][nt][3] * inv_hi);
        }
    }
}

// ---------------------------------------------------------------------------
// kernel_launch (5 launches)
// ---------------------------------------------------------------------------
extern "C" void kernel_launch(void* const* d_in, const int* in_sizes, int n_in,
                              void* d_out, int out_size)
{
    (void)in_sizes; (void)n_in; (void)out_size;
    const float* hs   = (const float*)d_in[0];
    const float* enc  = (const float*)d_in[1];
    const float* mask = (const float*)d_in[2];
    const float* wq   = (const float*)d_in[3];
    const float* bq   = (const float*)d_in[4];
    const float* wk   = (const float*)d_in[5];
    const float* bk   = (const float*)d_in[6];
    const float* wv   = (const float*)d_in[7];
    const float* bv   = (const float*)d_in[8];
    const float* nqw  = (const float*)d_in[9];
    const float* nkw  = (const float*)d_in[10];
    const float* akw  = (const float*)d_in[13];
    const float* akb  = (const float*)d_in[14];
    const float* avw  = (const float*)d_in[15];
    const float* avb  = (const float*)d_in[16];
    const float* nakw = (const float*)d_in[18];
    const float* wo   = (const float*)d_in[19];
    const float* bo   = (const float*)d_in[20];
    float* out = (float*)d_out;

    __half *pQ16, *pK16, *pV16, *pO16, *phs16, *penc16, *pw16;
    cudaGetSymbolAddress((void**)&pQ16, g_Q16);
    cudaGetSymbolAddress((void**)&pK16, g_K16);
    cudaGetSymbolAddress((void**)&pV16, g_V16);
    cudaGetSymbolAddress((void**)&pO16, g_O16);
    cudaGetSymbolAddress((void**)&phs16, g_hs16);
    cudaGetSymbolAddress((void**)&penc16, g_enc16);
    cudaGetSymbolAddress((void**)&pw16, g_w16);

    cudaFuncSetAttribute(gemm_fused, cudaFuncAttributeMaxDynamicSharedMemorySize, GEMM_SMEM);
    cudaFuncSetAttribute(attn_kernel, cudaFuncAttributeMaxDynamicSharedMemorySize, ATTN_SMEM);

    dim3 tb(256);
    const int ENC_OFF = S_HID * DMODEL;

    // 1: all converts (weights: q,k,v,ak,av,o) + mask prescale (half)
    Ptr6 wsrc; wsrc.p[0] = wq; wsrc.p[1] = wk; wsrc.p[2] = wv;
    wsrc.p[3] = akw; wsrc.p[4] = avw; wsrc.p[5] = wo;
    cvt_all<<<CVT_BLOCKS, tb>>>(hs, enc, mask, wsrc);

    // 2: merged QKV + encoder projections (624 CTAs)
    GemmArgs ga;
    ga.bias[0] = bq;  ga.bias[1] = bk;  ga.bias[2] = bv;
    ga.bias[3] = akb; ga.bias[4] = avb; ga.bias[5] = bo;
    ga.out16[0] = pQ16; ga.out16[1] = pK16; ga.out16[2] = pV16;
    ga.out16[3] = pK16 + ENC_OFF; ga.out16[4] = pV16 + ENC_OFF; ga.out16[5] = nullptr;
    ga.out32 = out;
    gemm_fused<<<624, tb, GEMM_SMEM>>>(phs16, penc16, pw16, ga, 0);

    // 3: fused RMSNorm (Q gets 0.125*log2e folded in)
    rms_fused<<<(QCHUNKS + KCHUNKS) / 8, tb>>>(nqw, nkw, nakw);

    // 4: flash attention (BQ=128, 4 warps x 32 rows, f16x2 exp + ones-MMA l)
    attn_kernel<<<dim3(S_HID / 128, HEADS), 128, ATTN_SMEM>>>();

    // 5: output projection -> fp32
    gemm_fused<<<192, tb, GEMM_SMEM>>>(pO16, nullptr, pw16, ga, 1);
}

// round 15
// speedup vs baseline: 10.3502x; 1.0741x over previous
#include <cuda_runtime.h>
#include <cuda_fp16.h>
#include <cstdint>

// Problem constants
#define DMODEL 1536
#define HEADS  24
#define HDIM   64
#define S_HID  2048
#define S_ENCC 256
#define T_TOT  2304
#define NKT2   (T_TOT / 128)          // 18 key tiles of 128
#define NW     (DMODEL * DMODEL)
#define LOG2E  1.44269504088896f

// ---------------------------------------------------------------------------
// Scratch (__device__ globals; no allocations allowed)
// ---------------------------------------------------------------------------
__device__ __align__(1024) __half g_Q16[(size_t)S_HID * DMODEL];
__device__ __align__(1024) __half g_K16[(size_t)T_TOT * DMODEL];
__device__ __align__(1024) __half g_V16[(size_t)T_TOT * DMODEL];
__device__ __align__(1024) __half g_O16[(size_t)S_HID * DMODEL];
__device__ __align__(1024) __half g_hs16[(size_t)S_HID * DMODEL];
__device__ __align__(1024) __half g_enc16[(size_t)S_ENCC * DMODEL];
__device__ __align__(1024) __half g_w16[6][(size_t)NW];
__device__ __align__(1024) __half g_mask2h[T_TOT];  // mask * log2(e), half

// ---------------------------------------------------------------------------
// PTX helpers (plain sm_103-safe)
// ---------------------------------------------------------------------------
__device__ __forceinline__ uint32_t smem_u32(const void* p) {
    return (uint32_t)__cvta_generic_to_shared(p);
}
__device__ __forceinline__ void cp_async16(uint32_t saddr, const void* gaddr) {
    asm volatile("cp.async.cg.shared.global [%0], [%1], 16;" :: "r"(saddr), "l"(gaddr) : "memory");
}
__device__ __forceinline__ void cp_async4(uint32_t saddr, const void* gaddr) {
    asm volatile("cp.async.ca.shared.global [%0], [%1], 4;" :: "r"(saddr), "l"(gaddr) : "memory");
}
__device__ __forceinline__ uint32_t hadd2u(uint32_t a, uint32_t b) {
    uint32_t d;
    asm("add.rn.f16x2 %0, %1, %2;" : "=r"(d) : "r"(a), "r"(b));
    return d;
}
__device__ __forceinline__ uint32_t ex2h2(uint32_t a) {
    uint32_t d;
    asm("ex2.approx.f16x2 %0, %1;" : "=r"(d) : "r"(a));
    return d;
}

#define CP_COMMIT()  asm volatile("cp.async.commit_group;" ::: "memory")
#define CP_WAIT(n)   asm volatile("cp.async.wait_group %0;" :: "n"(n) : "memory")

#define LDMATRIX_X4(r0, r1, r2, r3, addr) \
    asm volatile("ldmatrix.sync.aligned.m8n8.x4.shared.b16 {%0,%1,%2,%3}, [%4];" \
                 : "=r"(r0), "=r"(r1), "=r"(r2), "=r"(r3) : "r"(addr))
#define LDMATRIX_X4T(r0, r1, r2, r3, addr) \
    asm volatile("ldmatrix.sync.aligned.m8n8.x4.trans.shared.b16 {%0,%1,%2,%3}, [%4];" \
                 : "=r"(r0), "=r"(r1), "=r"(r2), "=r"(r3) : "r"(addr))

#define MMA16816(d, a, b) \
    asm volatile("mma.sync.aligned.m16n8k16.row.col.f32.f16.f16.f32 " \
                 "{%0,%1,%2,%3}, {%4,%5,%6,%7}, {%8,%9}, {%0,%1,%2,%3};" \
                 : "+f"((d)[0]), "+f"((d)[1]), "+f"((d)[2]), "+f"((d)[3]) \
                 : "r"((a)[0]), "r"((a)[1]), "r"((a)[2]), "r"((a)[3]), \
                   "r"((b)[0]), "r"((b)[1]))

__device__ __forceinline__ uint32_t pack_h2(float x, float y) {
    union { __half2 h; uint32_t u; } p;
    p.h = __floats2half2_rn(x, y);
    return p.u;
}

// ---------------------------------------------------------------------------
// Fused convert: hs + enc + 6 weights + mask (prescaled by log2e, half).
// blocks: [0,768) hs | [768,864) enc | [864,4320) weights | 4320 mask
// ---------------------------------------------------------------------------
struct Ptr6 { const float* p[6]; };
#define CVT_BLOCKS 4321

__global__ __launch_bounds__(256) void cvt_all(const float* __restrict__ hs,
                                               const float* __restrict__ enc,
                                               const float* __restrict__ mask,
                                               Ptr6 w) {
    int b = blockIdx.x;
    int t4 = threadIdx.x * 4;

    if (b == 4320) {
#pragma unroll
        for (int p = 0; p < 3; p++) {
            int i = t4 + p * 1024;
            if (i < T_TOT) {
                float4 v = *(const float4*)(mask + i);
                union { __half2 h[2]; uint2 u; } pk;
                pk.h[0] = __floats2half2_rn(v.x * LOG2E, v.y * LOG2E);
                pk.h[1] = __floats2half2_rn(v.z * LOG2E, v.w * LOG2E);
                *reinterpret_cast<uint2*>(g_mask2h + i) = pk.u;
            }
        }
        return;
    }

    const float* src; __half* dst; int off;
    if (b < 768)      { src = hs;  dst = g_hs16;  off = b * 4096; }
    else if (b < 864) { src = enc; dst = g_enc16; off = (b - 768) * 4096; }
    else {
        int e = b - 864;
        int seg = e / 576;
        src = w.p[seg]; dst = g_w16[seg]; off = (e % 576) * 4096;
    }

    float4 v[4];
#pragma unroll
    for (int p = 0; p < 4; p++)
        v[p] = *(const float4*)(src + off + t4 + p * 1024);
#pragma unroll
    for (int p = 0; p < 4; p++) {
        union { __half2 h[2]; uint2 u; } pk;
        pk.h[0] = __floats2half2_rn(v[p].x, v[p].y);
        pk.h[1] = __floats2half2_rn(v[p].z, v[p].w);
        *reinterpret_cast<uint2*>(dst + off + t4 + p * 1024) = pk.u;
    }
}

// ---------------------------------------------------------------------------
// Merged HMMA GEMM, 128 threads (2x2 warps, 64x64 warp tiles).
// Block 128x128, BK=32, 3-stage cp.async, one barrier per k-iter.
// mode 0: grid 624 (QKV + encoder).  mode 1: grid 192 (out-proj, fp32).
// ---------------------------------------------------------------------------
#define PADK 40
#define G_STAGE_H (2 * 128 * PADK)
#define GEMM_SMEM (3 * G_STAGE_H * 2)

struct GemmArgs {
    const float* bias[6];
    __half* out16[6];
    float* out32;
};

__global__ void __launch_bounds__(128, 2) gemm_fused(
    const __half* __restrict__ A0, const __half* __restrict__ A1,
    const __half* __restrict__ Wbase, GemmArgs args, int mode)
{
    extern __shared__ __half smg[];

    int tid = threadIdx.x;
    int wid = tid >> 5, lane = tid & 31;
    int wm = wid >> 1;           // 0..1 -> 64 rows
    int wn = wid & 1;            // 0..1 -> 64 cols

    int bid = blockIdx.x;
    const __half* A;
    int seg, mbase, nbase;
    if (mode == 1) {
        seg = 5;
        mbase = (bid / 12) << 7;
        nbase = (bid % 12) << 7;
        A = A0;
    } else if (bid < 576) {
        seg = bid / 192;
        int r = bid % 192;
        mbase = (r / 12) << 7;
        nbase = (r % 12) << 7;
        A = A0;
    } else {
        int e = bid - 576;
        seg = 3 + e / 24;
        int r = e % 24;
        mbase = (r / 12) << 7;
        nbase = (r % 12) << 7;
        A = A1;
    }
    const int K = DMODEL, N = DMODEL;
    const int NK = K >> 5;   // 48
    const __half* W = Wbase + (size_t)seg * NW;

    float acc[4][8][4];
#pragma unroll
    for (int mi = 0; mi < 4; mi++)
#pragma unroll
        for (int ni = 0; ni < 8; ni++)
#pragma unroll
            for (int e = 0; e < 4; e++) acc[mi][ni][e] = 0.f;

    auto load_tile = [&](int it) {
        __half* sA = smg + (it % 3) * G_STAGE_H;
        __half* sW = sA + 128 * PADK;
        int kb = it << 5;
#pragma unroll
        for (int i = 0; i < 4; i++) {
            int c = tid + (i << 7);          // 0..511
            int row = c >> 2;
            int col = (c & 3) << 3;
            cp_async16(smem_u32(&sA[row * PADK + col]),
                       A + (size_t)(mbase + row) * K + kb + col);
            cp_async16(smem_u32(&sW[row * PADK + col]),
                       W + (size_t)(nbase + row) * K + kb + col);
        }
        CP_COMMIT();
    };

    load_tile(0);
    load_tile(1);

    for (int it = 0; it < NK; it++) {
        if (it + 1 < NK) CP_WAIT(1); else CP_WAIT(0);
        __syncthreads();
        if (it + 2 < NK) load_tile(it + 2);

        const __half* sA = smg + (it % 3) * G_STAGE_H;
        const __half* sW = sA + 128 * PADK;
#pragma unroll
        for (int ks = 0; ks < 2; ks++) {
            uint32_t afr[4][4];
#pragma unroll
            for (int mi = 0; mi < 4; mi++) {
                int m = wm * 64 + mi * 16 + (lane & 15);
                int kk = ks * 16 + ((lane >> 4) << 3);
                LDMATRIX_X4(afr[mi][0], afr[mi][1], afr[mi][2], afr[mi][3],
                            smem_u32(&sA[m * PADK + kk]));
            }
            uint32_t bfr[8][2];
#pragma unroll
            for (int ntp = 0; ntp < 4; ntp++) {
                int n = wn * 64 + ntp * 16 + (lane & 7) + (((lane >> 4) & 1) << 3);
                int kk = ks * 16 + (((lane >> 3) & 1) << 3);
                uint32_t r0, r1, r2, r3;
                LDMATRIX_X4(r0, r1, r2, r3, smem_u32(&sW[n * PADK + kk]));
                bfr[ntp * 2][0] = r0; bfr[ntp * 2][1] = r1;
                bfr[ntp * 2 + 1][0] = r2; bfr[ntp * 2 + 1][1] = r3;
            }
#pragma unroll
            for (int mi = 0; mi < 4; mi++)
#pragma unroll
                for (int ni = 0; ni < 8; ni++)
                    MMA16816(acc[mi][ni], afr[mi], bfr[ni]);
        }
    }

    const float* bias = args.bias[seg];
    __half* O16 = args.out16[seg];
    int g = lane >> 2, tq = lane & 3;
#pragma unroll
    for (int mi = 0; mi < 4; mi++) {
        int row0 = mbase + wm * 64 + mi * 16 + g;
#pragma unroll
        for (int ni = 0; ni < 8; ni++) {
            int col = nbase + wn * 64 + ni * 8 + tq * 2;
            float bx = bias[col], by = bias[col + 1];
            float v00 = acc[mi][ni][0] + bx, v01 = acc[mi][ni][1] + by;
            float v10 = acc[mi][ni][2] + bx, v11 = acc[mi][ni][3] + by;
            if (mode == 1) {
                *(float2*)(args.out32 + (size_t)row0 * N + col) = make_float2(v00, v01);
                *(float2*)(args.out32 + (size_t)(row0 + 8) * N + col) = make_float2(v10, v11);
            } else {
                *(__half2*)(O16 + (size_t)row0 * N + col) = __floats2half2_rn(v00, v01);
                *(__half2*)(O16 + (size_t)(row0 + 8) * N + col) = __floats2half2_rn(v10, v11);
            }
        }
    }
}

// ---------------------------------------------------------------------------
// Fused per-head RMSNorm. Q chunks folded with 0.125*log2(e).
// ---------------------------------------------------------------------------
#define QCHUNKS (S_HID * HEADS)
#define KCHUNKS (T_TOT * HEADS)
#define QSCALE  (0.125f * LOG2E)

__global__ __launch_bounds__(256) void rms_fused(
    const float* __restrict__ wq, const float* __restrict__ wk,
    const float* __restrict__ wak)
{
    int chunk = blockIdx.x * 8 + (threadIdx.x >> 5);
    int lane = threadIdx.x & 31;

    __half* buf;
    const float* w;
    int row, head;
    float post;
    if (chunk < QCHUNKS) {
        buf = g_Q16; row = chunk / HEADS; head = chunk % HEADS; w = wq;
        post = QSCALE;
    } else {
        int c = chunk - QCHUNKS;
        buf = g_K16; row = c / HEADS; head = c % HEADS;
        w = (row < S_HID) ? wk : wak;
        post = 1.0f;
    }

    __half2* p = (__half2*)(buf + (size_t)row * DMODEL + head * HDIM);
    float2 x = __half22float2(p[lane]);
    float ss = x.x * x.x + x.y * x.y;
#pragma unroll
    for (int o = 16; o; o >>= 1) ss += __shfl_xor_sync(0xffffffffu, ss, o);
    float r = rsqrtf(ss * (1.0f / 64.0f) + 1e-6f) * post;
    p[lane] = __floats2half2_rn(x.x * r * w[2 * lane], x.y * r * w[2 * lane + 1]);
}

// ---------------------------------------------------------------------------
// HMMA flash attention, no-max softmax. BQ=128, 128 threads (4 warps x 32
// q-rows). K/V tiles of 128 keys (two 64-key halves per barrier): 18 waits
// instead of 36. 2-stage pipeline. f16x2 exp + ones-MMA denominator.
// ---------------------------------------------------------------------------
#define PADA 72
#define QT_H (128 * PADA)                 // halfs: Q tile AND each K/V 128-row tile
// layout (halfs): Q | K0 | V0 | K1 | V1 | mask[2][128]
#define ATTN_MSK_OFF (5 * QT_H * 2)       // byte offset
#define ATTN_SMEM (ATTN_MSK_OFF + 2 * 128 * 2)

__global__ void __launch_bounds__(128, 2) attn_kernel()
{
    extern __shared__ __half sm[];
    __half* sQ = sm;
    __half* smskh = (__half*)((char*)sm + ATTN_MSK_OFF);

    int tid = threadIdx.x;
    int wm = tid >> 5, lane = tid & 31;
    int g = lane >> 2, tq = lane & 3;
    int head = blockIdx.y;
    int qbase = blockIdx.x << 7;
    int hoff = head * HDIM;

    auto load_kv = [&](int kt) {
        int st = kt & 1;
        __half* sK = sm + (1 + 2 * st) * QT_H;
        __half* sV = sm + (2 + 2 * st) * QT_H;
        int kbase = kt << 7;
#pragma unroll
        for (int i = 0; i < 8; i++) {
            int c = tid + (i << 7);          // 0..1023
            int row = c >> 3, col = (c & 7) << 3;
            size_t goff = (size_t)(kbase + row) * DMODEL + hoff + col;
            cp_async16(smem_u32(&sK[row * PADA + col]), g_K16 + goff);
            cp_async16(smem_u32(&sV[row * PADA + col]), g_V16 + goff);
        }
        if (tid < 64) cp_async4(smem_u32(&smskh[st * 128 + tid * 2]),
                                g_mask2h + kbase + tid * 2);
        CP_COMMIT();
    };

    // prime: Q chunks (uncommitted) + KV tile 0 (commits both)
#pragma unroll
    for (int i = 0; i < 8; i++) {
        int c = tid + (i << 7);
        int row = c >> 3, col = (c & 7) << 3;
        cp_async16(smem_u32(&sQ[row * PADA + col]),
                   g_Q16 + (size_t)(qbase + row) * DMODEL + hoff + col);
    }
    load_kv(0);

    const uint32_t ones2[2] = {0x3C003C00u, 0x3C003C00u};

    uint32_t qfr[2][4][4];
    float o[2][8][4];
    float lacc[2][4];
#pragma unroll
    for (int mi = 0; mi < 2; mi++) {
#pragma unroll
        for (int nt = 0; nt < 8; nt++)
#pragma unroll
            for (int e = 0; e < 4; e++) o[mi][nt][e] = 0.f;
#pragma unroll
        for (int e = 0; e < 4; e++) lacc[mi][e] = 0.f;
    }

    for (int kt = 0; kt < NKT2; kt++) {
        CP_WAIT(0);
        __syncthreads();
        if (kt == 0) {
#pragma unroll
            for (int mi = 0; mi < 2; mi++)
#pragma unroll
                for (int kc = 0; kc < 4; kc++) {
                    int m = wm * 32 + mi * 16 + (lane & 15);
                    int kk = kc * 16 + ((lane >> 4) << 3);
                    LDMATRIX_X4(qfr[mi][kc][0], qfr[mi][kc][1], qfr[mi][kc][2],
                                qfr[mi][kc][3], smem_u32(&sQ[m * PADA + kk]));
                }
        }
        if (kt + 1 < NKT2) load_kv(kt + 1);

        int st = kt & 1;

        // two 64-key halves of the 128-key tile
#pragma unroll
        for (int h = 0; h < 2; h++) {
            const __half* sK = sm + (1 + 2 * st) * QT_H + h * 64 * PADA;
            const __half* sV = sm + (2 + 2 * st) * QT_H + h * 64 * PADA;
            const __half* mk = smskh + st * 128 + h * 64;

            // ---- S = Q @ K^T ----
            float sa[2][8][4];
#pragma unroll
            for (int mi = 0; mi < 2; mi++)
#pragma unroll
                for (int nt = 0; nt < 8; nt++)
#pragma unroll
                    for (int e = 0; e < 4; e++) sa[mi][nt][e] = 0.f;

#pragma unroll
            for (int kc = 0; kc < 4; kc++) {
                uint32_t kf[8][2];
#pragma unroll
                for (int ntp = 0; ntp < 4; ntp++) {
                    int n = ntp * 16 + (lane & 7) + (((lane >> 4) & 1) << 3);
                    int kk = kc * 16 + (((lane >> 3) & 1) << 3);
                    uint32_t r0, r1, r2, r3;
                    LDMATRIX_X4(r0, r1, r2, r3, smem_u32(&sK[n * PADA + kk]));
                    kf[ntp * 2][0] = r0; kf[ntp * 2][1] = r1;
                    kf[ntp * 2 + 1][0] = r2; kf[ntp * 2 + 1][1] = r3;
                }
#pragma unroll
                for (int nt = 0; nt < 8; nt++) {
                    MMA16816(sa[0][nt], qfr[0][kc], kf[nt]);
                    MMA16816(sa[1][nt], qfr[1][kc], kf[nt]);
                }
            }

            // ---- p = exp2(s + mask') in f16x2; l via ones-MMA ----
            uint32_t pa[2][4][4];
#pragma unroll
            for (int mi = 0; mi < 2; mi++) {
#pragma unroll
                for (int c = 0; c < 4; c++) {
                    int nt0 = 2 * c, nt1 = 2 * c + 1;
                    uint32_t hm0 = *(const uint32_t*)(mk + nt0 * 8 + 2 * tq);
                    uint32_t hm1 = *(const uint32_t*)(mk + nt1 * 8 + 2 * tq);
                    pa[mi][c][0] = ex2h2(hadd2u(pack_h2(sa[mi][nt0][0], sa[mi][nt0][1]), hm0));
                    pa[mi][c][1] = ex2h2(hadd2u(pack_h2(sa[mi][nt0][2], sa[mi][nt0][3]), hm0));
                    pa[mi][c][2] = ex2h2(hadd2u(pack_h2(sa[mi][nt1][0], sa[mi][nt1][1]), hm1));
                    pa[mi][c][3] = ex2h2(hadd2u(pack_h2(sa[mi][nt1][2], sa[mi][nt1][3]), hm1));
                    MMA16816(lacc[mi], pa[mi][c], ones2);
                }
            }

            // ---- O += P @ V ----
#pragma unroll
            for (int c = 0; c < 4; c++) {
                uint32_t vrow = smem_u32(&sV[(c * 16 + (lane & 15)) * PADA + ((lane >> 4) & 1) * 8]);
#pragma unroll
                for (int ntd = 0; ntd < 8; ntd += 2) {
                    uint32_t vb[4];
                    LDMATRIX_X4T(vb[0], vb[1], vb[2], vb[3], vrow + ntd * 16);
                    MMA16816(o[0][ntd], pa[0][c], vb);
                    MMA16816(o[0][ntd + 1], pa[0][c], (vb + 2));
                    MMA16816(o[1][ntd], pa[1][c], vb);
                    MMA16816(o[1][ntd + 1], pa[1][c], (vb + 2));
                }
            }
        }
    }

    // ---- finalize: l fully reduced in lacc (replicated across quad) ----
#pragma unroll
    for (int mi = 0; mi < 2; mi++) {
        float inv_lo = 1.f / lacc[mi][0], inv_hi = 1.f / lacc[mi][2];
        int row_lo = qbase + wm * 32 + mi * 16 + g;
#pragma unroll
        for (int nt = 0; nt < 8; nt++) {
            int col = hoff + nt * 8 + 2 * tq;
            *(__half2*)(g_O16 + (size_t)row_lo * DMODEL + col) =
                __floats2half2_rn(o[mi][nt][0] * inv_lo, o[mi][nt][1] * inv_lo);
            *(__half2*)(g_O16 + (size_t)(row_lo + 8) * DMODEL + col) =
                __floats2half2_rn(o[mi][nt][2] * inv_hi, o[mi][nt][3] * inv_hi);
        }
    }
}

// ---------------------------------------------------------------------------
// kernel_launch (5 launches)
// ---------------------------------------------------------------------------
extern "C" void kernel_launch(void* const* d_in, const int* in_sizes, int n_in,
                              void* d_out, int out_size)
{
    (void)in_sizes; (void)n_in; (void)out_size;
    const float* hs   = (const float*)d_in[0];
    const float* enc  = (const float*)d_in[1];
    const float* mask = (const float*)d_in[2];
    const float* wq   = (const float*)d_in[3];
    const float* bq   = (const float*)d_in[4];
    const float* wk   = (const float*)d_in[5];
    const float* bk   = (const float*)d_in[6];
    const float* wv   = (const float*)d_in[7];
    const float* bv   = (const float*)d_in[8];
    const float* nqw  = (const float*)d_in[9];
    const float* nkw  = (const float*)d_in[10];
    const float* akw  = (const float*)d_in[13];
    const float* akb  = (const float*)d_in[14];
    const float* avw  = (const float*)d_in[15];
    const float* avb  = (const float*)d_in[16];
    const float* nakw = (const float*)d_in[18];
    const float* wo   = (const float*)d_in[19];
    const float* bo   = (const float*)d_in[20];
    float* out = (float*)d_out;

    __half *pQ16, *pK16, *pV16, *pO16, *phs16, *penc16, *pw16;
    cudaGetSymbolAddress((void**)&pQ16, g_Q16);
    cudaGetSymbolAddress((void**)&pK16, g_K16);
    cudaGetSymbolAddress((void**)&pV16, g_V16);
    cudaGetSymbolAddress((void**)&pO16, g_O16);
    cudaGetSymbolAddress((void**)&phs16, g_hs16);
    cudaGetSymbolAddress((void**)&penc16, g_enc16);
    cudaGetSymbolAddress((void**)&pw16, g_w16);

    cudaFuncSetAttribute(gemm_fused, cudaFuncAttributeMaxDynamicSharedMemorySize, GEMM_SMEM);
    cudaFuncSetAttribute(attn_kernel, cudaFuncAttributeMaxDynamicSharedMemorySize, ATTN_SMEM);

    dim3 tb(256);
    const int ENC_OFF = S_HID * DMODEL;

    // 1: all converts (weights: q,k,v,ak,av,o) + mask prescale (half)
    Ptr6 wsrc; wsrc.p[0] = wq; wsrc.p[1] = wk; wsrc.p[2] = wv;
    wsrc.p[3] = akw; wsrc.p[4] = avw; wsrc.p[5] = wo;
    cvt_all<<<CVT_BLOCKS, tb>>>(hs, enc, mask, wsrc);

    // 2: merged QKV + encoder projections (624 CTAs x 128 thr)
    GemmArgs ga;
    ga.bias[0] = bq;  ga.bias[1] = bk;  ga.bias[2] = bv;
    ga.bias[3] = akb; ga.bias[4] = avb; ga.bias[5] = bo;
    ga.out16[0] = pQ16; ga.out16[1] = pK16; ga.out16[2] = pV16;
    ga.out16[3] = pK16 + ENC_OFF; ga.out16[4] = pV16 + ENC_OFF; ga.out16[5] = nullptr;
    ga.out32 = out;
    gemm_fused<<<624, 128, GEMM_SMEM>>>(phs16, penc16, pw16, ga, 0);

    // 3: fused RMSNorm (Q gets 0.125*log2e folded in)
    rms_fused<<<(QCHUNKS + KCHUNKS) / 8, tb>>>(nqw, nkw, nakw);

    // 4: flash attention (BQ=128, 128-key tiles, 18 barriers)
    attn_kernel<<<dim3(S_HID / 128, HEADS), 128, ATTN_SMEM>>>();

    // 5: output projection -> fp32 (192 CTAs x 128 thr)
    gemm_fused<<<192, 128, GEMM_SMEM>>>(pO16, nullptr, pw16, ga, 1);
}

// round 16
// speedup vs baseline: 10.6860x; 1.0324x over previous
#include <cuda_runtime.h>
#include <cuda_fp16.h>
#include <cstdint>

// Problem constants
#define DMODEL 1536
#define HEADS  24
#define HDIM   64
#define S_HID  2048
#define S_ENCC 256
#define T_TOT  2304
#define NSPLIT 3
#define TILES_PER_SPLIT 6             // 18 key-tiles(128) / 3 splits
#define NW     (DMODEL * DMODEL)
#define LOG2E  1.44269504088896f

// ---------------------------------------------------------------------------
// Scratch (__device__ globals; no allocations allowed)
// ---------------------------------------------------------------------------
__device__ __align__(1024) __half g_Q16[(size_t)S_HID * DMODEL];
__device__ __align__(1024) __half g_K16[(size_t)T_TOT * DMODEL];
__device__ __align__(1024) __half g_V16[(size_t)T_TOT * DMODEL];
__device__ __align__(1024) __half g_O16[(size_t)S_HID * DMODEL];
__device__ __align__(1024) __half g_hs16[(size_t)S_HID * DMODEL];
__device__ __align__(1024) __half g_enc16[(size_t)S_ENCC * DMODEL];
__device__ __align__(1024) __half g_w16[6][(size_t)NW];
__device__ __align__(1024) __half g_mask2h[T_TOT];  // mask * log2(e), half
__device__ __align__(1024) float  g_Opart[(size_t)NSPLIT * S_HID * DMODEL];
__device__ __align__(1024) float  g_lpart[(size_t)NSPLIT * HEADS * S_HID];

// ---------------------------------------------------------------------------
// PTX helpers (plain sm_103-safe)
// ---------------------------------------------------------------------------
__device__ __forceinline__ uint32_t smem_u32(const void* p) {
    return (uint32_t)__cvta_generic_to_shared(p);
}
__device__ __forceinline__ void cp_async16(uint32_t saddr, const void* gaddr) {
    asm volatile("cp.async.cg.shared.global [%0], [%1], 16;" :: "r"(saddr), "l"(gaddr) : "memory");
}
__device__ __forceinline__ void cp_async4(uint32_t saddr, const void* gaddr) {
    asm volatile("cp.async.ca.shared.global [%0], [%1], 4;" :: "r"(saddr), "l"(gaddr) : "memory");
}
__device__ __forceinline__ uint32_t hadd2u(uint32_t a, uint32_t b) {
    uint32_t d;
    asm("add.rn.f16x2 %0, %1, %2;" : "=r"(d) : "r"(a), "r"(b));
    return d;
}
__device__ __forceinline__ uint32_t ex2h2(uint32_t a) {
    uint32_t d;
    asm("ex2.approx.f16x2 %0, %1;" : "=r"(d) : "r"(a));
    return d;
}

#define CP_COMMIT()  asm volatile("cp.async.commit_group;" ::: "memory")
#define CP_WAIT(n)   asm volatile("cp.async.wait_group %0;" :: "n"(n) : "memory")

#define LDMATRIX_X4(r0, r1, r2, r3, addr) \
    asm volatile("ldmatrix.sync.aligned.m8n8.x4.shared.b16 {%0,%1,%2,%3}, [%4];" \
                 : "=r"(r0), "=r"(r1), "=r"(r2), "=r"(r3) : "r"(addr))
#define LDMATRIX_X4T(r0, r1, r2, r3, addr) \
    asm volatile("ldmatrix.sync.aligned.m8n8.x4.trans.shared.b16 {%0,%1,%2,%3}, [%4];" \
                 : "=r"(r0), "=r"(r1), "=r"(r2), "=r"(r3) : "r"(addr))

#define MMA16816(d, a, b) \
    asm volatile("mma.sync.aligned.m16n8k16.row.col.f32.f16.f16.f32 " \
                 "{%0,%1,%2,%3}, {%4,%5,%6,%7}, {%8,%9}, {%0,%1,%2,%3};" \
                 : "+f"((d)[0]), "+f"((d)[1]), "+f"((d)[2]), "+f"((d)[3]) \
                 : "r"((a)[0]), "r"((a)[1]), "r"((a)[2]), "r"((a)[3]), \
                   "r"((b)[0]), "r"((b)[1]))

__device__ __forceinline__ uint32_t pack_h2(float x, float y) {
    union { __half2 h; uint32_t u; } p;
    p.h = __floats2half2_rn(x, y);
    return p.u;
}

// ---------------------------------------------------------------------------
// Fused convert: hs + enc + 6 weights + mask (prescaled by log2e, half).
// blocks: [0,768) hs | [768,864) enc | [864,4320) weights | 4320 mask
// ---------------------------------------------------------------------------
struct Ptr6 { const float* p[6]; };
#define CVT_BLOCKS 4321

__global__ __launch_bounds__(256) void cvt_all(const float* __restrict__ hs,
                                               const float* __restrict__ enc,
                                               const float* __restrict__ mask,
                                               Ptr6 w) {
    int b = blockIdx.x;
    int t4 = threadIdx.x * 4;

    if (b == 4320) {
#pragma unroll
        for (int p = 0; p < 3; p++) {
            int i = t4 + p * 1024;
            if (i < T_TOT) {
                float4 v = *(const float4*)(mask + i);
                union { __half2 h[2]; uint2 u; } pk;
                pk.h[0] = __floats2half2_rn(v.x * LOG2E, v.y * LOG2E);
                pk.h[1] = __floats2half2_rn(v.z * LOG2E, v.w * LOG2E);
                *reinterpret_cast<uint2*>(g_mask2h + i) = pk.u;
            }
        }
        return;
    }

    const float* src; __half* dst; int off;
    if (b < 768)      { src = hs;  dst = g_hs16;  off = b * 4096; }
    else if (b < 864) { src = enc; dst = g_enc16; off = (b - 768) * 4096; }
    else {
        int e = b - 864;
        int seg = e / 576;
        src = w.p[seg]; dst = g_w16[seg]; off = (e % 576) * 4096;
    }

    float4 v[4];
#pragma unroll
    for (int p = 0; p < 4; p++)
        v[p] = *(const float4*)(src + off + t4 + p * 1024);
#pragma unroll
    for (int p = 0; p < 4; p++) {
        union { __half2 h[2]; uint2 u; } pk;
        pk.h[0] = __floats2half2_rn(v[p].x, v[p].y);
        pk.h[1] = __floats2half2_rn(v[p].z, v[p].w);
        *reinterpret_cast<uint2*>(dst + off + t4 + p * 1024) = pk.u;
    }
}

// ---------------------------------------------------------------------------
// Merged HMMA GEMM, 128 threads (2x2 warps, 64x64 warp tiles = one head per
// warp n-tile). Optional fused per-head RMSNorm in the epilogue (segs 0/1/3):
// bias -> sum-of-squares (quad shfl) -> rsqrt -> * norm-weight [* QSCALE].
// mode 0: grid 624 (QKV + encoder).  mode 1: grid 192 (out-proj, fp32).
// ---------------------------------------------------------------------------
#define PADK 40
#define G_STAGE_H (2 * 128 * PADK)
#define GEMM_SMEM (3 * G_STAGE_H * 2)

struct GemmArgs {
    const float* bias[6];
    __half* out16[6];
    const float* nw[6];    // per-head RMSNorm weight (null = no norm)
    float post[6];         // post-scale folded into norm (QSCALE for Q)
    float* out32;
};

__global__ void __launch_bounds__(128, 2) gemm_fused(
    const __half* __restrict__ A0, const __half* __restrict__ A1,
    const __half* __restrict__ Wbase, GemmArgs args, int mode)
{
    extern __shared__ __half smg[];

    int tid = threadIdx.x;
    int wid = tid >> 5, lane = tid & 31;
    int wm = wid >> 1;
    int wn = wid & 1;

    int bid = blockIdx.x;
    const __half* A;
    int seg, mbase, nbase;
    if (mode == 1) {
        seg = 5;
        mbase = (bid / 12) << 7;
        nbase = (bid % 12) << 7;
        A = A0;
    } else if (bid < 576) {
        seg = bid / 192;
        int r = bid % 192;
        mbase = (r / 12) << 7;
        nbase = (r % 12) << 7;
        A = A0;
    } else {
        int e = bid - 576;
        seg = 3 + e / 24;
        int r = e % 24;
        mbase = (r / 12) << 7;
        nbase = (r % 12) << 7;
        A = A1;
    }
    const int K = DMODEL, N = DMODEL;
    const int NK = K >> 5;   // 48
    const __half* W = Wbase + (size_t)seg * NW;

    float acc[4][8][4];
#pragma unroll
    for (int mi = 0; mi < 4; mi++)
#pragma unroll
        for (int ni = 0; ni < 8; ni++)
#pragma unroll
            for (int e = 0; e < 4; e++) acc[mi][ni][e] = 0.f;

    auto load_tile = [&](int it) {
        __half* sA = smg + (it % 3) * G_STAGE_H;
        __half* sW = sA + 128 * PADK;
        int kb = it << 5;
#pragma unroll
        for (int i = 0; i < 4; i++) {
            int c = tid + (i << 7);
            int row = c >> 2;
            int col = (c & 3) << 3;
            cp_async16(smem_u32(&sA[row * PADK + col]),
                       A + (size_t)(mbase + row) * K + kb + col);
            cp_async16(smem_u32(&sW[row * PADK + col]),
                       W + (size_t)(nbase + row) * K + kb + col);
        }
        CP_COMMIT();
    };

    load_tile(0);
    load_tile(1);

    for (int it = 0; it < NK; it++) {
        if (it + 1 < NK) CP_WAIT(1); else CP_WAIT(0);
        __syncthreads();
        if (it + 2 < NK) load_tile(it + 2);

        const __half* sA = smg + (it % 3) * G_STAGE_H;
        const __half* sW = sA + 128 * PADK;
#pragma unroll
        for (int ks = 0; ks < 2; ks++) {
            uint32_t afr[4][4];
#pragma unroll
            for (int mi = 0; mi < 4; mi++) {
                int m = wm * 64 + mi * 16 + (lane & 15);
                int kk = ks * 16 + ((lane >> 4) << 3);
                LDMATRIX_X4(afr[mi][0], afr[mi][1], afr[mi][2], afr[mi][3],
                            smem_u32(&sA[m * PADK + kk]));
            }
            uint32_t bfr[8][2];
#pragma unroll
            for (int ntp = 0; ntp < 4; ntp++) {
                int n = wn * 64 + ntp * 16 + (lane & 7) + (((lane >> 4) & 1) << 3);
                int kk = ks * 16 + (((lane >> 3) & 1) << 3);
                uint32_t r0, r1, r2, r3;
                LDMATRIX_X4(r0, r1, r2, r3, smem_u32(&sW[n * PADK + kk]));
                bfr[ntp * 2][0] = r0; bfr[ntp * 2][1] = r1;
                bfr[ntp * 2 + 1][0] = r2; bfr[ntp * 2 + 1][1] = r3;
            }
#pragma unroll
            for (int mi = 0; mi < 4; mi++)
#pragma unroll
                for (int ni = 0; ni < 8; ni++)
                    MMA16816(acc[mi][ni], afr[mi], bfr[ni]);
        }
    }

    const float* bias = args.bias[seg];
    __half* O16 = args.out16[seg];
    const float* nw = args.nw[seg];
    float post = args.post[seg];
    int g = lane >> 2, tq = lane & 3;

#pragma unroll
    for (int mi = 0; mi < 4; mi++) {
        int row0 = mbase + wm * 64 + mi * 16 + g;
        // add bias into accumulators
#pragma unroll
        for (int ni = 0; ni < 8; ni++) {
            int col = nbase + wn * 64 + ni * 8 + tq * 2;
            float bx = bias[col], by = bias[col + 1];
            acc[mi][ni][0] += bx; acc[mi][ni][1] += by;
            acc[mi][ni][2] += bx; acc[mi][ni][3] += by;
        }
        float r0 = 1.f, r1 = 1.f;
        if (nw) {
            float ss0 = 0.f, ss1 = 0.f;
#pragma unroll
            for (int ni = 0; ni < 8; ni++) {
                ss0 += acc[mi][ni][0] * acc[mi][ni][0] + acc[mi][ni][1] * acc[mi][ni][1];
                ss1 += acc[mi][ni][2] * acc[mi][ni][2] + acc[mi][ni][3] * acc[mi][ni][3];
            }
#pragma unroll
            for (int off = 1; off < 4; off <<= 1) {
                ss0 += __shfl_xor_sync(0xffffffffu, ss0, off);
                ss1 += __shfl_xor_sync(0xffffffffu, ss1, off);
            }
            r0 = rsqrtf(ss0 * (1.0f / 64.0f) + 1e-6f) * post;
            r1 = rsqrtf(ss1 * (1.0f / 64.0f) + 1e-6f) * post;
        }
#pragma unroll
        for (int ni = 0; ni < 8; ni++) {
            int col = nbase + wn * 64 + ni * 8 + tq * 2;
            float w0 = 1.f, w1 = 1.f;
            if (nw) {
                float2 wv = *(const float2*)(nw + ni * 8 + tq * 2);
                w0 = wv.x; w1 = wv.y;
            }
            float v00 = acc[mi][ni][0] * r0 * w0, v01 = acc[mi][ni][1] * r0 * w1;
            float v10 = acc[mi][ni][2] * r1 * w0, v11 = acc[mi][ni][3] * r1 * w1;
            if (mode == 1) {
                *(float2*)(args.out32 + (size_t)row0 * N + col) = make_float2(v00, v01);
                *(float2*)(args.out32 + (size_t)(row0 + 8) * N + col) = make_float2(v10, v11);
            } else {
                *(__half2*)(O16 + (size_t)row0 * N + col) = __floats2half2_rn(v00, v01);
                *(__half2*)(O16 + (size_t)(row0 + 8) * N + col) = __floats2half2_rn(v10, v11);
            }
        }
    }
}

// ---------------------------------------------------------------------------
// HMMA flash attention, split-K over keys (3 splits x 768 keys).
// BQ=128, 128 threads (4 warps x 32 q-rows). 128-key K/V tiles, 2-stage
// pipeline, f16x2 exp + ones-MMA denominator. Writes UNNORMALIZED fp32
// partial O + partial l to scratch; combine kernel finishes.
// ---------------------------------------------------------------------------
#define PADA 72
#define QT_H (128 * PADA)
#define ATTN_MSK_OFF (5 * QT_H * 2)
#define ATTN_SMEM (ATTN_MSK_OFF + 2 * 128 * 2)

__global__ void __launch_bounds__(128, 2) attn_kernel()
{
    extern __shared__ __half sm[];
    __half* sQ = sm;
    __half* smskh = (__half*)((char*)sm + ATTN_MSK_OFF);

    int tid = threadIdx.x;
    int wm = tid >> 5, lane = tid & 31;
    int g = lane >> 2, tq = lane & 3;
    int head = blockIdx.y;
    int split = blockIdx.z;
    int qbase = blockIdx.x << 7;
    int hoff = head * HDIM;
    int t0 = split * TILES_PER_SPLIT;

    auto load_kv = [&](int kt) {
        int st = kt & 1;
        __half* sK = sm + (1 + 2 * st) * QT_H;
        __half* sV = sm + (2 + 2 * st) * QT_H;
        int kbase = kt << 7;
#pragma unroll
        for (int i = 0; i < 8; i++) {
            int c = tid + (i << 7);
            int row = c >> 3, col = (c & 7) << 3;
            size_t goff = (size_t)(kbase + row) * DMODEL + hoff + col;
            cp_async16(smem_u32(&sK[row * PADA + col]), g_K16 + goff);
            cp_async16(smem_u32(&sV[row * PADA + col]), g_V16 + goff);
        }
        if (tid < 64) cp_async4(smem_u32(&smskh[st * 128 + tid * 2]),
                                g_mask2h + kbase + tid * 2);
        CP_COMMIT();
    };

#pragma unroll
    for (int i = 0; i < 8; i++) {
        int c = tid + (i << 7);
        int row = c >> 3, col = (c & 7) << 3;
        cp_async16(smem_u32(&sQ[row * PADA + col]),
                   g_Q16 + (size_t)(qbase + row) * DMODEL + hoff + col);
    }
    load_kv(t0);

    const uint32_t ones2[2] = {0x3C003C00u, 0x3C003C00u};

    uint32_t qfr[2][4][4];
    float o[2][8][4];
    float lacc[2][4];
#pragma unroll
    for (int mi = 0; mi < 2; mi++) {
#pragma unroll
        for (int nt = 0; nt < 8; nt++)
#pragma unroll
            for (int e = 0; e < 4; e++) o[mi][nt][e] = 0.f;
#pragma unroll
        for (int e = 0; e < 4; e++) lacc[mi][e] = 0.f;
    }

    for (int ki = 0; ki < TILES_PER_SPLIT; ki++) {
        int kt = t0 + ki;
        CP_WAIT(0);
        __syncthreads();
        if (ki == 0) {
#pragma unroll
            for (int mi = 0; mi < 2; mi++)
#pragma unroll
                for (int kc = 0; kc < 4; kc++) {
                    int m = wm * 32 + mi * 16 + (lane & 15);
                    int kk = kc * 16 + ((lane >> 4) << 3);
                    LDMATRIX_X4(qfr[mi][kc][0], qfr[mi][kc][1], qfr[mi][kc][2],
                                qfr[mi][kc][3], smem_u32(&sQ[m * PADA + kk]));
                }
        }
        if (ki + 1 < TILES_PER_SPLIT) load_kv(kt + 1);

        int st = kt & 1;

#pragma unroll
        for (int h = 0; h < 2; h++) {
            const __half* sK = sm + (1 + 2 * st) * QT_H + h * 64 * PADA;
            const __half* sV = sm + (2 + 2 * st) * QT_H + h * 64 * PADA;
            const __half* mk = smskh + st * 128 + h * 64;

            // ---- S = Q @ K^T ----
            float sa[2][8][4];
#pragma unroll
            for (int mi = 0; mi < 2; mi++)
#pragma unroll
                for (int nt = 0; nt < 8; nt++)
#pragma unroll
                    for (int e = 0; e < 4; e++) sa[mi][nt][e] = 0.f;

#pragma unroll
            for (int kc = 0; kc < 4; kc++) {
                uint32_t kf[8][2];
#pragma unroll
                for (int ntp = 0; ntp < 4; ntp++) {
                    int n = ntp * 16 + (lane & 7) + (((lane >> 4) & 1) << 3);
                    int kk = kc * 16 + (((lane >> 3) & 1) << 3);
                    uint32_t r0, r1, r2, r3;
                    LDMATRIX_X4(r0, r1, r2, r3, smem_u32(&sK[n * PADA + kk]));
                    kf[ntp * 2][0] = r0; kf[ntp * 2][1] = r1;
                    kf[ntp * 2 + 1][0] = r2; kf[ntp * 2 + 1][1] = r3;
                }
#pragma unroll
                for (int nt = 0; nt < 8; nt++) {
                    MMA16816(sa[0][nt], qfr[0][kc], kf[nt]);
                    MMA16816(sa[1][nt], qfr[1][kc], kf[nt]);
                }
            }

            // ---- p = exp2(s + mask') in f16x2; l via ones-MMA ----
            uint32_t pa[2][4][4];
#pragma unroll
            for (int mi = 0; mi < 2; mi++) {
#pragma unroll
                for (int c = 0; c < 4; c++) {
                    int nt0 = 2 * c, nt1 = 2 * c + 1;
                    uint32_t hm0 = *(const uint32_t*)(mk + nt0 * 8 + 2 * tq);
                    uint32_t hm1 = *(const uint32_t*)(mk + nt1 * 8 + 2 * tq);
                    pa[mi][c][0] = ex2h2(hadd2u(pack_h2(sa[mi][nt0][0], sa[mi][nt0][1]), hm0));
                    pa[mi][c][1] = ex2h2(hadd2u(pack_h2(sa[mi][nt0][2], sa[mi][nt0][3]), hm0));
                    pa[mi][c][2] = ex2h2(hadd2u(pack_h2(sa[mi][nt1][0], sa[mi][nt1][1]), hm1));
                    pa[mi][c][3] = ex2h2(hadd2u(pack_h2(sa[mi][nt1][2], sa[mi][nt1][3]), hm1));
                    MMA16816(lacc[mi], pa[mi][c], ones2);
                }
            }

            // ---- O += P @ V ----
#pragma unroll
            for (int c = 0; c < 4; c++) {
                uint32_t vrow = smem_u32(&sV[(c * 16 + (lane & 15)) * PADA + ((lane >> 4) & 1) * 8]);
#pragma unroll
                for (int ntd = 0; ntd < 8; ntd += 2) {
                    uint32_t vb[4];
                    LDMATRIX_X4T(vb[0], vb[1], vb[2], vb[3], vrow + ntd * 16);
                    MMA16816(o[0][ntd], pa[0][c], vb);
                    MMA16816(o[0][ntd + 1], pa[0][c], (vb + 2));
                    MMA16816(o[1][ntd], pa[1][c], vb);
                    MMA16816(o[1][ntd + 1], pa[1][c], (vb + 2));
                }
            }
        }
    }

    // ---- write unnormalized partial O (fp32) + partial l ----
    float* Op = g_Opart + (size_t)split * S_HID * DMODEL;
    float* lp = g_lpart + (size_t)split * HEADS * S_HID + (size_t)head * S_HID;
#pragma unroll
    for (int mi = 0; mi < 2; mi++) {
        int row_lo = qbase + wm * 32 + mi * 16 + g;
        if (tq == 0) {
            lp[row_lo] = lacc[mi][0];
            lp[row_lo + 8] = lacc[mi][2];
        }
#pragma unroll
        for (int nt = 0; nt < 8; nt++) {
            int col = hoff + nt * 8 + 2 * tq;
            *(float2*)(Op + (size_t)row_lo * DMODEL + col) =
                make_float2(o[mi][nt][0], o[mi][nt][1]);
            *(float2*)(Op + (size_t)(row_lo + 8) * DMODEL + col) =
                make_float2(o[mi][nt][2], o[mi][nt][3]);
        }
    }
}

// ---------------------------------------------------------------------------
// Combine: O16[r][c] = (sum_s Opart[s][r][c]) / (sum_s lpart[s][head][r]).
// One block per row (384 threads x 4 cols).
// ---------------------------------------------------------------------------
__global__ __launch_bounds__(384) void combine_o()
{
    int row = blockIdx.x;
    int c = threadIdx.x * 4;
    int head = c >> 6;

    float l = 0.f;
#pragma unroll
    for (int s = 0; s < NSPLIT; s++)
        l += g_lpart[(size_t)s * HEADS * S_HID + (size_t)head * S_HID + row];
    float inv = 1.f / l;

    float4 a = make_float4(0.f, 0.f, 0.f, 0.f);
#pragma unroll
    for (int s = 0; s < NSPLIT; s++) {
        float4 v = *(const float4*)(g_Opart + (size_t)s * S_HID * DMODEL +
                                    (size_t)row * DMODEL + c);
        a.x += v.x; a.y += v.y; a.z += v.z; a.w += v.w;
    }
    union { __half2 h[2]; uint2 u; } pk;
    pk.h[0] = __floats2half2_rn(a.x * inv, a.y * inv);
    pk.h[1] = __floats2half2_rn(a.z * inv, a.w * inv);
    *reinterpret_cast<uint2*>(g_O16 + (size_t)row * DMODEL + c) = pk.u;
}

// ---------------------------------------------------------------------------
// kernel_launch (5 launches)
// ---------------------------------------------------------------------------
extern "C" void kernel_launch(void* const* d_in, const int* in_sizes, int n_in,
                              void* d_out, int out_size)
{
    (void)in_sizes; (void)n_in; (void)out_size;
    const float* hs   = (const float*)d_in[0];
    const float* enc  = (const float*)d_in[1];
    const float* mask = (const float*)d_in[2];
    const float* wq   = (const float*)d_in[3];
    const float* bq   = (const float*)d_in[4];
    const float* wk   = (const float*)d_in[5];
    const float* bk   = (const float*)d_in[6];
    const float* wv   = (const float*)d_in[7];
    const float* bv   = (const float*)d_in[8];
    const float* nqw  = (const float*)d_in[9];
    const float* nkw  = (const float*)d_in[10];
    const float* akw  = (const float*)d_in[13];
    const float* akb  = (const float*)d_in[14];
    const float* avw  = (const float*)d_in[15];
    const float* avb  = (const float*)d_in[16];
    const float* nakw = (const float*)d_in[18];
    const float* wo   = (const float*)d_in[19];
    const float* bo   = (const float*)d_in[20];
    float* out = (float*)d_out;

    __half *pQ16, *pK16, *pV16, *pO16, *phs16, *penc16, *pw16;
    cudaGetSymbolAddress((void**)&pQ16, g_Q16);
    cudaGetSymbolAddress((void**)&pK16, g_K16);
    cudaGetSymbolAddress((void**)&pV16, g_V16);
    cudaGetSymbolAddress((void**)&pO16, g_O16);
    cudaGetSymbolAddress((void**)&phs16, g_hs16);
    cudaGetSymbolAddress((void**)&penc16, g_enc16);
    cudaGetSymbolAddress((void**)&pw16, g_w16);

    cudaFuncSetAttribute(gemm_fused, cudaFuncAttributeMaxDynamicSharedMemorySize, GEMM_SMEM);
    cudaFuncSetAttribute(attn_kernel, cudaFuncAttributeMaxDynamicSharedMemorySize, ATTN_SMEM);

    dim3 tb(256);
    const int ENC_OFF = S_HID * DMODEL;

    // 1: all converts (weights: q,k,v,ak,av,o) + mask prescale (half)
    Ptr6 wsrc; wsrc.p[0] = wq; wsrc.p[1] = wk; wsrc.p[2] = wv;
    wsrc.p[3] = akw; wsrc.p[4] = avw; wsrc.p[5] = wo;
    cvt_all<<<CVT_BLOCKS, tb>>>(hs, enc, mask, wsrc);

    // 2: merged QKV + encoder projections with fused RMSNorm (624 CTAs)
    GemmArgs ga;
    ga.bias[0] = bq;  ga.bias[1] = bk;  ga.bias[2] = bv;
    ga.bias[3] = akb; ga.bias[4] = avb; ga.bias[5] = bo;
    ga.out16[0] = pQ16; ga.out16[1] = pK16; ga.out16[2] = pV16;
    ga.out16[3] = pK16 + ENC_OFF; ga.out16[4] = pV16 + ENC_OFF; ga.out16[5] = nullptr;
    ga.nw[0] = nqw; ga.nw[1] = nkw; ga.nw[2] = nullptr;
    ga.nw[3] = nakw; ga.nw[4] = nullptr; ga.nw[5] = nullptr;
    ga.post[0] = 0.125f * LOG2E; ga.post[1] = 1.f; ga.post[2] = 1.f;
    ga.post[3] = 1.f; ga.post[4] = 1.f; ga.post[5] = 1.f;
    ga.out32 = out;
    gemm_fused<<<624, 128, GEMM_SMEM>>>(phs16, penc16, pw16, ga, 0);

    // 3: split-K flash attention (16 q-tiles x 24 heads x 3 splits)
    attn_kernel<<<dim3(S_HID / 128, HEADS, NSPLIT), 128, ATTN_SMEM>>>();

    // 4: combine partials -> O16
    combine_o<<<S_HID, 384>>>();

    // 5: output projection -> fp32
    gemm_fused<<<192, 128, GEMM_SMEM>>>(pO16, nullptr, pw16, ga, 1);
}